// round 10
// baseline (speedup 1.0000x reference)
#include <cuda_runtime.h>
#include <cuda_bf16.h>
#include <cstdint>
#include <math.h>

// Problem constants
#define BB 64
#define SS 64
#define TT 21
#define DD 512
#define VV 32000
#define BT (BB*TT)        // 1344
#define NT2 250           // proj N tiles of 128
#define MT128 11          // ceil(1344/128)
#define MT16 88           // m-frag tiles (1408/16)
#define KT16 32           // 512/16 k-steps

// ---------------- static device scratch ----------------
__device__ float g_cat[BB*640];
__device__ float g_inp2[BB*1024];      // [context | h]
__device__ float g_gates[BB*2048];
__device__ float g_c[BB*512];
__device__ float g_xproj[BT*2048];
__device__ float g_wcomb[2048*1024];   // [W_ih_ctx | W_hh]
__device__ float g_biassum[2048];
__device__ float g_E2[BB*SS*512];      // enc @ attn_W^T
__device__ float g_outs[BT*512];
__device__ uint4 g_afrag[MT16*KT16*32];        // outs A-frags
__device__ uint4 g_eafrag[MT16*KT16*32];       // emb  A-frags
__device__ uint4 g_bfrag[(VV/16)*KT16*32];     // proj_w B-frags
__device__ uint4 g_wfrag[(2048/16)*KT16*32];   // W_ih_emb B-frags
__device__ float g_pmax[BT*NT2];
__device__ float g_psum[BT*NT2];
__device__ float g_lab[BT];
__device__ float g_nll[BT];

// ---------------- packed f32x2 helpers ----------------
__device__ __forceinline__ double pk2(float lo, float hi) {
    double d;
    asm("mov.b64 %0, {%1, %2};" : "=d"(d) : "f"(lo), "f"(hi));
    return d;
}
__device__ __forceinline__ void upk2(double v, float& lo, float& hi) {
    asm("mov.b64 {%0, %1}, %2;" : "=f"(lo), "=f"(hi) : "d"(v));
}
__device__ __forceinline__ void fma2(double& d, double a, double b) {
    asm("fma.rn.f32x2 %0, %1, %2, %0;" : "+d"(d) : "d"(a), "d"(b));
}

// ---------------- generic tiled fp32 GEMM (baseline-best) ----------------
template<bool TRANSB, bool ATOMIC>
__global__ void gemm_kernel(int klen,
                            const float* __restrict__ A, int lda,
                            const float* __restrict__ B, int ldb,
                            float* __restrict__ C, int ldc,
                            const float* __restrict__ bias,
                            const float* __restrict__ addf, int ldd)
{
    __shared__ float As[32][68];
    __shared__ float Bs[32][68];
    const int bm = blockIdx.y * 64;
    const int bn = blockIdx.x * 64;
    const int kbeg = blockIdx.z * klen;
    const int tid = threadIdx.x;
    const int tm = (tid >> 4) << 2;
    const int tn = (tid & 15) << 2;
    double acc2[4][2] = {};

    for (int k0 = kbeg; k0 < kbeg + klen; k0 += 32) {
#pragma unroll
        for (int i = 0; i < 8; i++) {
            int e = tid + i * 256;
            int m = e >> 5, k = e & 31;
            As[k][m] = A[(size_t)(bm + m) * lda + k0 + k];
        }
        if (TRANSB) {
#pragma unroll
            for (int i = 0; i < 8; i++) {
                int e = tid + i * 256;
                int n = e >> 5, k = e & 31;
                Bs[k][n] = B[(size_t)(bn + n) * ldb + k0 + k];
            }
        } else {
#pragma unroll
            for (int i = 0; i < 8; i++) {
                int e = tid + i * 256;
                int k = e >> 6, n = e & 63;
                Bs[k][n] = B[(size_t)(k0 + k) * ldb + bn + n];
            }
        }
        __syncthreads();
#pragma unroll
        for (int k = 0; k < 32; k++) {
            float4 av = *reinterpret_cast<const float4*>(&As[k][tm]);
            float4 bv = *reinterpret_cast<const float4*>(&Bs[k][tn]);
            double b01 = pk2(bv.x, bv.y), b23 = pk2(bv.z, bv.w);
            double a0 = pk2(av.x, av.x), a1 = pk2(av.y, av.y);
            double a2 = pk2(av.z, av.z), a3 = pk2(av.w, av.w);
            fma2(acc2[0][0], a0, b01); fma2(acc2[0][1], a0, b23);
            fma2(acc2[1][0], a1, b01); fma2(acc2[1][1], a1, b23);
            fma2(acc2[2][0], a2, b01); fma2(acc2[2][1], a2, b23);
            fma2(acc2[3][0], a3, b01); fma2(acc2[3][1], a3, b23);
        }
        __syncthreads();
    }

    float acc[4][4];
#pragma unroll
    for (int i = 0; i < 4; i++) {
        upk2(acc2[i][0], acc[i][0], acc[i][1]);
        upk2(acc2[i][1], acc[i][2], acc[i][3]);
    }

    if (ATOMIC) {
#pragma unroll
        for (int i = 0; i < 4; i++) {
            size_t ro = (size_t)(bm + tm + i);
#pragma unroll
            for (int j = 0; j < 4; j++)
                atomicAdd(&C[ro * ldc + bn + tn + j], acc[i][j]);
        }
    } else {
#pragma unroll
        for (int i = 0; i < 4; i++) {
            size_t ro = (size_t)(bm + tm + i);
#pragma unroll
            for (int j = 0; j < 4; j++) {
                float v = acc[i][j];
                int n = bn + tn + j;
                if (bias) v += bias[n];
                if (addf) v += addf[ro * ldd + n];
                C[ro * ldc + n] = v;
            }
        }
    }
}

// ---------------- bf16 helpers ----------------
__device__ __forceinline__ unsigned pkbf(float lo, float hi) {
    __nv_bfloat162 h = __floats2bfloat162_rn(lo, hi);
    return *reinterpret_cast<unsigned*>(&h);
}

__device__ __forceinline__ void mma_bf16(float* d,
    unsigned a0, unsigned a1, unsigned a2, unsigned a3,
    unsigned b0, unsigned b1)
{
    asm volatile(
        "mma.sync.aligned.m16n8k16.row.col.f32.bf16.bf16.f32 "
        "{%0,%1,%2,%3},{%4,%5,%6,%7},{%8,%9},{%0,%1,%2,%3};\n"
        : "+f"(d[0]), "+f"(d[1]), "+f"(d[2]), "+f"(d[3])
        : "r"(a0), "r"(a1), "r"(a2), "r"(a3), "r"(b0), "r"(b1));
}

// ---------------- fragment conversion kernels ----------------
__global__ void conv_afrag_kernel()
{
    int gt = blockIdx.x * 256 + threadIdx.x;
    if (gt >= MT16 * KT16 * 32) return;
    int lane = gt & 31;
    int kt = (gt >> 5) & 31;
    int mt = gt >> 10;
    int gid = lane >> 2, tig = lane & 3;
    int r0 = mt * 16 + gid, r1 = r0 + 8;
    int c0 = kt * 16 + tig * 2;
    const float* A = g_outs;
    uint4 v;
    v.x = (r0 < BT) ? pkbf(A[(size_t)r0*512 + c0],     A[(size_t)r0*512 + c0 + 1]) : 0u;
    v.y = (r1 < BT) ? pkbf(A[(size_t)r1*512 + c0],     A[(size_t)r1*512 + c0 + 1]) : 0u;
    v.z = (r0 < BT) ? pkbf(A[(size_t)r0*512 + c0 + 8], A[(size_t)r0*512 + c0 + 9]) : 0u;
    v.w = (r1 < BT) ? pkbf(A[(size_t)r1*512 + c0 + 8], A[(size_t)r1*512 + c0 + 9]) : 0u;
    g_afrag[(mt * KT16 + kt) * 32 + lane] = v;
}

// emb A-frags: gathers emb_table[decoder_input[r]] directly
__global__ void conv_eafrag_kernel(const int* __restrict__ di,
                                   const float* __restrict__ et)
{
    int gt = blockIdx.x * 256 + threadIdx.x;
    if (gt >= MT16 * KT16 * 32) return;
    int lane = gt & 31;
    int kt = (gt >> 5) & 31;
    int mt = gt >> 10;
    int gid = lane >> 2, tig = lane & 3;
    int r0 = mt * 16 + gid, r1 = r0 + 8;
    int c0 = kt * 16 + tig * 2;
    uint4 v = make_uint4(0u, 0u, 0u, 0u);
    if (r0 < BT) {
        const float* e0 = et + (size_t)di[r0] * 512;
        v.x = pkbf(e0[c0], e0[c0 + 1]);
        v.z = pkbf(e0[c0 + 8], e0[c0 + 9]);
    }
    if (r1 < BT) {
        const float* e1 = et + (size_t)di[r1] * 512;
        v.y = pkbf(e1[c0], e1[c0 + 1]);
        v.w = pkbf(e1[c0 + 8], e1[c0 + 9]);
    }
    g_eafrag[(mt * KT16 + kt) * 32 + lane] = v;
}

// proj_w B-frags
__global__ void conv_bfrag_kernel(const float* __restrict__ W)
{
    int gt = blockIdx.x * 256 + threadIdx.x;
    int lane = gt & 31;
    int kt = (gt >> 5) & 31;
    int nt2 = gt >> 10;
    if (nt2 >= VV / 16) return;
    int gid = lane >> 2, tig = lane & 3;
    int k0 = kt * 16 + tig * 2;
    const float* w0 = W + (size_t)((nt2 * 2) * 8 + gid) * 512;
    const float* w1 = W + (size_t)((nt2 * 2 + 1) * 8 + gid) * 512;
    uint4 v;
    v.x = pkbf(w0[k0],     w0[k0 + 1]);
    v.y = pkbf(w0[k0 + 8], w0[k0 + 9]);
    v.z = pkbf(w1[k0],     w1[k0 + 1]);
    v.w = pkbf(w1[k0 + 8], w1[k0 + 9]);
    g_bfrag[(nt2 * KT16 + kt) * 32 + lane] = v;
}

// W_ih emb-slice B-frags: element (n,k) = w_ih[n*1024 + 512 + k]
__global__ void conv_wfrag_kernel(const float* __restrict__ wih)
{
    int gt = blockIdx.x * 256 + threadIdx.x;
    int lane = gt & 31;
    int kt = (gt >> 5) & 31;
    int nt2 = gt >> 10;
    if (nt2 >= 2048 / 16) return;
    int gid = lane >> 2, tig = lane & 3;
    int k0 = kt * 16 + tig * 2;
    const float* w0 = wih + (size_t)((nt2 * 2) * 8 + gid) * 1024 + 512;
    const float* w1 = wih + (size_t)((nt2 * 2 + 1) * 8 + gid) * 1024 + 512;
    uint4 v;
    v.x = pkbf(w0[k0],     w0[k0 + 1]);
    v.y = pkbf(w0[k0 + 8], w0[k0 + 9]);
    v.z = pkbf(w1[k0],     w1[k0 + 1]);
    v.w = pkbf(w1[k0 + 8], w1[k0 + 9]);
    g_wfrag[(nt2 * KT16 + kt) * 32 + lane] = v;
}

// ---------------- HMMA frag GEMM core (warp 32x32, CTA 128x128, 16 warps) ----------------
#define FRAG_LOOP(Af, Bf, mtbase, nt2base)                                     \
    const uint4* a0p = (Af) + (size_t)(((mtbase) + 0) * KT16) * 32 + lane;     \
    const uint4* a1p = (Af) + (size_t)(((mtbase) + 1) * KT16) * 32 + lane;     \
    const uint4* b0p = (Bf) + (size_t)(((nt2base) + 0) * KT16) * 32 + lane;    \
    const uint4* b1p = (Bf) + (size_t)(((nt2base) + 1) * KT16) * 32 + lane;    \
    float acc[2][4][4] = {};                                                   \
    _Pragma("unroll 2")                                                        \
    for (int kt = 0; kt < KT16; kt++) {                                        \
        uint4 av0 = a0p[kt * 32];                                              \
        uint4 av1 = a1p[kt * 32];                                              \
        uint4 bv0 = b0p[kt * 32];                                              \
        uint4 bv1 = b1p[kt * 32];                                              \
        mma_bf16(acc[0][0], av0.x, av0.y, av0.z, av0.w, bv0.x, bv0.y);         \
        mma_bf16(acc[0][1], av0.x, av0.y, av0.z, av0.w, bv0.z, bv0.w);         \
        mma_bf16(acc[0][2], av0.x, av0.y, av0.z, av0.w, bv1.x, bv1.y);         \
        mma_bf16(acc[0][3], av0.x, av0.y, av0.z, av0.w, bv1.z, bv1.w);         \
        mma_bf16(acc[1][0], av1.x, av1.y, av1.z, av1.w, bv0.x, bv0.y);         \
        mma_bf16(acc[1][1], av1.x, av1.y, av1.z, av1.w, bv0.z, bv0.w);         \
        mma_bf16(acc[1][2], av1.x, av1.y, av1.z, av1.w, bv1.x, bv1.y);         \
        mma_bf16(acc[1][3], av1.x, av1.y, av1.z, av1.w, bv1.z, bv1.w);         \
    }

// proj: fused bias + per-row logsumexp partials
__global__ void __launch_bounds__(512)
proj_hmma_kernel(const uint4* __restrict__ Af, const uint4* __restrict__ Bf,
                 const float* __restrict__ pb)
{
    __shared__ float sb[128];
    __shared__ float smax[4][128], ssum[4][128];
    const int tid = threadIdx.x, lane = tid & 31, wid = tid >> 5;
    const int wm = wid >> 2, wn = wid & 3;
    const int gid = lane >> 2, tig = lane & 3;
    const int nb = blockIdx.x, mb = blockIdx.y;

    if (tid < 128) sb[tid] = pb[nb * 128 + tid];

    FRAG_LOOP(Af, Bf, mb * 8 + wm * 2, nb * 8 + wn * 2)
    __syncthreads();   // sb ready

#pragma unroll
    for (int f = 0; f < 2; f++) {
#pragma unroll
        for (int half = 0; half < 2; half++) {
            float v[8];
#pragma unroll
            for (int nf = 0; nf < 4; nf++) {
                float b0 = sb[wn * 32 + nf * 8 + tig * 2];
                float b1 = sb[wn * 32 + nf * 8 + tig * 2 + 1];
                v[nf * 2]     = acc[f][nf][half * 2]     + b0;
                v[nf * 2 + 1] = acc[f][nf][half * 2 + 1] + b1;
            }
            float mx = v[0];
#pragma unroll
            for (int i = 1; i < 8; i++) mx = fmaxf(mx, v[i]);
            mx = fmaxf(mx, __shfl_xor_sync(0xffffffffu, mx, 1));
            mx = fmaxf(mx, __shfl_xor_sync(0xffffffffu, mx, 2));
            float se = 0.f;
#pragma unroll
            for (int i = 0; i < 8; i++) se += expf(v[i] - mx);
            se += __shfl_xor_sync(0xffffffffu, se, 1);
            se += __shfl_xor_sync(0xffffffffu, se, 2);
            if (tig == 0) {
                int rowl = wm * 32 + f * 16 + half * 8 + gid;
                smax[wn][rowl] = mx;
                ssum[wn][rowl] = se;
            }
        }
    }
    __syncthreads();

    if (tid < 128) {
        int row = mb * 128 + tid;
        if (row < BT) {
            float M = fmaxf(fmaxf(smax[0][tid], smax[1][tid]),
                            fmaxf(smax[2][tid], smax[3][tid]));
            float S = ssum[0][tid] * expf(smax[0][tid] - M)
                    + ssum[1][tid] * expf(smax[1][tid] - M)
                    + ssum[2][tid] * expf(smax[2][tid] - M)
                    + ssum[3][tid] * expf(smax[3][tid] - M);
            g_pmax[(size_t)row * NT2 + nb] = M;
            g_psum[(size_t)row * NT2 + nb] = S;
        }
    }
}

// xproj: store C = embA @ WihB^T + biassum
__global__ void __launch_bounds__(512)
xproj_hmma_kernel(const uint4* __restrict__ Af, const uint4* __restrict__ Bf)
{
    __shared__ float sb[128];
    const int tid = threadIdx.x, lane = tid & 31, wid = tid >> 5;
    const int wm = wid >> 2, wn = wid & 3;
    const int gid = lane >> 2, tig = lane & 3;
    const int nbx = blockIdx.x, mb = blockIdx.y;

    if (tid < 128) sb[tid] = g_biassum[nbx * 128 + tid];

    FRAG_LOOP(Af, Bf, mb * 8 + wm * 2, nbx * 8 + wn * 2)
    __syncthreads();

#pragma unroll
    for (int f = 0; f < 2; f++) {
#pragma unroll
        for (int half = 0; half < 2; half++) {
            int r = mb * 128 + wm * 32 + f * 16 + half * 8 + gid;
            if (r >= BT) continue;
#pragma unroll
            for (int nf = 0; nf < 4; nf++) {
                int nl = wn * 32 + nf * 8 + tig * 2;
                float v0 = acc[f][nf][half * 2]     + sb[nl];
                float v1 = acc[f][nf][half * 2 + 1] + sb[nl + 1];
                *reinterpret_cast<float2*>(
                    &g_xproj[(size_t)r * 2048 + nbx * 128 + nl]) = make_float2(v0, v1);
            }
        }
    }
}

// ---------------- fused pointwise(t-1) + attention(t) ----------------
__global__ void pwattn_kernel(const float* __restrict__ enc,
                              const float* __restrict__ be2d, int t)
{
    __shared__ float hs[512];
    __shared__ float sc[64];
    __shared__ float s_inv;
    const int b = blockIdx.x, tid = threadIdx.x;

    if (t > 0) {
        const int gb = b * 2048;
#pragma unroll
        for (int u = 0; u < 2; u++) {
            int j = tid + u * 256;
            float gi = g_gates[gb + j];
            float gf = g_gates[gb + 512 + j];
            float gg = g_gates[gb + 1024 + j];
            float go = g_gates[gb + 1536 + j];
            float c = g_c[b * 512 + j];
            float si = 1.f / (1.f + expf(-gi));
            float sf = 1.f / (1.f + expf(-gf));
            float so = 1.f / (1.f + expf(-go));
            c = sf * c + si * tanhf(gg);
            g_c[b * 512 + j] = c;
            float h = so * tanhf(c);
            g_outs[(size_t)(b * TT + (t - 1)) * 512 + j] = h;
            g_inp2[b * 1024 + 512 + j] = h;
            hs[j] = h;
        }
    } else {
        // h0 came from split-K atomic GEMM without bias; add it here
#pragma unroll
        for (int u = 0; u < 2; u++) {
            int j = tid + u * 256;
            float h = g_inp2[b * 1024 + 512 + j] + be2d[j];
            g_inp2[b * 1024 + 512 + j] = h;
            hs[j] = h;
        }
    }
    __syncthreads();

    // init gates = xproj[:, t, :] for the split-K atomic GEMM
    {
        size_t xo = (size_t)(b * TT + t) * 2048;
#pragma unroll
        for (int i = 0; i < 8; i++)
            g_gates[b * 2048 + tid + i * 256] = g_xproj[xo + tid + i * 256];
    }

    const int w = tid >> 5, lane = tid & 31;
    const float* E2b = g_E2 + (size_t)b * SS * 512;
    for (int s = w; s < SS; s += 8) {
        const float* er = E2b + (size_t)s * 512;
        float a = 0.f;
        for (int k = lane; k < 512; k += 32) a += hs[k] * er[k];
#pragma unroll
        for (int o = 16; o; o >>= 1) a += __shfl_xor_sync(0xffffffffu, a, o);
        if (lane == 0) sc[s] = a;
    }
    __syncthreads();

    if (w == 0) {
        float v0 = sc[lane], v1 = sc[lane + 32];
        float m = fmaxf(v0, v1);
#pragma unroll
        for (int o = 16; o; o >>= 1) m = fmaxf(m, __shfl_xor_sync(0xffffffffu, m, o));
        float e0 = expf(v0 - m), e1 = expf(v1 - m);
        float ssm = e0 + e1;
#pragma unroll
        for (int o = 16; o; o >>= 1) ssm += __shfl_xor_sync(0xffffffffu, ssm, o);
        sc[lane] = e0; sc[lane + 32] = e1;
        if (lane == 0) s_inv = 1.f / ssm;
    }
    __syncthreads();

    float inv = s_inv;
    const float* eb = enc + (size_t)b * SS * DD;
    for (int d = tid; d < DD; d += 256) {
        float a = 0.f;
#pragma unroll 8
        for (int s = 0; s < SS; s++) a += sc[s] * eb[(size_t)s * DD + d];
        g_inp2[b * 1024 + d] = a * inv;
    }
}

// final pointwise (produces outs[T-1])
__global__ void pw_final_kernel()
{
    const int b = blockIdx.x, j = threadIdx.x;
    const int gb = b * 2048;
    float gi = g_gates[gb + j];
    float gf = g_gates[gb + 512 + j];
    float gg = g_gates[gb + 1024 + j];
    float go = g_gates[gb + 1536 + j];
    float c = g_c[b * 512 + j];
    float si = 1.f / (1.f + expf(-gi));
    float sf = 1.f / (1.f + expf(-gf));
    float so = 1.f / (1.f + expf(-go));
    c = sf * c + si * tanhf(gg);
    float h = so * tanhf(c);
    g_outs[(size_t)(b * TT + TT - 1) * 512 + j] = h;
}

// ---------------- one-time prep ----------------
__global__ void prep_small_kernel(const float* __restrict__ eh, const float* __restrict__ st,
                                  const float* __restrict__ bih, const float* __restrict__ bhh)
{
    int i = blockIdx.x * blockDim.x + threadIdx.x;
    if (i < BB * 640) {
        int b = i / 640, j = i - b * 640;
        g_cat[i] = (j < 512) ? eh[b * 512 + j] : st[b * 512 + 384 + (j - 512)];
    } else if (i < BB * 640 + 2048) {
        int j = i - BB * 640;
        g_biassum[j] = bih[j] + bhh[j];
    } else if (i < BB * 640 + 2048 + BB * 512) {
        g_c[i - (BB * 640 + 2048)] = 0.f;
    } else if (i < BB * 640 + 2048 + 2 * BB * 512) {
        int i2 = i - (BB * 640 + 2048 + BB * 512);
        int b = i2 >> 9, j = i2 & 511;
        g_inp2[b * 1024 + 512 + j] = 0.f;   // h0 accumulator
    }
}

__global__ void wcomb_kernel(const float* __restrict__ wih, const float* __restrict__ whh)
{
    int i = blockIdx.x * blockDim.x + threadIdx.x;
    int r = i >> 10, c = i & 1023;
    g_wcomb[i] = (c < 512) ? wih[(size_t)r * 1024 + c] : whh[(size_t)r * 512 + (c - 512)];
}

// ---------------- loss ----------------
__global__ void lablogit_kernel(const int* __restrict__ lab, const float* __restrict__ pw,
                                const float* __restrict__ pb)
{
    int gt = blockIdx.x * blockDim.x + threadIdx.x;
    int w = gt >> 5, lane = gt & 31;
    if (w >= BT) return;
    int l = lab[w];
    const float* o  = g_outs + (size_t)w * 512;
    const float* wr = pw + (size_t)l * 512;
    float a = 0.f;
    for (int k = lane; k < 512; k += 32) a += o[k] * wr[k];
#pragma unroll
    for (int off = 16; off; off >>= 1) a += __shfl_xor_sync(0xffffffffu, a, off);
    if (lane == 0) g_lab[w] = a + pb[l];
}

__global__ void loss_row_kernel(const int* __restrict__ lab)
{
    __shared__ float red[128];
    const int r = blockIdx.x, tid = threadIdx.x;
    const float* pm = g_pmax + (size_t)r * NT2;
    const float* ps = g_psum + (size_t)r * NT2;
    float m = -1e30f;
    for (int j = tid; j < NT2; j += 128) m = fmaxf(m, pm[j]);
    red[tid] = m; __syncthreads();
    for (int s = 64; s; s >>= 1) { if (tid < s) red[tid] = fmaxf(red[tid], red[tid + s]); __syncthreads(); }
    float M = red[0]; __syncthreads();
    float se = 0.f;
    for (int j = tid; j < NT2; j += 128) se += ps[j] * expf(pm[j] - M);
    red[tid] = se; __syncthreads();
    for (int s = 64; s; s >>= 1) { if (tid < s) red[tid] += red[tid + s]; __syncthreads(); }
    if (tid == 0) {
        float lse = M + logf(red[0]);
        int l = lab[r];
        g_nll[r] = (l > 0) ? (lse - g_lab[r]) : 0.f;
    }
}

__global__ void loss_final_kernel(const int* __restrict__ lab, float* __restrict__ out)
{
    __shared__ float red[64];
    const int b = threadIdx.x;
    float s = 0.f, cnt = 0.f;
    for (int t = 0; t < TT; t++) {
        int r = b * TT + t;
        s += g_nll[r];
        cnt += (lab[r] > 0) ? 1.f : 0.f;
    }
    red[b] = s / (cnt + 1e-6f);
    __syncthreads();
    if (b == 0) {
        float a = 0.f;
        for (int i = 0; i < 64; i++) a += red[i];
        out[0] = a / 64.f;
    }
}

// ---------------- host launcher ----------------
extern "C" void kernel_launch(void* const* d_in, const int* in_sizes, int n_in,
                              void* d_out, int out_size)
{
    const float* encode_hidden = (const float*)d_in[0];
    const float* encode_output = (const float*)d_in[1];
    const int*   seq_label     = (const int*)  d_in[3];
    const int*   decoder_input = (const int*)  d_in[4];
    const float* style_emb     = (const float*)d_in[5];
    const float* w_e2d         = (const float*)d_in[6];
    const float* b_e2d         = (const float*)d_in[7];
    const float* attn_W        = (const float*)d_in[8];
    const float* emb_table     = (const float*)d_in[9];
    const float* w_ih          = (const float*)d_in[10];
    const float* w_hh          = (const float*)d_in[11];
    const float* b_ih          = (const float*)d_in[12];
    const float* b_hh          = (const float*)d_in[13];
    const float* proj_w        = (const float*)d_in[14];
    const float* proj_b        = (const float*)d_in[15];
    float* out = (float*)d_out;

    float *p_cat, *p_inp2, *p_gates, *p_wcomb, *p_E2;
    uint4 *p_afrag, *p_eafrag, *p_bfrag, *p_wfrag;
    cudaGetSymbolAddress((void**)&p_cat,     g_cat);
    cudaGetSymbolAddress((void**)&p_inp2,    g_inp2);
    cudaGetSymbolAddress((void**)&p_gates,   g_gates);
    cudaGetSymbolAddress((void**)&p_wcomb,   g_wcomb);
    cudaGetSymbolAddress((void**)&p_E2,      g_E2);
    cudaGetSymbolAddress((void**)&p_afrag,   g_afrag);
    cudaGetSymbolAddress((void**)&p_eafrag,  g_eafrag);
    cudaGetSymbolAddress((void**)&p_bfrag,   g_bfrag);
    cudaGetSymbolAddress((void**)&p_wfrag,   g_wfrag);

    // one-time prep
    prep_small_kernel<<<552, 256>>>(encode_hidden, style_emb, b_ih, b_hh);
    wcomb_kernel<<<2048, 1024>>>(w_ih, w_hh);
    conv_eafrag_kernel<<<352, 256>>>(decoder_input, emb_table);
    conv_wfrag_kernel<<<512, 256>>>(w_ih);
    conv_bfrag_kernel<<<8000, 256>>>(proj_w);

    // h0 = cat @ W_e2d^T (bias added in pwattn t=0), split-K atomic
    gemm_kernel<true, true><<<dim3(8, 1, 5), 256>>>(128,
        p_cat, 640, w_e2d, 640, p_inp2 + 512, 1024, nullptr, nullptr, 0);

    // xproj = emb @ W_ih_emb^T + biassum  (HMMA frag-direct)
    xproj_hmma_kernel<<<dim3(16, MT128), 512>>>(p_eafrag, p_wfrag);

    // E2 = enc @ attn_W^T (fp32)
    gemm_kernel<true, false><<<dim3(8, 64, 1), 256>>>(512,
        encode_output, 512, attn_W, 512, p_E2, 512, nullptr, nullptr, 0);

    for (int t = 0; t < TT; t++) {
        pwattn_kernel<<<64, 256>>>(encode_output, b_e2d, t);
        gemm_kernel<true, true><<<dim3(32, 1, 4), 256>>>(256,
            p_inp2, 1024, p_wcomb, 1024, p_gates, 2048, nullptr, nullptr, 0);
    }
    pw_final_kernel<<<64, 512>>>();

    // loss
    conv_afrag_kernel<<<352, 256>>>();
    lablogit_kernel<<<168, 256>>>(seq_label, proj_w, proj_b);
    proj_hmma_kernel<<<dim3(NT2, MT128), 512>>>(p_afrag, p_bfrag, proj_b);
    loss_row_kernel<<<BT, 128>>>(seq_label);
    loss_final_kernel<<<1, 64>>>(seq_label, out);
}

// round 11
// speedup vs baseline: 1.4158x; 1.4158x over previous
#include <cuda_runtime.h>
#include <cuda_bf16.h>
#include <cstdint>
#include <math.h>

// Problem constants
#define BB 64
#define SS 64
#define TT 21
#define DD 512
#define VV 32000
#define BT (BB*TT)        // 1344
#define NT2 250           // proj N tiles of 128
#define MT128 11          // ceil(1344/128)
#define MT16 88           // m-frag tiles (1408/16)
#define KT16 32           // 512/16 k-steps

// ---------------- static device scratch ----------------
__device__ float g_cat[BB*640];
__device__ float g_inp2[BB*1024];      // [context | h]
__device__ float g_gates[BB*2048];
__device__ float g_c[BB*512];
__device__ float g_xproj[BT*2048];
__device__ float g_wcomb[2048*1024];   // [W_ih_ctx | W_hh]
__device__ float g_biassum[2048];
__device__ float g_E2[BB*SS*512];      // enc @ attn_W^T
__device__ float g_outs[BT*512];
__device__ uint4 g_afrag[MT16*KT16*32];        // outs A-frags
__device__ uint4 g_eafrag[MT16*KT16*32];       // emb  A-frags
__device__ uint4 g_bfrag[(VV/16)*KT16*32];     // proj_w B-frags
__device__ uint4 g_wfrag[(2048/16)*KT16*32];   // W_ih_emb B-frags
__device__ float g_pmax[BT*NT2];
__device__ float g_psum[BT*NT2];
__device__ float g_lab[BT];
__device__ float g_nll[BT];

// ---------------- packed f32x2 helpers ----------------
__device__ __forceinline__ double pk2(float lo, float hi) {
    double d;
    asm("mov.b64 %0, {%1, %2};" : "=d"(d) : "f"(lo), "f"(hi));
    return d;
}
__device__ __forceinline__ void upk2(double v, float& lo, float& hi) {
    asm("mov.b64 {%0, %1}, %2;" : "=f"(lo), "=f"(hi) : "d"(v));
}
__device__ __forceinline__ void fma2(double& d, double a, double b) {
    asm("fma.rn.f32x2 %0, %1, %2, %0;" : "+d"(d) : "d"(a), "d"(b));
}

// ---------------- generic tiled fp32 GEMM (baseline-best) ----------------
template<bool TRANSB, bool ATOMIC>
__global__ void gemm_kernel(int klen,
                            const float* __restrict__ A, int lda,
                            const float* __restrict__ B, int ldb,
                            float* __restrict__ C, int ldc,
                            const float* __restrict__ bias,
                            const float* __restrict__ addf, int ldd)
{
    __shared__ float As[32][68];
    __shared__ float Bs[32][68];
    const int bm = blockIdx.y * 64;
    const int bn = blockIdx.x * 64;
    const int kbeg = blockIdx.z * klen;
    const int tid = threadIdx.x;
    const int tm = (tid >> 4) << 2;
    const int tn = (tid & 15) << 2;
    double acc2[4][2] = {};

    for (int k0 = kbeg; k0 < kbeg + klen; k0 += 32) {
#pragma unroll
        for (int i = 0; i < 8; i++) {
            int e = tid + i * 256;
            int m = e >> 5, k = e & 31;
            As[k][m] = A[(size_t)(bm + m) * lda + k0 + k];
        }
        if (TRANSB) {
#pragma unroll
            for (int i = 0; i < 8; i++) {
                int e = tid + i * 256;
                int n = e >> 5, k = e & 31;
                Bs[k][n] = B[(size_t)(bn + n) * ldb + k0 + k];
            }
        } else {
#pragma unroll
            for (int i = 0; i < 8; i++) {
                int e = tid + i * 256;
                int k = e >> 6, n = e & 63;
                Bs[k][n] = B[(size_t)(k0 + k) * ldb + bn + n];
            }
        }
        __syncthreads();
#pragma unroll
        for (int k = 0; k < 32; k++) {
            float4 av = *reinterpret_cast<const float4*>(&As[k][tm]);
            float4 bv = *reinterpret_cast<const float4*>(&Bs[k][tn]);
            double b01 = pk2(bv.x, bv.y), b23 = pk2(bv.z, bv.w);
            double a0 = pk2(av.x, av.x), a1 = pk2(av.y, av.y);
            double a2 = pk2(av.z, av.z), a3 = pk2(av.w, av.w);
            fma2(acc2[0][0], a0, b01); fma2(acc2[0][1], a0, b23);
            fma2(acc2[1][0], a1, b01); fma2(acc2[1][1], a1, b23);
            fma2(acc2[2][0], a2, b01); fma2(acc2[2][1], a2, b23);
            fma2(acc2[3][0], a3, b01); fma2(acc2[3][1], a3, b23);
        }
        __syncthreads();
    }

    float acc[4][4];
#pragma unroll
    for (int i = 0; i < 4; i++) {
        upk2(acc2[i][0], acc[i][0], acc[i][1]);
        upk2(acc2[i][1], acc[i][2], acc[i][3]);
    }

    if (ATOMIC) {
#pragma unroll
        for (int i = 0; i < 4; i++) {
            size_t ro = (size_t)(bm + tm + i);
#pragma unroll
            for (int j = 0; j < 4; j++)
                atomicAdd(&C[ro * ldc + bn + tn + j], acc[i][j]);
        }
    } else {
#pragma unroll
        for (int i = 0; i < 4; i++) {
            size_t ro = (size_t)(bm + tm + i);
#pragma unroll
            for (int j = 0; j < 4; j++) {
                float v = acc[i][j];
                int n = bn + tn + j;
                if (bias) v += bias[n];
                if (addf) v += addf[ro * ldd + n];
                C[ro * ldc + n] = v;
            }
        }
    }
}

// ---------------- bf16 helpers ----------------
__device__ __forceinline__ unsigned pkbf(float lo, float hi) {
    __nv_bfloat162 h = __floats2bfloat162_rn(lo, hi);
    return *reinterpret_cast<unsigned*>(&h);
}

__device__ __forceinline__ void mma_bf16(float* d,
    unsigned a0, unsigned a1, unsigned a2, unsigned a3,
    unsigned b0, unsigned b1)
{
    asm volatile(
        "mma.sync.aligned.m16n8k16.row.col.f32.bf16.bf16.f32 "
        "{%0,%1,%2,%3},{%4,%5,%6,%7},{%8,%9},{%0,%1,%2,%3};\n"
        : "+f"(d[0]), "+f"(d[1]), "+f"(d[2]), "+f"(d[3])
        : "r"(a0), "r"(a1), "r"(a2), "r"(a3), "r"(b0), "r"(b1));
}

// ---------------- fragment conversion kernels ----------------
__global__ void conv_afrag_kernel()
{
    int gt = blockIdx.x * 256 + threadIdx.x;
    if (gt >= MT16 * KT16 * 32) return;
    int lane = gt & 31;
    int kt = (gt >> 5) & 31;
    int mt = gt >> 10;
    int gid = lane >> 2, tig = lane & 3;
    int r0 = mt * 16 + gid, r1 = r0 + 8;
    int c0 = kt * 16 + tig * 2;
    const float* A = g_outs;
    uint4 v;
    v.x = (r0 < BT) ? pkbf(A[(size_t)r0*512 + c0],     A[(size_t)r0*512 + c0 + 1]) : 0u;
    v.y = (r1 < BT) ? pkbf(A[(size_t)r1*512 + c0],     A[(size_t)r1*512 + c0 + 1]) : 0u;
    v.z = (r0 < BT) ? pkbf(A[(size_t)r0*512 + c0 + 8], A[(size_t)r0*512 + c0 + 9]) : 0u;
    v.w = (r1 < BT) ? pkbf(A[(size_t)r1*512 + c0 + 8], A[(size_t)r1*512 + c0 + 9]) : 0u;
    g_afrag[(mt * KT16 + kt) * 32 + lane] = v;
}

// emb A-frags: gathers emb_table[decoder_input[r]] directly
__global__ void conv_eafrag_kernel(const int* __restrict__ di,
                                   const float* __restrict__ et)
{
    int gt = blockIdx.x * 256 + threadIdx.x;
    if (gt >= MT16 * KT16 * 32) return;
    int lane = gt & 31;
    int kt = (gt >> 5) & 31;
    int mt = gt >> 10;
    int gid = lane >> 2, tig = lane & 3;
    int r0 = mt * 16 + gid, r1 = r0 + 8;
    int c0 = kt * 16 + tig * 2;
    uint4 v = make_uint4(0u, 0u, 0u, 0u);
    if (r0 < BT) {
        const float* e0 = et + (size_t)di[r0] * 512;
        v.x = pkbf(e0[c0], e0[c0 + 1]);
        v.z = pkbf(e0[c0 + 8], e0[c0 + 9]);
    }
    if (r1 < BT) {
        const float* e1 = et + (size_t)di[r1] * 512;
        v.y = pkbf(e1[c0], e1[c0 + 1]);
        v.w = pkbf(e1[c0 + 8], e1[c0 + 9]);
    }
    g_eafrag[(mt * KT16 + kt) * 32 + lane] = v;
}

// proj_w B-frags
__global__ void conv_bfrag_kernel(const float* __restrict__ W)
{
    int gt = blockIdx.x * 256 + threadIdx.x;
    int lane = gt & 31;
    int kt = (gt >> 5) & 31;
    int nt2 = gt >> 10;
    if (nt2 >= VV / 16) return;
    int gid = lane >> 2, tig = lane & 3;
    int k0 = kt * 16 + tig * 2;
    const float* w0 = W + (size_t)((nt2 * 2) * 8 + gid) * 512;
    const float* w1 = W + (size_t)((nt2 * 2 + 1) * 8 + gid) * 512;
    uint4 v;
    v.x = pkbf(w0[k0],     w0[k0 + 1]);
    v.y = pkbf(w0[k0 + 8], w0[k0 + 9]);
    v.z = pkbf(w1[k0],     w1[k0 + 1]);
    v.w = pkbf(w1[k0 + 8], w1[k0 + 9]);
    g_bfrag[(nt2 * KT16 + kt) * 32 + lane] = v;
}

// W_ih emb-slice B-frags: element (n,k) = w_ih[n*1024 + 512 + k]
__global__ void conv_wfrag_kernel(const float* __restrict__ wih)
{
    int gt = blockIdx.x * 256 + threadIdx.x;
    int lane = gt & 31;
    int kt = (gt >> 5) & 31;
    int nt2 = gt >> 10;
    if (nt2 >= 2048 / 16) return;
    int gid = lane >> 2, tig = lane & 3;
    int k0 = kt * 16 + tig * 2;
    const float* w0 = wih + (size_t)((nt2 * 2) * 8 + gid) * 1024 + 512;
    const float* w1 = wih + (size_t)((nt2 * 2 + 1) * 8 + gid) * 1024 + 512;
    uint4 v;
    v.x = pkbf(w0[k0],     w0[k0 + 1]);
    v.y = pkbf(w0[k0 + 8], w0[k0 + 9]);
    v.z = pkbf(w1[k0],     w1[k0 + 1]);
    v.w = pkbf(w1[k0 + 8], w1[k0 + 9]);
    g_wfrag[(nt2 * KT16 + kt) * 32 + lane] = v;
}

// ---------------- HMMA frag GEMM core (R9 config: CTA 128x128, 8 warps, warp 32x64) ----------------
#define FRAG_LOOP16(Af, Bf, mt0, nt2b)                                         \
    const uint4* a0p = (Af) + (size_t)((mt0) * KT16) * 32 + lane;              \
    const uint4* a1p = (Af) + (size_t)(((mt0) + 1) * KT16) * 32 + lane;        \
    const uint4* bp0 = (Bf) + (size_t)(((nt2b) + 0) * KT16) * 32 + lane;       \
    const uint4* bp1 = (Bf) + (size_t)(((nt2b) + 1) * KT16) * 32 + lane;       \
    const uint4* bp2 = (Bf) + (size_t)(((nt2b) + 2) * KT16) * 32 + lane;       \
    const uint4* bp3 = (Bf) + (size_t)(((nt2b) + 3) * KT16) * 32 + lane;       \
    float acc[2][8][4] = {};                                                   \
    _Pragma("unroll 4")                                                        \
    for (int kt = 0; kt < KT16; kt++) {                                        \
        uint4 av0 = a0p[kt * 32];                                              \
        uint4 av1 = a1p[kt * 32];                                              \
        uint4 bv0 = bp0[kt * 32];                                              \
        uint4 bv1 = bp1[kt * 32];                                              \
        uint4 bv2 = bp2[kt * 32];                                              \
        uint4 bv3 = bp3[kt * 32];                                              \
        mma_bf16(acc[0][0], av0.x, av0.y, av0.z, av0.w, bv0.x, bv0.y);         \
        mma_bf16(acc[0][1], av0.x, av0.y, av0.z, av0.w, bv0.z, bv0.w);         \
        mma_bf16(acc[0][2], av0.x, av0.y, av0.z, av0.w, bv1.x, bv1.y);         \
        mma_bf16(acc[0][3], av0.x, av0.y, av0.z, av0.w, bv1.z, bv1.w);         \
        mma_bf16(acc[0][4], av0.x, av0.y, av0.z, av0.w, bv2.x, bv2.y);         \
        mma_bf16(acc[0][5], av0.x, av0.y, av0.z, av0.w, bv2.z, bv2.w);         \
        mma_bf16(acc[0][6], av0.x, av0.y, av0.z, av0.w, bv3.x, bv3.y);         \
        mma_bf16(acc[0][7], av0.x, av0.y, av0.z, av0.w, bv3.z, bv3.w);         \
        mma_bf16(acc[1][0], av1.x, av1.y, av1.z, av1.w, bv0.x, bv0.y);         \
        mma_bf16(acc[1][1], av1.x, av1.y, av1.z, av1.w, bv0.z, bv0.w);         \
        mma_bf16(acc[1][2], av1.x, av1.y, av1.z, av1.w, bv1.x, bv1.y);         \
        mma_bf16(acc[1][3], av1.x, av1.y, av1.z, av1.w, bv1.z, bv1.w);         \
        mma_bf16(acc[1][4], av1.x, av1.y, av1.z, av1.w, bv2.x, bv2.y);         \
        mma_bf16(acc[1][5], av1.x, av1.y, av1.z, av1.w, bv2.z, bv2.w);         \
        mma_bf16(acc[1][6], av1.x, av1.y, av1.z, av1.w, bv3.x, bv3.y);         \
        mma_bf16(acc[1][7], av1.x, av1.y, av1.z, av1.w, bv3.z, bv3.w);         \
    }

// proj: fused bias + per-row logsumexp partials (EXACT R9 winner)
__global__ void __launch_bounds__(256)
proj_hmma_kernel(const uint4* __restrict__ Af, const uint4* __restrict__ Bf,
                 const float* __restrict__ pb)
{
    __shared__ float sb[128];
    __shared__ float smax[2][128], ssum[2][128];
    const int tid = threadIdx.x, lane = tid & 31, wid = tid >> 5;
    const int wm = wid >> 1, wn = wid & 1;
    const int gid = lane >> 2, tig = lane & 3;
    const int nb = blockIdx.x, mb = blockIdx.y;

    if (tid < 128) sb[tid] = pb[nb * 128 + tid];

    FRAG_LOOP16(Af, Bf, mb * 8 + wm * 2, nb * 8 + wn * 4)
    __syncthreads();   // sb ready

#pragma unroll
    for (int f = 0; f < 2; f++) {
#pragma unroll
        for (int half = 0; half < 2; half++) {
            float v[16];
#pragma unroll
            for (int nf = 0; nf < 8; nf++) {
                float b0 = sb[wn * 64 + nf * 8 + tig * 2];
                float b1 = sb[wn * 64 + nf * 8 + tig * 2 + 1];
                v[nf * 2]     = acc[f][nf][half * 2]     + b0;
                v[nf * 2 + 1] = acc[f][nf][half * 2 + 1] + b1;
            }
            float mx = v[0];
#pragma unroll
            for (int i = 1; i < 16; i++) mx = fmaxf(mx, v[i]);
            mx = fmaxf(mx, __shfl_xor_sync(0xffffffffu, mx, 1));
            mx = fmaxf(mx, __shfl_xor_sync(0xffffffffu, mx, 2));
            float se = 0.f;
#pragma unroll
            for (int i = 0; i < 16; i++) se += expf(v[i] - mx);
            se += __shfl_xor_sync(0xffffffffu, se, 1);
            se += __shfl_xor_sync(0xffffffffu, se, 2);
            if (tig == 0) {
                int rowl = wm * 32 + f * 16 + half * 8 + gid;
                smax[wn][rowl] = mx;
                ssum[wn][rowl] = se;
            }
        }
    }
    __syncthreads();

    if (tid < 128) {
        int row = mb * 128 + tid;
        if (row < BT) {
            float m0 = smax[0][tid], m1 = smax[1][tid];
            float M = fmaxf(m0, m1);
            float S = ssum[0][tid] * expf(m0 - M) + ssum[1][tid] * expf(m1 - M);
            g_pmax[(size_t)row * NT2 + nb] = M;
            g_psum[(size_t)row * NT2 + nb] = S;
        }
    }
}

// xproj: C = embA @ WihB^T + biassum  (same R9-style core, store epilogue)
__global__ void __launch_bounds__(256)
xproj_hmma_kernel(const uint4* __restrict__ Af, const uint4* __restrict__ Bf)
{
    __shared__ float sb[128];
    const int tid = threadIdx.x, lane = tid & 31, wid = tid >> 5;
    const int wm = wid >> 1, wn = wid & 1;
    const int gid = lane >> 2, tig = lane & 3;
    const int nb = blockIdx.x, mb = blockIdx.y;

    if (tid < 128) sb[tid] = g_biassum[nb * 128 + tid];

    FRAG_LOOP16(Af, Bf, mb * 8 + wm * 2, nb * 8 + wn * 4)
    __syncthreads();

#pragma unroll
    for (int f = 0; f < 2; f++) {
#pragma unroll
        for (int half = 0; half < 2; half++) {
            int r = mb * 128 + wm * 32 + f * 16 + half * 8 + gid;
            if (r >= BT) continue;
#pragma unroll
            for (int nf = 0; nf < 8; nf++) {
                int nl = wn * 64 + nf * 8 + tig * 2;
                float v0 = acc[f][nf][half * 2]     + sb[nl];
                float v1 = acc[f][nf][half * 2 + 1] + sb[nl + 1];
                *reinterpret_cast<float2*>(
                    &g_xproj[(size_t)r * 2048 + nb * 128 + nl]) = make_float2(v0, v1);
            }
        }
    }
}

// ---------------- fused pointwise(t-1) + attention(t) ----------------
__global__ void pwattn_kernel(const float* __restrict__ enc,
                              const float* __restrict__ be2d, int t)
{
    __shared__ float hs[512];
    __shared__ float sc[64];
    __shared__ float s_inv;
    const int b = blockIdx.x, tid = threadIdx.x;

    if (t > 0) {
        const int gb = b * 2048;
#pragma unroll
        for (int u = 0; u < 2; u++) {
            int j = tid + u * 256;
            float gi = g_gates[gb + j];
            float gf = g_gates[gb + 512 + j];
            float gg = g_gates[gb + 1024 + j];
            float go = g_gates[gb + 1536 + j];
            float c = g_c[b * 512 + j];
            float si = 1.f / (1.f + expf(-gi));
            float sf = 1.f / (1.f + expf(-gf));
            float so = 1.f / (1.f + expf(-go));
            c = sf * c + si * tanhf(gg);
            g_c[b * 512 + j] = c;
            float h = so * tanhf(c);
            g_outs[(size_t)(b * TT + (t - 1)) * 512 + j] = h;
            g_inp2[b * 1024 + 512 + j] = h;
            hs[j] = h;
        }
    } else {
        // h0 came from split-K atomic GEMM without bias; add it here
#pragma unroll
        for (int u = 0; u < 2; u++) {
            int j = tid + u * 256;
            float h = g_inp2[b * 1024 + 512 + j] + be2d[j];
            g_inp2[b * 1024 + 512 + j] = h;
            hs[j] = h;
        }
    }
    __syncthreads();

    // init gates = xproj[:, t, :] for the split-K atomic GEMM
    {
        size_t xo = (size_t)(b * TT + t) * 2048;
#pragma unroll
        for (int i = 0; i < 8; i++)
            g_gates[b * 2048 + tid + i * 256] = g_xproj[xo + tid + i * 256];
    }

    const int w = tid >> 5, lane = tid & 31;
    const float* E2b = g_E2 + (size_t)b * SS * 512;
    for (int s = w; s < SS; s += 8) {
        const float* er = E2b + (size_t)s * 512;
        float a = 0.f;
        for (int k = lane; k < 512; k += 32) a += hs[k] * er[k];
#pragma unroll
        for (int o = 16; o; o >>= 1) a += __shfl_xor_sync(0xffffffffu, a, o);
        if (lane == 0) sc[s] = a;
    }
    __syncthreads();

    if (w == 0) {
        float v0 = sc[lane], v1 = sc[lane + 32];
        float m = fmaxf(v0, v1);
#pragma unroll
        for (int o = 16; o; o >>= 1) m = fmaxf(m, __shfl_xor_sync(0xffffffffu, m, o));
        float e0 = expf(v0 - m), e1 = expf(v1 - m);
        float ssm = e0 + e1;
#pragma unroll
        for (int o = 16; o; o >>= 1) ssm += __shfl_xor_sync(0xffffffffu, ssm, o);
        sc[lane] = e0; sc[lane + 32] = e1;
        if (lane == 0) s_inv = 1.f / ssm;
    }
    __syncthreads();

    float inv = s_inv;
    const float* eb = enc + (size_t)b * SS * DD;
    for (int d = tid; d < DD; d += 256) {
        float a = 0.f;
#pragma unroll 8
        for (int s = 0; s < SS; s++) a += sc[s] * eb[(size_t)s * DD + d];
        g_inp2[b * 1024 + d] = a * inv;
    }
}

// final pointwise (produces outs[T-1])
__global__ void pw_final_kernel()
{
    const int b = blockIdx.x, j = threadIdx.x;
    const int gb = b * 2048;
    float gi = g_gates[gb + j];
    float gf = g_gates[gb + 512 + j];
    float gg = g_gates[gb + 1024 + j];
    float go = g_gates[gb + 1536 + j];
    float c = g_c[b * 512 + j];
    float si = 1.f / (1.f + expf(-gi));
    float sf = 1.f / (1.f + expf(-gf));
    float so = 1.f / (1.f + expf(-go));
    c = sf * c + si * tanhf(gg);
    float h = so * tanhf(c);
    g_outs[(size_t)(b * TT + TT - 1) * 512 + j] = h;
}

// ---------------- one-time prep ----------------
__global__ void prep_small_kernel(const float* __restrict__ eh, const float* __restrict__ st,
                                  const float* __restrict__ bih, const float* __restrict__ bhh)
{
    int i = blockIdx.x * blockDim.x + threadIdx.x;
    if (i < BB * 640) {
        int b = i / 640, j = i - b * 640;
        g_cat[i] = (j < 512) ? eh[b * 512 + j] : st[b * 512 + 384 + (j - 512)];
    } else if (i < BB * 640 + 2048) {
        int j = i - BB * 640;
        g_biassum[j] = bih[j] + bhh[j];
    } else if (i < BB * 640 + 2048 + BB * 512) {
        g_c[i - (BB * 640 + 2048)] = 0.f;
    } else if (i < BB * 640 + 2048 + 2 * BB * 512) {
        int i2 = i - (BB * 640 + 2048 + BB * 512);
        int b = i2 >> 9, j = i2 & 511;
        g_inp2[b * 1024 + 512 + j] = 0.f;   // h0 accumulator
    }
}

__global__ void wcomb_kernel(const float* __restrict__ wih, const float* __restrict__ whh)
{
    int i = blockIdx.x * blockDim.x + threadIdx.x;
    int r = i >> 10, c = i & 1023;
    g_wcomb[i] = (c < 512) ? wih[(size_t)r * 1024 + c] : whh[(size_t)r * 512 + (c - 512)];
}

// ---------------- loss ----------------
__global__ void lablogit_kernel(const int* __restrict__ lab, const float* __restrict__ pw,
                                const float* __restrict__ pb)
{
    int gt = blockIdx.x * blockDim.x + threadIdx.x;
    int w = gt >> 5, lane = gt & 31;
    if (w >= BT) return;
    int l = lab[w];
    const float* o  = g_outs + (size_t)w * 512;
    const float* wr = pw + (size_t)l * 512;
    float a = 0.f;
    for (int k = lane; k < 512; k += 32) a += o[k] * wr[k];
#pragma unroll
    for (int off = 16; off; off >>= 1) a += __shfl_xor_sync(0xffffffffu, a, off);
    if (lane == 0) g_lab[w] = a + pb[l];
}

__global__ void loss_row_kernel(const int* __restrict__ lab)
{
    __shared__ float red[128];
    const int r = blockIdx.x, tid = threadIdx.x;
    const float* pm = g_pmax + (size_t)r * NT2;
    const float* ps = g_psum + (size_t)r * NT2;
    float m = -1e30f;
    for (int j = tid; j < NT2; j += 128) m = fmaxf(m, pm[j]);
    red[tid] = m; __syncthreads();
    for (int s = 64; s; s >>= 1) { if (tid < s) red[tid] = fmaxf(red[tid], red[tid + s]); __syncthreads(); }
    float M = red[0]; __syncthreads();
    float se = 0.f;
    for (int j = tid; j < NT2; j += 128) se += ps[j] * expf(pm[j] - M);
    red[tid] = se; __syncthreads();
    for (int s = 64; s; s >>= 1) { if (tid < s) red[tid] += red[tid + s]; __syncthreads(); }
    if (tid == 0) {
        float lse = M + logf(red[0]);
        int l = lab[r];
        g_nll[r] = (l > 0) ? (lse - g_lab[r]) : 0.f;
    }
}

__global__ void loss_final_kernel(const int* __restrict__ lab, float* __restrict__ out)
{
    __shared__ float red[64];
    const int b = threadIdx.x;
    float s = 0.f, cnt = 0.f;
    for (int t = 0; t < TT; t++) {
        int r = b * TT + t;
        s += g_nll[r];
        cnt += (lab[r] > 0) ? 1.f : 0.f;
    }
    red[b] = s / (cnt + 1e-6f);
    __syncthreads();
    if (b == 0) {
        float a = 0.f;
        for (int i = 0; i < 64; i++) a += red[i];
        out[0] = a / 64.f;
    }
}

// ---------------- host launcher ----------------
extern "C" void kernel_launch(void* const* d_in, const int* in_sizes, int n_in,
                              void* d_out, int out_size)
{
    const float* encode_hidden = (const float*)d_in[0];
    const float* encode_output = (const float*)d_in[1];
    const int*   seq_label     = (const int*)  d_in[3];
    const int*   decoder_input = (const int*)  d_in[4];
    const float* style_emb     = (const float*)d_in[5];
    const float* w_e2d         = (const float*)d_in[6];
    const float* b_e2d         = (const float*)d_in[7];
    const float* attn_W        = (const float*)d_in[8];
    const float* emb_table     = (const float*)d_in[9];
    const float* w_ih          = (const float*)d_in[10];
    const float* w_hh          = (const float*)d_in[11];
    const float* b_ih          = (const float*)d_in[12];
    const float* b_hh          = (const float*)d_in[13];
    const float* proj_w        = (const float*)d_in[14];
    const float* proj_b        = (const float*)d_in[15];
    float* out = (float*)d_out;

    float *p_cat, *p_inp2, *p_gates, *p_wcomb, *p_E2;
    uint4 *p_afrag, *p_eafrag, *p_bfrag, *p_wfrag;
    cudaGetSymbolAddress((void**)&p_cat,     g_cat);
    cudaGetSymbolAddress((void**)&p_inp2,    g_inp2);
    cudaGetSymbolAddress((void**)&p_gates,   g_gates);
    cudaGetSymbolAddress((void**)&p_wcomb,   g_wcomb);
    cudaGetSymbolAddress((void**)&p_E2,      g_E2);
    cudaGetSymbolAddress((void**)&p_afrag,   g_afrag);
    cudaGetSymbolAddress((void**)&p_eafrag,  g_eafrag);
    cudaGetSymbolAddress((void**)&p_bfrag,   g_bfrag);
    cudaGetSymbolAddress((void**)&p_wfrag,   g_wfrag);

    // one-time prep
    prep_small_kernel<<<552, 256>>>(encode_hidden, style_emb, b_ih, b_hh);
    wcomb_kernel<<<2048, 1024>>>(w_ih, w_hh);
    conv_eafrag_kernel<<<352, 256>>>(decoder_input, emb_table);
    conv_wfrag_kernel<<<512, 256>>>(w_ih);
    conv_bfrag_kernel<<<8000, 256>>>(proj_w);

    // h0 = cat @ W_e2d^T (bias added in pwattn t=0), split-K atomic
    gemm_kernel<true, true><<<dim3(8, 1, 5), 256>>>(128,
        p_cat, 640, w_e2d, 640, p_inp2 + 512, 1024, nullptr, nullptr, 0);

    // xproj = emb @ W_ih_emb^T + biassum  (HMMA frag-direct, R9-style core)
    xproj_hmma_kernel<<<dim3(16, MT128), 256>>>(p_eafrag, p_wfrag);

    // E2 = enc @ attn_W^T (fp32)
    gemm_kernel<true, false><<<dim3(8, 64, 1), 256>>>(512,
        encode_output, 512, attn_W, 512, p_E2, 512, nullptr, nullptr, 0);

    for (int t = 0; t < TT; t++) {
        pwattn_kernel<<<64, 256>>>(encode_output, b_e2d, t);
        gemm_kernel<true, true><<<dim3(32, 1, 4), 256>>>(256,
            p_inp2, 1024, p_wcomb, 1024, p_gates, 2048, nullptr, nullptr, 0);
    }
    pw_final_kernel<<<64, 512>>>();

    // loss
    conv_afrag_kernel<<<352, 256>>>();
    lablogit_kernel<<<168, 256>>>(seq_label, proj_w, proj_b);
    proj_hmma_kernel<<<dim3(NT2, MT128), 256>>>(p_afrag, p_bfrag, proj_b);
    loss_row_kernel<<<BT, 128>>>(seq_label);
    loss_final_kernel<<<1, 64>>>(seq_label, out);
}

// round 12
// speedup vs baseline: 1.4313x; 1.0110x over previous
#include <cuda_runtime.h>
#include <cuda_bf16.h>
#include <cstdint>
#include <math.h>

// Problem constants
#define BB 64
#define SS 64
#define TT 21
#define DD 512
#define VV 32000
#define BT (BB*TT)        // 1344
#define NT2 250           // proj N tiles of 128
#define MT128 11          // ceil(1344/128)
#define MT16 88           // m-frag tiles (1408/16)
#define KT16 32           // 512/16 k-steps
#define EMT 256           // enc m-frag tiles (4096/16)

// ---------------- static device scratch ----------------
__device__ float g_cat[BB*640];
__device__ float g_inp2[BB*1024];      // [context | h] fp32
__device__ float g_gates[BB*2048];
__device__ float g_c[BB*512];
__device__ float g_xproj[BT*2048];
__device__ float g_biassum[2048];
__device__ float g_E2[BB*SS*512];      // enc @ attn_W^T
__device__ float g_outs[BT*512];
__device__ uint4 g_afrag[MT16*KT16*32];        // outs A-frags
__device__ uint4 g_eafrag[MT16*KT16*32];       // emb  A-frags
__device__ uint4 g_bfrag[(VV/16)*KT16*32];     // proj_w B-frags
__device__ uint4 g_wfrag[(2048/16)*KT16*32];   // W_ih_emb B-frags
__device__ uint4 g_wcfrag[128*64*32];          // [W_ih_ctx|W_hh] B-frags (N=2048,K=1024)
__device__ uint4 g_encfrag[EMT*KT16*32];       // enc A-frags
__device__ uint4 g_awfrag[32*KT16*32];         // attn_W B-frags
__device__ uint4 g_gfrag[4*64*32];             // per-step [ctx|h] A-frags (M=64,K=1024)
__device__ float g_pmax[BT*NT2];
__device__ float g_psum[BT*NT2];
__device__ float g_lab[BT];
__device__ float g_nll[BT];

// ---------------- packed f32x2 helpers (h0 FFMA GEMM) ----------------
__device__ __forceinline__ double pk2(float lo, float hi) {
    double d;
    asm("mov.b64 %0, {%1, %2};" : "=d"(d) : "f"(lo), "f"(hi));
    return d;
}
__device__ __forceinline__ void upk2(double v, float& lo, float& hi) {
    asm("mov.b64 {%0, %1}, %2;" : "=f"(lo), "=f"(hi) : "d"(v));
}
__device__ __forceinline__ void fma2(double& d, double a, double b) {
    asm("fma.rn.f32x2 %0, %1, %2, %0;" : "+d"(d) : "d"(a), "d"(b));
}

// ---------------- generic fp32 GEMM (only for h0), split-K atomic ----------------
__global__ void gemm_atomic_kernel(int klen,
                                   const float* __restrict__ A, int lda,
                                   const float* __restrict__ B, int ldb,
                                   float* __restrict__ C, int ldc)
{
    __shared__ float As[32][68];
    __shared__ float Bs[32][68];
    const int bm = blockIdx.y * 64;
    const int bn = blockIdx.x * 64;
    const int kbeg = blockIdx.z * klen;
    const int tid = threadIdx.x;
    const int tm = (tid >> 4) << 2;
    const int tn = (tid & 15) << 2;
    double acc2[4][2] = {};

    for (int k0 = kbeg; k0 < kbeg + klen; k0 += 32) {
#pragma unroll
        for (int i = 0; i < 8; i++) {
            int e = tid + i * 256;
            int m = e >> 5, k = e & 31;
            As[k][m] = A[(size_t)(bm + m) * lda + k0 + k];
        }
#pragma unroll
        for (int i = 0; i < 8; i++) {
            int e = tid + i * 256;
            int n = e >> 5, k = e & 31;
            Bs[k][n] = B[(size_t)(bn + n) * ldb + k0 + k];
        }
        __syncthreads();
#pragma unroll
        for (int k = 0; k < 32; k++) {
            float4 av = *reinterpret_cast<const float4*>(&As[k][tm]);
            float4 bv = *reinterpret_cast<const float4*>(&Bs[k][tn]);
            double b01 = pk2(bv.x, bv.y), b23 = pk2(bv.z, bv.w);
            double a0 = pk2(av.x, av.x), a1 = pk2(av.y, av.y);
            double a2 = pk2(av.z, av.z), a3 = pk2(av.w, av.w);
            fma2(acc2[0][0], a0, b01); fma2(acc2[0][1], a0, b23);
            fma2(acc2[1][0], a1, b01); fma2(acc2[1][1], a1, b23);
            fma2(acc2[2][0], a2, b01); fma2(acc2[2][1], a2, b23);
            fma2(acc2[3][0], a3, b01); fma2(acc2[3][1], a3, b23);
        }
        __syncthreads();
    }

    float acc[4][4];
#pragma unroll
    for (int i = 0; i < 4; i++) {
        upk2(acc2[i][0], acc[i][0], acc[i][1]);
        upk2(acc2[i][1], acc[i][2], acc[i][3]);
    }
#pragma unroll
    for (int i = 0; i < 4; i++) {
        size_t ro = (size_t)(bm + tm + i);
#pragma unroll
        for (int j = 0; j < 4; j++)
            atomicAdd(&C[ro * ldc + bn + tn + j], acc[i][j]);
    }
}

// ---------------- bf16 helpers ----------------
__device__ __forceinline__ unsigned pkbf(float lo, float hi) {
    __nv_bfloat162 h = __floats2bfloat162_rn(lo, hi);
    return *reinterpret_cast<unsigned*>(&h);
}

__device__ __forceinline__ void mma_bf16(float* d,
    unsigned a0, unsigned a1, unsigned a2, unsigned a3,
    unsigned b0, unsigned b1)
{
    asm volatile(
        "mma.sync.aligned.m16n8k16.row.col.f32.bf16.bf16.f32 "
        "{%0,%1,%2,%3},{%4,%5,%6,%7},{%8,%9},{%0,%1,%2,%3};\n"
        : "+f"(d[0]), "+f"(d[1]), "+f"(d[2]), "+f"(d[3])
        : "r"(a0), "r"(a1), "r"(a2), "r"(a3), "r"(b0), "r"(b1));
}

// ---------------- fragment conversion kernels ----------------
__global__ void conv_afrag_kernel()
{
    int gt = blockIdx.x * 256 + threadIdx.x;
    if (gt >= MT16 * KT16 * 32) return;
    int lane = gt & 31;
    int kt = (gt >> 5) & 31;
    int mt = gt >> 10;
    int gid = lane >> 2, tig = lane & 3;
    int r0 = mt * 16 + gid, r1 = r0 + 8;
    int c0 = kt * 16 + tig * 2;
    const float* A = g_outs;
    uint4 v;
    v.x = (r0 < BT) ? pkbf(A[(size_t)r0*512 + c0],     A[(size_t)r0*512 + c0 + 1]) : 0u;
    v.y = (r1 < BT) ? pkbf(A[(size_t)r1*512 + c0],     A[(size_t)r1*512 + c0 + 1]) : 0u;
    v.z = (r0 < BT) ? pkbf(A[(size_t)r0*512 + c0 + 8], A[(size_t)r0*512 + c0 + 9]) : 0u;
    v.w = (r1 < BT) ? pkbf(A[(size_t)r1*512 + c0 + 8], A[(size_t)r1*512 + c0 + 9]) : 0u;
    g_afrag[(mt * KT16 + kt) * 32 + lane] = v;
}

// emb A-frags: gathers emb_table[decoder_input[r]] directly
__global__ void conv_eafrag_kernel(const int* __restrict__ di,
                                   const float* __restrict__ et)
{
    int gt = blockIdx.x * 256 + threadIdx.x;
    if (gt >= MT16 * KT16 * 32) return;
    int lane = gt & 31;
    int kt = (gt >> 5) & 31;
    int mt = gt >> 10;
    int gid = lane >> 2, tig = lane & 3;
    int r0 = mt * 16 + gid, r1 = r0 + 8;
    int c0 = kt * 16 + tig * 2;
    uint4 v = make_uint4(0u, 0u, 0u, 0u);
    if (r0 < BT) {
        const float* e0 = et + (size_t)di[r0] * 512;
        v.x = pkbf(e0[c0], e0[c0 + 1]);
        v.z = pkbf(e0[c0 + 8], e0[c0 + 9]);
    }
    if (r1 < BT) {
        const float* e1 = et + (size_t)di[r1] * 512;
        v.y = pkbf(e1[c0], e1[c0 + 1]);
        v.w = pkbf(e1[c0 + 8], e1[c0 + 9]);
    }
    g_eafrag[(mt * KT16 + kt) * 32 + lane] = v;
}

// proj_w B-frags
__global__ void conv_bfrag_kernel(const float* __restrict__ W)
{
    int gt = blockIdx.x * 256 + threadIdx.x;
    int lane = gt & 31;
    int kt = (gt >> 5) & 31;
    int nt2 = gt >> 10;
    if (nt2 >= VV / 16) return;
    int gid = lane >> 2, tig = lane & 3;
    int k0 = kt * 16 + tig * 2;
    const float* w0 = W + (size_t)((nt2 * 2) * 8 + gid) * 512;
    const float* w1 = W + (size_t)((nt2 * 2 + 1) * 8 + gid) * 512;
    uint4 v;
    v.x = pkbf(w0[k0],     w0[k0 + 1]);
    v.y = pkbf(w0[k0 + 8], w0[k0 + 9]);
    v.z = pkbf(w1[k0],     w1[k0 + 1]);
    v.w = pkbf(w1[k0 + 8], w1[k0 + 9]);
    g_bfrag[(nt2 * KT16 + kt) * 32 + lane] = v;
}

// W_ih emb-slice B-frags: (n,k) = w_ih[n*1024 + 512 + k], N=2048, K=512
__global__ void conv_wfrag_kernel(const float* __restrict__ wih)
{
    int gt = blockIdx.x * 256 + threadIdx.x;
    int lane = gt & 31;
    int kt = (gt >> 5) & 31;
    int nt2 = gt >> 10;
    if (nt2 >= 2048 / 16) return;
    int gid = lane >> 2, tig = lane & 3;
    int k0 = kt * 16 + tig * 2;
    const float* w0 = wih + (size_t)((nt2 * 2) * 8 + gid) * 1024 + 512;
    const float* w1 = wih + (size_t)((nt2 * 2 + 1) * 8 + gid) * 1024 + 512;
    uint4 v;
    v.x = pkbf(w0[k0],     w0[k0 + 1]);
    v.y = pkbf(w0[k0 + 8], w0[k0 + 9]);
    v.z = pkbf(w1[k0],     w1[k0 + 1]);
    v.w = pkbf(w1[k0 + 8], w1[k0 + 9]);
    g_wfrag[(nt2 * KT16 + kt) * 32 + lane] = v;
}

// Wcomb B-frags directly from wih/whh: (n,k): k<512 -> wih[n*1024+k], else whh[n*512+k-512]
// N=2048 (nt2 in [0,128)), K=1024 (kt in [0,64))
__global__ void conv_wcfrag_kernel(const float* __restrict__ wih,
                                   const float* __restrict__ whh)
{
    int gt = blockIdx.x * 256 + threadIdx.x;
    int lane = gt & 31;
    int kt = (gt >> 5) & 63;
    int nt2 = gt >> 11;
    if (nt2 >= 128) return;
    int gid = lane >> 2, tig = lane & 3;
    int n0 = (nt2 * 2) * 8 + gid;
    int n1 = (nt2 * 2 + 1) * 8 + gid;
    int k0 = kt * 16 + tig * 2;
    const float *p0, *p1;
    if (k0 < 512) {
        p0 = wih + (size_t)n0 * 1024 + k0;
        p1 = wih + (size_t)n1 * 1024 + k0;
    } else {
        p0 = whh + (size_t)n0 * 512 + (k0 - 512);
        p1 = whh + (size_t)n1 * 512 + (k0 - 512);
    }
    uint4 v;
    v.x = pkbf(p0[0], p0[1]);
    v.y = pkbf(p0[8], p0[9]);
    v.z = pkbf(p1[0], p1[1]);
    v.w = pkbf(p1[8], p1[9]);
    g_wcfrag[(nt2 * 64 + kt) * 32 + lane] = v;
}

// enc A-frags: M=4096, K=512
__global__ void conv_encfrag_kernel(const float* __restrict__ enc)
{
    int gt = blockIdx.x * 256 + threadIdx.x;
    if (gt >= EMT * KT16 * 32) return;
    int lane = gt & 31;
    int kt = (gt >> 5) & 31;
    int mt = gt >> 10;
    int gid = lane >> 2, tig = lane & 3;
    int r0 = mt * 16 + gid, r1 = r0 + 8;
    int c0 = kt * 16 + tig * 2;
    uint4 v;
    v.x = pkbf(enc[(size_t)r0*512 + c0],     enc[(size_t)r0*512 + c0 + 1]);
    v.y = pkbf(enc[(size_t)r1*512 + c0],     enc[(size_t)r1*512 + c0 + 1]);
    v.z = pkbf(enc[(size_t)r0*512 + c0 + 8], enc[(size_t)r0*512 + c0 + 9]);
    v.w = pkbf(enc[(size_t)r1*512 + c0 + 8], enc[(size_t)r1*512 + c0 + 9]);
    g_encfrag[(mt * KT16 + kt) * 32 + lane] = v;
}

// attn_W B-frags: N=512, K=512
__global__ void conv_awfrag_kernel(const float* __restrict__ W)
{
    int gt = blockIdx.x * 256 + threadIdx.x;
    int lane = gt & 31;
    int kt = (gt >> 5) & 31;
    int nt2 = gt >> 10;
    if (nt2 >= 32) return;
    int gid = lane >> 2, tig = lane & 3;
    int k0 = kt * 16 + tig * 2;
    const float* w0 = W + (size_t)((nt2 * 2) * 8 + gid) * 512;
    const float* w1 = W + (size_t)((nt2 * 2 + 1) * 8 + gid) * 512;
    uint4 v;
    v.x = pkbf(w0[k0],     w0[k0 + 1]);
    v.y = pkbf(w0[k0 + 8], w0[k0 + 9]);
    v.z = pkbf(w1[k0],     w1[k0 + 1]);
    v.w = pkbf(w1[k0 + 8], w1[k0 + 9]);
    g_awfrag[(nt2 * KT16 + kt) * 32 + lane] = v;
}

// ---------------- HMMA frag GEMM core (R9 config: 8 warps, warp 32x64) ----------------
#define FRAG_LOOP16(Af, Bf, mt0, nt2b)                                         \
    const uint4* a0p = (Af) + (size_t)((mt0) * KT16) * 32 + lane;              \
    const uint4* a1p = (Af) + (size_t)(((mt0) + 1) * KT16) * 32 + lane;        \
    const uint4* bp0 = (Bf) + (size_t)(((nt2b) + 0) * KT16) * 32 + lane;       \
    const uint4* bp1 = (Bf) + (size_t)(((nt2b) + 1) * KT16) * 32 + lane;       \
    const uint4* bp2 = (Bf) + (size_t)(((nt2b) + 2) * KT16) * 32 + lane;       \
    const uint4* bp3 = (Bf) + (size_t)(((nt2b) + 3) * KT16) * 32 + lane;       \
    float acc[2][8][4] = {};                                                   \
    _Pragma("unroll 4")                                                        \
    for (int kt = 0; kt < KT16; kt++) {                                        \
        uint4 av0 = a0p[kt * 32];                                              \
        uint4 av1 = a1p[kt * 32];                                              \
        uint4 bv0 = bp0[kt * 32];                                              \
        uint4 bv1 = bp1[kt * 32];                                              \
        uint4 bv2 = bp2[kt * 32];                                              \
        uint4 bv3 = bp3[kt * 32];                                              \
        mma_bf16(acc[0][0], av0.x, av0.y, av0.z, av0.w, bv0.x, bv0.y);         \
        mma_bf16(acc[0][1], av0.x, av0.y, av0.z, av0.w, bv0.z, bv0.w);         \
        mma_bf16(acc[0][2], av0.x, av0.y, av0.z, av0.w, bv1.x, bv1.y);         \
        mma_bf16(acc[0][3], av0.x, av0.y, av0.z, av0.w, bv1.z, bv1.w);         \
        mma_bf16(acc[0][4], av0.x, av0.y, av0.z, av0.w, bv2.x, bv2.y);         \
        mma_bf16(acc[0][5], av0.x, av0.y, av0.z, av0.w, bv2.z, bv2.w);         \
        mma_bf16(acc[0][6], av0.x, av0.y, av0.z, av0.w, bv3.x, bv3.y);         \
        mma_bf16(acc[0][7], av0.x, av0.y, av0.z, av0.w, bv3.z, bv3.w);         \
        mma_bf16(acc[1][0], av1.x, av1.y, av1.z, av1.w, bv0.x, bv0.y);         \
        mma_bf16(acc[1][1], av1.x, av1.y, av1.z, av1.w, bv0.z, bv0.w);         \
        mma_bf16(acc[1][2], av1.x, av1.y, av1.z, av1.w, bv1.x, bv1.y);         \
        mma_bf16(acc[1][3], av1.x, av1.y, av1.z, av1.w, bv1.z, bv1.w);         \
        mma_bf16(acc[1][4], av1.x, av1.y, av1.z, av1.w, bv2.x, bv2.y);         \
        mma_bf16(acc[1][5], av1.x, av1.y, av1.z, av1.w, bv2.z, bv2.w);         \
        mma_bf16(acc[1][6], av1.x, av1.y, av1.z, av1.w, bv3.x, bv3.y);         \
        mma_bf16(acc[1][7], av1.x, av1.y, av1.z, av1.w, bv3.z, bv3.w);         \
    }

// proj: fused bias + per-row logsumexp partials (R9 winner)
__global__ void __launch_bounds__(256)
proj_hmma_kernel(const uint4* __restrict__ Af, const uint4* __restrict__ Bf,
                 const float* __restrict__ pb)
{
    __shared__ float sb[128];
    __shared__ float smax[2][128], ssum[2][128];
    const int tid = threadIdx.x, lane = tid & 31, wid = tid >> 5;
    const int wm = wid >> 1, wn = wid & 1;
    const int gid = lane >> 2, tig = lane & 3;
    const int nb = blockIdx.x, mb = blockIdx.y;

    if (tid < 128) sb[tid] = pb[nb * 128 + tid];

    FRAG_LOOP16(Af, Bf, mb * 8 + wm * 2, nb * 8 + wn * 4)
    __syncthreads();

#pragma unroll
    for (int f = 0; f < 2; f++) {
#pragma unroll
        for (int half = 0; half < 2; half++) {
            float v[16];
#pragma unroll
            for (int nf = 0; nf < 8; nf++) {
                float b0 = sb[wn * 64 + nf * 8 + tig * 2];
                float b1 = sb[wn * 64 + nf * 8 + tig * 2 + 1];
                v[nf * 2]     = acc[f][nf][half * 2]     + b0;
                v[nf * 2 + 1] = acc[f][nf][half * 2 + 1] + b1;
            }
            float mx = v[0];
#pragma unroll
            for (int i = 1; i < 16; i++) mx = fmaxf(mx, v[i]);
            mx = fmaxf(mx, __shfl_xor_sync(0xffffffffu, mx, 1));
            mx = fmaxf(mx, __shfl_xor_sync(0xffffffffu, mx, 2));
            float se = 0.f;
#pragma unroll
            for (int i = 0; i < 16; i++) se += expf(v[i] - mx);
            se += __shfl_xor_sync(0xffffffffu, se, 1);
            se += __shfl_xor_sync(0xffffffffu, se, 2);
            if (tig == 0) {
                int rowl = wm * 32 + f * 16 + half * 8 + gid;
                smax[wn][rowl] = mx;
                ssum[wn][rowl] = se;
            }
        }
    }
    __syncthreads();

    if (tid < 128) {
        int row = mb * 128 + tid;
        if (row < BT) {
            float m0 = smax[0][tid], m1 = smax[1][tid];
            float M = fmaxf(m0, m1);
            float S = ssum[0][tid] * expf(m0 - M) + ssum[1][tid] * expf(m1 - M);
            g_pmax[(size_t)row * NT2 + nb] = M;
            g_psum[(size_t)row * NT2 + nb] = S;
        }
    }
}

// xproj: C = embA @ WihB^T + biassum
__global__ void __launch_bounds__(256)
xproj_hmma_kernel(const uint4* __restrict__ Af, const uint4* __restrict__ Bf)
{
    __shared__ float sb[128];
    const int tid = threadIdx.x, lane = tid & 31, wid = tid >> 5;
    const int wm = wid >> 1, wn = wid & 1;
    const int gid = lane >> 2, tig = lane & 3;
    const int nb = blockIdx.x, mb = blockIdx.y;

    if (tid < 128) sb[tid] = g_biassum[nb * 128 + tid];

    FRAG_LOOP16(Af, Bf, mb * 8 + wm * 2, nb * 8 + wn * 4)
    __syncthreads();

#pragma unroll
    for (int f = 0; f < 2; f++) {
#pragma unroll
        for (int half = 0; half < 2; half++) {
            int r = mb * 128 + wm * 32 + f * 16 + half * 8 + gid;
            if (r >= BT) continue;
#pragma unroll
            for (int nf = 0; nf < 8; nf++) {
                int nl = wn * 64 + nf * 8 + tig * 2;
                float v0 = acc[f][nf][half * 2]     + sb[nl];
                float v1 = acc[f][nf][half * 2 + 1] + sb[nl + 1];
                *reinterpret_cast<float2*>(
                    &g_xproj[(size_t)r * 2048 + nb * 128 + nl]) = make_float2(v0, v1);
            }
        }
    }
}

// E2 = enc @ attn_W^T (store fp32, no bias; M=4096, N=512)
__global__ void __launch_bounds__(256)
e2_hmma_kernel(const uint4* __restrict__ Af, const uint4* __restrict__ Bf)
{
    const int tid = threadIdx.x, lane = tid & 31, wid = tid >> 5;
    const int wm = wid >> 1, wn = wid & 1;
    const int gid = lane >> 2, tig = lane & 3;
    const int nb = blockIdx.x, mb = blockIdx.y;

    FRAG_LOOP16(Af, Bf, mb * 8 + wm * 2, nb * 8 + wn * 4)

#pragma unroll
    for (int f = 0; f < 2; f++) {
#pragma unroll
        for (int half = 0; half < 2; half++) {
            int r = mb * 128 + wm * 32 + f * 16 + half * 8 + gid;
#pragma unroll
            for (int nf = 0; nf < 8; nf++) {
                int nl = wn * 64 + nf * 8 + tig * 2;
                *reinterpret_cast<float2*>(
                    &g_E2[(size_t)r * 512 + nb * 128 + nl]) =
                    make_float2(acc[f][nf][half * 2], acc[f][nf][half * 2 + 1]);
            }
        }
    }
}

// gates (per step): g_gates[64,2048] = gfrag(bf16 [ctx|h]) @ wcfrag^T + xproj[:,t,:]
// grid 32 (nb, 64 cols each), 8 warps: wm=mt (4), wn (2 x 32 cols)
__global__ void __launch_bounds__(256)
gates_hmma_kernel(int t)
{
    const int tid = threadIdx.x, lane = tid & 31, wid = tid >> 5;
    const int wm = wid >> 1, wn = wid & 1;
    const int gid = lane >> 2, tig = lane & 3;
    const int nb = blockIdx.x;

    const uint4* ap  = g_gfrag + (size_t)(wm * 64) * 32 + lane;
    const uint4* bq0 = g_wcfrag + (size_t)((nb * 4 + wn * 2) * 64) * 32 + lane;
    const uint4* bq1 = bq0 + (size_t)64 * 32;
    float acc[4][4] = {};

#pragma unroll 4
    for (int kt = 0; kt < 64; kt++) {
        uint4 av  = ap[kt * 32];
        uint4 bv0 = bq0[kt * 32];
        uint4 bv1 = bq1[kt * 32];
        mma_bf16(acc[0], av.x, av.y, av.z, av.w, bv0.x, bv0.y);
        mma_bf16(acc[1], av.x, av.y, av.z, av.w, bv0.z, bv0.w);
        mma_bf16(acc[2], av.x, av.y, av.z, av.w, bv1.x, bv1.y);
        mma_bf16(acc[3], av.x, av.y, av.z, av.w, bv1.z, bv1.w);
    }

    // rows r0 = wm*16+gid, r1 = r0+8 (= batch b); cols nb*64 + wn*32 + nf*8 + tig*2
#pragma unroll
    for (int nf = 0; nf < 4; nf++) {
        int c = nb * 64 + wn * 32 + nf * 8 + tig * 2;
        int r0 = wm * 16 + gid, r1 = r0 + 8;
        const float2 x0 = *reinterpret_cast<const float2*>(
            &g_xproj[(size_t)(r0 * TT + t) * 2048 + c]);
        const float2 x1 = *reinterpret_cast<const float2*>(
            &g_xproj[(size_t)(r1 * TT + t) * 2048 + c]);
        *reinterpret_cast<float2*>(&g_gates[r0 * 2048 + c]) =
            make_float2(acc[nf][0] + x0.x, acc[nf][1] + x0.y);
        *reinterpret_cast<float2*>(&g_gates[r1 * 2048 + c]) =
            make_float2(acc[nf][2] + x1.x, acc[nf][3] + x1.y);
    }
}

// ---------------- gfrag scatter helper (row r, even col c, pair v0,v1) ----------------
__device__ __forceinline__ void gfrag_store(int r, int c, float v0, float v1)
{
    int mt = r >> 4, rr = r & 15, gid = rr & 7;
    int kt = c >> 4, cc = c & 15;
    int tig = (cc & 7) >> 1;
    int comp = ((cc >> 3) << 1) | (rr >> 3);
    unsigned* base = reinterpret_cast<unsigned*>(
        &g_gfrag[(size_t)(mt * 64 + kt) * 32 + gid * 4 + tig]);
    base[comp] = pkbf(v0, v1);
}

// ---------------- fused pointwise(t-1) + attention(t) ----------------
__global__ void pwattn_kernel(const float* __restrict__ enc,
                              const float* __restrict__ be2d, int t)
{
    __shared__ float hs[512];
    __shared__ float sc[64];
    __shared__ float s_inv;
    const int b = blockIdx.x, tid = threadIdx.x;
    const int j = 2 * tid;                 // pair base (0..510)

    if (t > 0) {
        const int gb = b * 2048;
        float2 gi = *reinterpret_cast<const float2*>(&g_gates[gb + j]);
        float2 gf = *reinterpret_cast<const float2*>(&g_gates[gb + 512 + j]);
        float2 gg = *reinterpret_cast<const float2*>(&g_gates[gb + 1024 + j]);
        float2 go = *reinterpret_cast<const float2*>(&g_gates[gb + 1536 + j]);
        float2 cc = *reinterpret_cast<const float2*>(&g_c[b * 512 + j]);
        float si0 = 1.f / (1.f + expf(-gi.x)), si1 = 1.f / (1.f + expf(-gi.y));
        float sf0 = 1.f / (1.f + expf(-gf.x)), sf1 = 1.f / (1.f + expf(-gf.y));
        float so0 = 1.f / (1.f + expf(-go.x)), so1 = 1.f / (1.f + expf(-go.y));
        cc.x = sf0 * cc.x + si0 * tanhf(gg.x);
        cc.y = sf1 * cc.y + si1 * tanhf(gg.y);
        *reinterpret_cast<float2*>(&g_c[b * 512 + j]) = cc;
        float h0 = so0 * tanhf(cc.x);
        float h1 = so1 * tanhf(cc.y);
        *reinterpret_cast<float2*>(
            &g_outs[(size_t)(b * TT + (t - 1)) * 512 + j]) = make_float2(h0, h1);
        *reinterpret_cast<float2*>(&g_inp2[b * 1024 + 512 + j]) = make_float2(h0, h1);
        hs[j] = h0; hs[j + 1] = h1;
        gfrag_store(b, 512 + j, h0, h1);
    } else {
        float2 hv = *reinterpret_cast<const float2*>(&g_inp2[b * 1024 + 512 + j]);
        hv.x += be2d[j]; hv.y += be2d[j + 1];
        *reinterpret_cast<float2*>(&g_inp2[b * 1024 + 512 + j]) = hv;
        hs[j] = hv.x; hs[j + 1] = hv.y;
        gfrag_store(b, 512 + j, hv.x, hv.y);
    }
    __syncthreads();

    const int w = tid >> 5, lane = tid & 31;
    const float* E2b = g_E2 + (size_t)b * SS * 512;
    for (int s = w; s < SS; s += 8) {
        const float* er = E2b + (size_t)s * 512;
        float a = 0.f;
        for (int k = lane; k < 512; k += 32) a += hs[k] * er[k];
#pragma unroll
        for (int o = 16; o; o >>= 1) a += __shfl_xor_sync(0xffffffffu, a, o);
        if (lane == 0) sc[s] = a;
    }
    __syncthreads();

    if (w == 0) {
        float v0 = sc[lane], v1 = sc[lane + 32];
        float m = fmaxf(v0, v1);
#pragma unroll
        for (int o = 16; o; o >>= 1) m = fmaxf(m, __shfl_xor_sync(0xffffffffu, m, o));
        float e0 = expf(v0 - m), e1 = expf(v1 - m);
        float ssm = e0 + e1;
#pragma unroll
        for (int o = 16; o; o >>= 1) ssm += __shfl_xor_sync(0xffffffffu, ssm, o);
        sc[lane] = e0; sc[lane + 32] = e1;
        if (lane == 0) s_inv = 1.f / ssm;
    }
    __syncthreads();

    float inv = s_inv;
    const float* eb = enc + (size_t)b * SS * DD;
    {
        float a0 = 0.f, a1 = 0.f;
#pragma unroll 8
        for (int s = 0; s < SS; s++) {
            float2 e = *reinterpret_cast<const float2*>(&eb[(size_t)s * DD + j]);
            a0 += sc[s] * e.x;
            a1 += sc[s] * e.y;
        }
        a0 *= inv; a1 *= inv;
        *reinterpret_cast<float2*>(&g_inp2[b * 1024 + j]) = make_float2(a0, a1);
        gfrag_store(b, j, a0, a1);
    }
}

// final pointwise (produces outs[T-1])
__global__ void pw_final_kernel()
{
    const int b = blockIdx.x, j = threadIdx.x;
    const int gb = b * 2048;
    float gi = g_gates[gb + j];
    float gf = g_gates[gb + 512 + j];
    float gg = g_gates[gb + 1024 + j];
    float go = g_gates[gb + 1536 + j];
    float c = g_c[b * 512 + j];
    float si = 1.f / (1.f + expf(-gi));
    float sf = 1.f / (1.f + expf(-gf));
    float so = 1.f / (1.f + expf(-go));
    c = sf * c + si * tanhf(gg);
    float h = so * tanhf(c);
    g_outs[(size_t)(b * TT + TT - 1) * 512 + j] = h;
}

// ---------------- one-time prep ----------------
__global__ void prep_small_kernel(const float* __restrict__ eh, const float* __restrict__ st,
                                  const float* __restrict__ bih, const float* __restrict__ bhh)
{
    int i = blockIdx.x * blockDim.x + threadIdx.x;
    if (i < BB * 640) {
        int b = i / 640, j = i - b * 640;
        g_cat[i] = (j < 512) ? eh[b * 512 + j] : st[b * 512 + 384 + (j - 512)];
    } else if (i < BB * 640 + 2048) {
        int j = i - BB * 640;
        g_biassum[j] = bih[j] + bhh[j];
    } else if (i < BB * 640 + 2048 + BB * 512) {
        g_c[i - (BB * 640 + 2048)] = 0.f;
    } else if (i < BB * 640 + 2048 + 2 * BB * 512) {
        int i2 = i - (BB * 640 + 2048 + BB * 512);
        int b = i2 >> 9, j = i2 & 511;
        g_inp2[b * 1024 + 512 + j] = 0.f;   // h0 accumulator
    }
}

// ---------------- loss ----------------
__global__ void lablogit_kernel(const int* __restrict__ lab, const float* __restrict__ pw,
                                const float* __restrict__ pb)
{
    int gt = blockIdx.x * blockDim.x + threadIdx.x;
    int w = gt >> 5, lane = gt & 31;
    if (w >= BT) return;
    int l = lab[w];
    const float* o  = g_outs + (size_t)w * 512;
    const float* wr = pw + (size_t)l * 512;
    float a = 0.f;
    for (int k = lane; k < 512; k += 32) a += o[k] * wr[k];
#pragma unroll
    for (int off = 16; off; off >>= 1) a += __shfl_xor_sync(0xffffffffu, a, off);
    if (lane == 0) g_lab[w] = a + pb[l];
}

__global__ void loss_row_kernel(const int* __restrict__ lab)
{
    __shared__ float red[128];
    const int r = blockIdx.x, tid = threadIdx.x;
    const float* pm = g_pmax + (size_t)r * NT2;
    const float* ps = g_psum + (size_t)r * NT2;
    float m = -1e30f;
    for (int j = tid; j < NT2; j += 128) m = fmaxf(m, pm[j]);
    red[tid] = m; __syncthreads();
    for (int s = 64; s; s >>= 1) { if (tid < s) red[tid] = fmaxf(red[tid], red[tid + s]); __syncthreads(); }
    float M = red[0]; __syncthreads();
    float se = 0.f;
    for (int j = tid; j < NT2; j += 128) se += ps[j] * expf(pm[j] - M);
    red[tid] = se; __syncthreads();
    for (int s = 64; s; s >>= 1) { if (tid < s) red[tid] += red[tid + s]; __syncthreads(); }
    if (tid == 0) {
        float lse = M + logf(red[0]);
        int l = lab[r];
        g_nll[r] = (l > 0) ? (lse - g_lab[r]) : 0.f;
    }
}

__global__ void loss_final_kernel(const int* __restrict__ lab, float* __restrict__ out)
{
    __shared__ float red[64];
    const int b = threadIdx.x;
    float s = 0.f, cnt = 0.f;
    for (int t = 0; t < TT; t++) {
        int r = b * TT + t;
        s += g_nll[r];
        cnt += (lab[r] > 0) ? 1.f : 0.f;
    }
    red[b] = s / (cnt + 1e-6f);
    __syncthreads();
    if (b == 0) {
        float a = 0.f;
        for (int i = 0; i < 64; i++) a += red[i];
        out[0] = a / 64.f;
    }
}

// ---------------- host launcher ----------------
extern "C" void kernel_launch(void* const* d_in, const int* in_sizes, int n_in,
                              void* d_out, int out_size)
{
    const float* encode_hidden = (const float*)d_in[0];
    const float* encode_output = (const float*)d_in[1];
    const int*   seq_label     = (const int*)  d_in[3];
    const int*   decoder_input = (const int*)  d_in[4];
    const float* style_emb     = (const float*)d_in[5];
    const float* w_e2d         = (const float*)d_in[6];
    const float* b_e2d         = (const float*)d_in[7];
    const float* attn_W        = (const float*)d_in[8];
    const float* emb_table     = (const float*)d_in[9];
    const float* w_ih          = (const float*)d_in[10];
    const float* w_hh          = (const float*)d_in[11];
    const float* b_ih          = (const float*)d_in[12];
    const float* b_hh          = (const float*)d_in[13];
    const float* proj_w        = (const float*)d_in[14];
    const float* proj_b        = (const float*)d_in[15];
    float* out = (float*)d_out;

    float *p_cat, *p_inp2;
    uint4 *p_afrag, *p_eafrag, *p_bfrag, *p_wfrag, *p_encfrag, *p_awfrag;
    cudaGetSymbolAddress((void**)&p_cat,     g_cat);
    cudaGetSymbolAddress((void**)&p_inp2,    g_inp2);
    cudaGetSymbolAddress((void**)&p_afrag,   g_afrag);
    cudaGetSymbolAddress((void**)&p_eafrag,  g_eafrag);
    cudaGetSymbolAddress((void**)&p_bfrag,   g_bfrag);
    cudaGetSymbolAddress((void**)&p_wfrag,   g_wfrag);
    cudaGetSymbolAddress((void**)&p_encfrag, g_encfrag);
    cudaGetSymbolAddress((void**)&p_awfrag,  g_awfrag);

    // one-time prep + fragment conversions
    prep_small_kernel<<<552, 256>>>(encode_hidden, style_emb, b_ih, b_hh);
    conv_eafrag_kernel<<<352, 256>>>(decoder_input, emb_table);
    conv_wfrag_kernel<<<512, 256>>>(w_ih);
    conv_wcfrag_kernel<<<1024, 256>>>(w_ih, w_hh);
    conv_encfrag_kernel<<<1024, 256>>>(encode_output);
    conv_awfrag_kernel<<<128, 256>>>(attn_W);
    conv_bfrag_kernel<<<8000, 256>>>(proj_w);

    // h0 = cat @ W_e2d^T (bias added in pwattn t=0), split-K atomic fp32
    gemm_atomic_kernel<<<dim3(8, 1, 5), 256>>>(128,
        p_cat, 640, w_e2d, 640, p_inp2 + 512, 1024);

    // xproj = emb @ W_ih_emb^T + biassum  (HMMA)
    xproj_hmma_kernel<<<dim3(16, MT128), 256>>>(p_eafrag, p_wfrag);

    // E2 = enc @ attn_W^T  (HMMA)
    e2_hmma_kernel<<<dim3(4, 32), 256>>>(p_encfrag, p_awfrag);

    for (int t = 0; t < TT; t++) {
        pwattn_kernel<<<64, 256>>>(encode_output, b_e2d, t);
        gates_hmma_kernel<<<32, 256>>>(t);
    }
    pw_final_kernel<<<64, 512>>>();

    // loss
    conv_afrag_kernel<<<352, 256>>>();
    lablogit_kernel<<<168, 256>>>(seq_label, proj_w, proj_b);
    proj_hmma_kernel<<<dim3(NT2, MT128), 256>>>(p_afrag, p_bfrag, proj_b);
    loss_row_kernel<<<BT, 128>>>(seq_label);
    loss_final_kernel<<<1, 64>>>(seq_label, out);
}

// round 13
// speedup vs baseline: 1.4436x; 1.0086x over previous
#include <cuda_runtime.h>
#include <cuda_bf16.h>
#include <cstdint>
#include <math.h>

// Problem constants
#define BB 64
#define SS 64
#define TT 21
#define DD 512
#define VV 32000
#define BT (BB*TT)        // 1344
#define NT2 250           // proj N tiles of 128
#define MT128 11          // ceil(1344/128)
#define MT16 88           // m-frag tiles (1408/16)
#define KT16 32           // 512/16 k-steps
#define EMT 256           // enc m-frag tiles (4096/16)

// ---------------- static device scratch ----------------
__device__ float g_cat[BB*640];
__device__ float g_inp2[BB*1024];      // [context | h] fp32
__device__ float g_gates[BB*2048];
__device__ float g_c[BB*512];
__device__ float g_xproj[BT*2048];
__device__ float g_biassum[2048];
__device__ float g_E2[BB*SS*512];      // enc @ attn_W^T
__device__ float g_outs[BT*512];
__device__ uint4 g_afrag[MT16*KT16*32];        // outs A-frags
__device__ uint4 g_eafrag[MT16*KT16*32];       // emb  A-frags
__device__ uint4 g_bfrag[(VV/16)*KT16*32];     // proj_w B-frags
__device__ uint4 g_wfrag[(2048/16)*KT16*32];   // W_ih_emb B-frags
__device__ uint4 g_wcfrag[128*64*32];          // [W_ih_ctx|W_hh] B-frags (N=2048,K=1024)
__device__ uint4 g_encfrag[EMT*KT16*32];       // enc A-frags
__device__ uint4 g_awfrag[32*KT16*32];         // attn_W B-frags
__device__ uint4 g_gfrag[4*64*32];             // per-step [ctx|h] A-frags (M=64,K=1024)
__device__ float g_pmax[BT*NT2];
__device__ float g_psum[BT*NT2];
__device__ float g_lab[BT];
__device__ float g_nll[BT];

// ---------------- packed f32x2 helpers (h0 FFMA GEMM) ----------------
__device__ __forceinline__ double pk2(float lo, float hi) {
    double d;
    asm("mov.b64 %0, {%1, %2};" : "=d"(d) : "f"(lo), "f"(hi));
    return d;
}
__device__ __forceinline__ void upk2(double v, float& lo, float& hi) {
    asm("mov.b64 {%0, %1}, %2;" : "=f"(lo), "=f"(hi) : "d"(v));
}
__device__ __forceinline__ void fma2(double& d, double a, double b) {
    asm("fma.rn.f32x2 %0, %1, %2, %0;" : "+d"(d) : "d"(a), "d"(b));
}

// ---------------- generic fp32 GEMM (only for h0), split-K atomic ----------------
__global__ void gemm_atomic_kernel(int klen,
                                   const float* __restrict__ A, int lda,
                                   const float* __restrict__ B, int ldb,
                                   float* __restrict__ C, int ldc)
{
    __shared__ float As[32][68];
    __shared__ float Bs[32][68];
    const int bm = blockIdx.y * 64;
    const int bn = blockIdx.x * 64;
    const int kbeg = blockIdx.z * klen;
    const int tid = threadIdx.x;
    const int tm = (tid >> 4) << 2;
    const int tn = (tid & 15) << 2;
    double acc2[4][2] = {};

    for (int k0 = kbeg; k0 < kbeg + klen; k0 += 32) {
#pragma unroll
        for (int i = 0; i < 8; i++) {
            int e = tid + i * 256;
            int m = e >> 5, k = e & 31;
            As[k][m] = A[(size_t)(bm + m) * lda + k0 + k];
        }
#pragma unroll
        for (int i = 0; i < 8; i++) {
            int e = tid + i * 256;
            int n = e >> 5, k = e & 31;
            Bs[k][n] = B[(size_t)(bn + n) * ldb + k0 + k];
        }
        __syncthreads();
#pragma unroll
        for (int k = 0; k < 32; k++) {
            float4 av = *reinterpret_cast<const float4*>(&As[k][tm]);
            float4 bv = *reinterpret_cast<const float4*>(&Bs[k][tn]);
            double b01 = pk2(bv.x, bv.y), b23 = pk2(bv.z, bv.w);
            double a0 = pk2(av.x, av.x), a1 = pk2(av.y, av.y);
            double a2 = pk2(av.z, av.z), a3 = pk2(av.w, av.w);
            fma2(acc2[0][0], a0, b01); fma2(acc2[0][1], a0, b23);
            fma2(acc2[1][0], a1, b01); fma2(acc2[1][1], a1, b23);
            fma2(acc2[2][0], a2, b01); fma2(acc2[2][1], a2, b23);
            fma2(acc2[3][0], a3, b01); fma2(acc2[3][1], a3, b23);
        }
        __syncthreads();
    }

    float acc[4][4];
#pragma unroll
    for (int i = 0; i < 4; i++) {
        upk2(acc2[i][0], acc[i][0], acc[i][1]);
        upk2(acc2[i][1], acc[i][2], acc[i][3]);
    }
#pragma unroll
    for (int i = 0; i < 4; i++) {
        size_t ro = (size_t)(bm + tm + i);
#pragma unroll
        for (int j = 0; j < 4; j++)
            atomicAdd(&C[ro * ldc + bn + tn + j], acc[i][j]);
    }
}

// ---------------- bf16 helpers ----------------
__device__ __forceinline__ unsigned pkbf(float lo, float hi) {
    __nv_bfloat162 h = __floats2bfloat162_rn(lo, hi);
    return *reinterpret_cast<unsigned*>(&h);
}

__device__ __forceinline__ void mma_bf16(float* d,
    unsigned a0, unsigned a1, unsigned a2, unsigned a3,
    unsigned b0, unsigned b1)
{
    asm volatile(
        "mma.sync.aligned.m16n8k16.row.col.f32.bf16.bf16.f32 "
        "{%0,%1,%2,%3},{%4,%5,%6,%7},{%8,%9},{%0,%1,%2,%3};\n"
        : "+f"(d[0]), "+f"(d[1]), "+f"(d[2]), "+f"(d[3])
        : "r"(a0), "r"(a1), "r"(a2), "r"(a3), "r"(b0), "r"(b1));
}

// ---------------- fragment conversion kernels ----------------
__global__ void conv_afrag_kernel()
{
    int gt = blockIdx.x * 256 + threadIdx.x;
    if (gt >= MT16 * KT16 * 32) return;
    int lane = gt & 31;
    int kt = (gt >> 5) & 31;
    int mt = gt >> 10;
    int gid = lane >> 2, tig = lane & 3;
    int r0 = mt * 16 + gid, r1 = r0 + 8;
    int c0 = kt * 16 + tig * 2;
    const float* A = g_outs;
    uint4 v;
    v.x = (r0 < BT) ? pkbf(A[(size_t)r0*512 + c0],     A[(size_t)r0*512 + c0 + 1]) : 0u;
    v.y = (r1 < BT) ? pkbf(A[(size_t)r1*512 + c0],     A[(size_t)r1*512 + c0 + 1]) : 0u;
    v.z = (r0 < BT) ? pkbf(A[(size_t)r0*512 + c0 + 8], A[(size_t)r0*512 + c0 + 9]) : 0u;
    v.w = (r1 < BT) ? pkbf(A[(size_t)r1*512 + c0 + 8], A[(size_t)r1*512 + c0 + 9]) : 0u;
    g_afrag[(mt * KT16 + kt) * 32 + lane] = v;
}

// emb A-frags: gathers emb_table[decoder_input[r]] directly
__global__ void conv_eafrag_kernel(const int* __restrict__ di,
                                   const float* __restrict__ et)
{
    int gt = blockIdx.x * 256 + threadIdx.x;
    if (gt >= MT16 * KT16 * 32) return;
    int lane = gt & 31;
    int kt = (gt >> 5) & 31;
    int mt = gt >> 10;
    int gid = lane >> 2, tig = lane & 3;
    int r0 = mt * 16 + gid, r1 = r0 + 8;
    int c0 = kt * 16 + tig * 2;
    uint4 v = make_uint4(0u, 0u, 0u, 0u);
    if (r0 < BT) {
        const float* e0 = et + (size_t)di[r0] * 512;
        v.x = pkbf(e0[c0], e0[c0 + 1]);
        v.z = pkbf(e0[c0 + 8], e0[c0 + 9]);
    }
    if (r1 < BT) {
        const float* e1 = et + (size_t)di[r1] * 512;
        v.y = pkbf(e1[c0], e1[c0 + 1]);
        v.w = pkbf(e1[c0 + 8], e1[c0 + 9]);
    }
    g_eafrag[(mt * KT16 + kt) * 32 + lane] = v;
}

// proj_w B-frags
__global__ void conv_bfrag_kernel(const float* __restrict__ W)
{
    int gt = blockIdx.x * 256 + threadIdx.x;
    int lane = gt & 31;
    int kt = (gt >> 5) & 31;
    int nt2 = gt >> 10;
    if (nt2 >= VV / 16) return;
    int gid = lane >> 2, tig = lane & 3;
    int k0 = kt * 16 + tig * 2;
    const float* w0 = W + (size_t)((nt2 * 2) * 8 + gid) * 512;
    const float* w1 = W + (size_t)((nt2 * 2 + 1) * 8 + gid) * 512;
    uint4 v;
    v.x = pkbf(w0[k0],     w0[k0 + 1]);
    v.y = pkbf(w0[k0 + 8], w0[k0 + 9]);
    v.z = pkbf(w1[k0],     w1[k0 + 1]);
    v.w = pkbf(w1[k0 + 8], w1[k0 + 9]);
    g_bfrag[(nt2 * KT16 + kt) * 32 + lane] = v;
}

// W_ih emb-slice B-frags: (n,k) = w_ih[n*1024 + 512 + k], N=2048, K=512
__global__ void conv_wfrag_kernel(const float* __restrict__ wih)
{
    int gt = blockIdx.x * 256 + threadIdx.x;
    int lane = gt & 31;
    int kt = (gt >> 5) & 31;
    int nt2 = gt >> 10;
    if (nt2 >= 2048 / 16) return;
    int gid = lane >> 2, tig = lane & 3;
    int k0 = kt * 16 + tig * 2;
    const float* w0 = wih + (size_t)((nt2 * 2) * 8 + gid) * 1024 + 512;
    const float* w1 = wih + (size_t)((nt2 * 2 + 1) * 8 + gid) * 1024 + 512;
    uint4 v;
    v.x = pkbf(w0[k0],     w0[k0 + 1]);
    v.y = pkbf(w0[k0 + 8], w0[k0 + 9]);
    v.z = pkbf(w1[k0],     w1[k0 + 1]);
    v.w = pkbf(w1[k0 + 8], w1[k0 + 9]);
    g_wfrag[(nt2 * KT16 + kt) * 32 + lane] = v;
}

// Wcomb B-frags directly from wih/whh
__global__ void conv_wcfrag_kernel(const float* __restrict__ wih,
                                   const float* __restrict__ whh)
{
    int gt = blockIdx.x * 256 + threadIdx.x;
    int lane = gt & 31;
    int kt = (gt >> 5) & 63;
    int nt2 = gt >> 11;
    if (nt2 >= 128) return;
    int gid = lane >> 2, tig = lane & 3;
    int n0 = (nt2 * 2) * 8 + gid;
    int n1 = (nt2 * 2 + 1) * 8 + gid;
    int k0 = kt * 16 + tig * 2;
    const float *p0, *p1;
    if (k0 < 512) {
        p0 = wih + (size_t)n0 * 1024 + k0;
        p1 = wih + (size_t)n1 * 1024 + k0;
    } else {
        p0 = whh + (size_t)n0 * 512 + (k0 - 512);
        p1 = whh + (size_t)n1 * 512 + (k0 - 512);
    }
    uint4 v;
    v.x = pkbf(p0[0], p0[1]);
    v.y = pkbf(p0[8], p0[9]);
    v.z = pkbf(p1[0], p1[1]);
    v.w = pkbf(p1[8], p1[9]);
    g_wcfrag[(nt2 * 64 + kt) * 32 + lane] = v;
}

// enc A-frags: M=4096, K=512
__global__ void conv_encfrag_kernel(const float* __restrict__ enc)
{
    int gt = blockIdx.x * 256 + threadIdx.x;
    if (gt >= EMT * KT16 * 32) return;
    int lane = gt & 31;
    int kt = (gt >> 5) & 31;
    int mt = gt >> 10;
    int gid = lane >> 2, tig = lane & 3;
    int r0 = mt * 16 + gid, r1 = r0 + 8;
    int c0 = kt * 16 + tig * 2;
    uint4 v;
    v.x = pkbf(enc[(size_t)r0*512 + c0],     enc[(size_t)r0*512 + c0 + 1]);
    v.y = pkbf(enc[(size_t)r1*512 + c0],     enc[(size_t)r1*512 + c0 + 1]);
    v.z = pkbf(enc[(size_t)r0*512 + c0 + 8], enc[(size_t)r0*512 + c0 + 9]);
    v.w = pkbf(enc[(size_t)r1*512 + c0 + 8], enc[(size_t)r1*512 + c0 + 9]);
    g_encfrag[(mt * KT16 + kt) * 32 + lane] = v;
}

// attn_W B-frags: N=512, K=512
__global__ void conv_awfrag_kernel(const float* __restrict__ W)
{
    int gt = blockIdx.x * 256 + threadIdx.x;
    int lane = gt & 31;
    int kt = (gt >> 5) & 31;
    int nt2 = gt >> 10;
    if (nt2 >= 32) return;
    int gid = lane >> 2, tig = lane & 3;
    int k0 = kt * 16 + tig * 2;
    const float* w0 = W + (size_t)((nt2 * 2) * 8 + gid) * 512;
    const float* w1 = W + (size_t)((nt2 * 2 + 1) * 8 + gid) * 512;
    uint4 v;
    v.x = pkbf(w0[k0],     w0[k0 + 1]);
    v.y = pkbf(w0[k0 + 8], w0[k0 + 9]);
    v.z = pkbf(w1[k0],     w1[k0 + 1]);
    v.w = pkbf(w1[k0 + 8], w1[k0 + 9]);
    g_awfrag[(nt2 * KT16 + kt) * 32 + lane] = v;
}

// ---------------- HMMA frag GEMM core (R9 config: 8 warps, warp 32x64) ----------------
#define FRAG_LOOP16(Af, Bf, mt0, nt2b)                                         \
    const uint4* a0p = (Af) + (size_t)((mt0) * KT16) * 32 + lane;              \
    const uint4* a1p = (Af) + (size_t)(((mt0) + 1) * KT16) * 32 + lane;        \
    const uint4* bp0 = (Bf) + (size_t)(((nt2b) + 0) * KT16) * 32 + lane;       \
    const uint4* bp1 = (Bf) + (size_t)(((nt2b) + 1) * KT16) * 32 + lane;       \
    const uint4* bp2 = (Bf) + (size_t)(((nt2b) + 2) * KT16) * 32 + lane;       \
    const uint4* bp3 = (Bf) + (size_t)(((nt2b) + 3) * KT16) * 32 + lane;       \
    float acc[2][8][4] = {};                                                   \
    _Pragma("unroll 4")                                                        \
    for (int kt = 0; kt < KT16; kt++) {                                        \
        uint4 av0 = a0p[kt * 32];                                              \
        uint4 av1 = a1p[kt * 32];                                              \
        uint4 bv0 = bp0[kt * 32];                                              \
        uint4 bv1 = bp1[kt * 32];                                              \
        uint4 bv2 = bp2[kt * 32];                                              \
        uint4 bv3 = bp3[kt * 32];                                              \
        mma_bf16(acc[0][0], av0.x, av0.y, av0.z, av0.w, bv0.x, bv0.y);         \
        mma_bf16(acc[0][1], av0.x, av0.y, av0.z, av0.w, bv0.z, bv0.w);         \
        mma_bf16(acc[0][2], av0.x, av0.y, av0.z, av0.w, bv1.x, bv1.y);         \
        mma_bf16(acc[0][3], av0.x, av0.y, av0.z, av0.w, bv1.z, bv1.w);         \
        mma_bf16(acc[0][4], av0.x, av0.y, av0.z, av0.w, bv2.x, bv2.y);         \
        mma_bf16(acc[0][5], av0.x, av0.y, av0.z, av0.w, bv2.z, bv2.w);         \
        mma_bf16(acc[0][6], av0.x, av0.y, av0.z, av0.w, bv3.x, bv3.y);         \
        mma_bf16(acc[0][7], av0.x, av0.y, av0.z, av0.w, bv3.z, bv3.w);         \
        mma_bf16(acc[1][0], av1.x, av1.y, av1.z, av1.w, bv0.x, bv0.y);         \
        mma_bf16(acc[1][1], av1.x, av1.y, av1.z, av1.w, bv0.z, bv0.w);         \
        mma_bf16(acc[1][2], av1.x, av1.y, av1.z, av1.w, bv1.x, bv1.y);         \
        mma_bf16(acc[1][3], av1.x, av1.y, av1.z, av1.w, bv1.z, bv1.w);         \
        mma_bf16(acc[1][4], av1.x, av1.y, av1.z, av1.w, bv2.x, bv2.y);         \
        mma_bf16(acc[1][5], av1.x, av1.y, av1.z, av1.w, bv2.z, bv2.w);         \
        mma_bf16(acc[1][6], av1.x, av1.y, av1.z, av1.w, bv3.x, bv3.y);         \
        mma_bf16(acc[1][7], av1.x, av1.y, av1.z, av1.w, bv3.z, bv3.w);         \
    }

// 16-mma issue block on current registers
#define MMA_BLOCK16()                                                          \
        mma_bf16(acc[0][0], av0.x, av0.y, av0.z, av0.w, bv0.x, bv0.y);         \
        mma_bf16(acc[0][1], av0.x, av0.y, av0.z, av0.w, bv0.z, bv0.w);         \
        mma_bf16(acc[0][2], av0.x, av0.y, av0.z, av0.w, bv1.x, bv1.y);         \
        mma_bf16(acc[0][3], av0.x, av0.y, av0.z, av0.w, bv1.z, bv1.w);         \
        mma_bf16(acc[0][4], av0.x, av0.y, av0.z, av0.w, bv2.x, bv2.y);         \
        mma_bf16(acc[0][5], av0.x, av0.y, av0.z, av0.w, bv2.z, bv2.w);         \
        mma_bf16(acc[0][6], av0.x, av0.y, av0.z, av0.w, bv3.x, bv3.y);         \
        mma_bf16(acc[0][7], av0.x, av0.y, av0.z, av0.w, bv3.z, bv3.w);         \
        mma_bf16(acc[1][0], av1.x, av1.y, av1.z, av1.w, bv0.x, bv0.y);         \
        mma_bf16(acc[1][1], av1.x, av1.y, av1.z, av1.w, bv0.z, bv0.w);         \
        mma_bf16(acc[1][2], av1.x, av1.y, av1.z, av1.w, bv1.x, bv1.y);         \
        mma_bf16(acc[1][3], av1.x, av1.y, av1.z, av1.w, bv1.z, bv1.w);         \
        mma_bf16(acc[1][4], av1.x, av1.y, av1.z, av1.w, bv2.x, bv2.y);         \
        mma_bf16(acc[1][5], av1.x, av1.y, av1.z, av1.w, bv2.z, bv2.w);         \
        mma_bf16(acc[1][6], av1.x, av1.y, av1.z, av1.w, bv3.x, bv3.y);         \
        mma_bf16(acc[1][7], av1.x, av1.y, av1.z, av1.w, bv3.z, bv3.w);

// proj: fused bias + per-row logsumexp partials, depth-1 register prefetch
__global__ void __launch_bounds__(256, 2)
proj_hmma_kernel(const uint4* __restrict__ Af, const uint4* __restrict__ Bf,
                 const float* __restrict__ pb)
{
    __shared__ float sb[128];
    __shared__ float smax[2][128], ssum[2][128];
    const int tid = threadIdx.x, lane = tid & 31, wid = tid >> 5;
    const int wm = wid >> 1, wn = wid & 1;
    const int gid = lane >> 2, tig = lane & 3;
    const int nb = blockIdx.x, mb = blockIdx.y;

    if (tid < 128) sb[tid] = pb[nb * 128 + tid];

    const int mt0 = mb * 8 + wm * 2;
    const int nt2b = nb * 8 + wn * 4;
    const uint4* a0p = Af + (size_t)(mt0 * KT16) * 32 + lane;
    const uint4* a1p = Af + (size_t)((mt0 + 1) * KT16) * 32 + lane;
    const uint4* bp0 = Bf + (size_t)((nt2b + 0) * KT16) * 32 + lane;
    const uint4* bp1 = Bf + (size_t)((nt2b + 1) * KT16) * 32 + lane;
    const uint4* bp2 = Bf + (size_t)((nt2b + 2) * KT16) * 32 + lane;
    const uint4* bp3 = Bf + (size_t)((nt2b + 3) * KT16) * 32 + lane;

    float acc[2][8][4] = {};
    uint4 av0 = a0p[0], av1 = a1p[0];
    uint4 bv0 = bp0[0], bv1 = bp1[0], bv2 = bp2[0], bv3 = bp3[0];

#pragma unroll 1
    for (int kt = 0; kt < KT16; kt++) {
        const int kn = (kt < KT16 - 1 ? kt + 1 : kt) * 32;
        uint4 nav0 = a0p[kn], nav1 = a1p[kn];
        uint4 nbv0 = bp0[kn], nbv1 = bp1[kn], nbv2 = bp2[kn], nbv3 = bp3[kn];
        MMA_BLOCK16()
        av0 = nav0; av1 = nav1;
        bv0 = nbv0; bv1 = nbv1; bv2 = nbv2; bv3 = nbv3;
    }
    __syncthreads();   // sb ready

#pragma unroll
    for (int f = 0; f < 2; f++) {
#pragma unroll
        for (int half = 0; half < 2; half++) {
            float v[16];
#pragma unroll
            for (int nf = 0; nf < 8; nf++) {
                float b0 = sb[wn * 64 + nf * 8 + tig * 2];
                float b1 = sb[wn * 64 + nf * 8 + tig * 2 + 1];
                v[nf * 2]     = acc[f][nf][half * 2]     + b0;
                v[nf * 2 + 1] = acc[f][nf][half * 2 + 1] + b1;
            }
            float mx = v[0];
#pragma unroll
            for (int i = 1; i < 16; i++) mx = fmaxf(mx, v[i]);
            mx = fmaxf(mx, __shfl_xor_sync(0xffffffffu, mx, 1));
            mx = fmaxf(mx, __shfl_xor_sync(0xffffffffu, mx, 2));
            float se = 0.f;
#pragma unroll
            for (int i = 0; i < 16; i++) se += expf(v[i] - mx);
            se += __shfl_xor_sync(0xffffffffu, se, 1);
            se += __shfl_xor_sync(0xffffffffu, se, 2);
            if (tig == 0) {
                int rowl = wm * 32 + f * 16 + half * 8 + gid;
                smax[wn][rowl] = mx;
                ssum[wn][rowl] = se;
            }
        }
    }
    __syncthreads();

    if (tid < 128) {
        int row = mb * 128 + tid;
        if (row < BT) {
            float m0 = smax[0][tid], m1 = smax[1][tid];
            float M = fmaxf(m0, m1);
            float S = ssum[0][tid] * expf(m0 - M) + ssum[1][tid] * expf(m1 - M);
            g_pmax[(size_t)row * NT2 + nb] = M;
            g_psum[(size_t)row * NT2 + nb] = S;
        }
    }
}

// xproj: C = embA @ WihB^T + biassum
__global__ void __launch_bounds__(256)
xproj_hmma_kernel(const uint4* __restrict__ Af, const uint4* __restrict__ Bf)
{
    __shared__ float sb[128];
    const int tid = threadIdx.x, lane = tid & 31, wid = tid >> 5;
    const int wm = wid >> 1, wn = wid & 1;
    const int gid = lane >> 2, tig = lane & 3;
    const int nb = blockIdx.x, mb = blockIdx.y;

    if (tid < 128) sb[tid] = g_biassum[nb * 128 + tid];

    FRAG_LOOP16(Af, Bf, mb * 8 + wm * 2, nb * 8 + wn * 4)
    __syncthreads();

#pragma unroll
    for (int f = 0; f < 2; f++) {
#pragma unroll
        for (int half = 0; half < 2; half++) {
            int r = mb * 128 + wm * 32 + f * 16 + half * 8 + gid;
            if (r >= BT) continue;
#pragma unroll
            for (int nf = 0; nf < 8; nf++) {
                int nl = wn * 64 + nf * 8 + tig * 2;
                float v0 = acc[f][nf][half * 2]     + sb[nl];
                float v1 = acc[f][nf][half * 2 + 1] + sb[nl + 1];
                *reinterpret_cast<float2*>(
                    &g_xproj[(size_t)r * 2048 + nb * 128 + nl]) = make_float2(v0, v1);
            }
        }
    }
}

// E2 = enc @ attn_W^T (store fp32, no bias; M=4096, N=512)
__global__ void __launch_bounds__(256)
e2_hmma_kernel(const uint4* __restrict__ Af, const uint4* __restrict__ Bf)
{
    const int tid = threadIdx.x, lane = tid & 31, wid = tid >> 5;
    const int wm = wid >> 1, wn = wid & 1;
    const int gid = lane >> 2, tig = lane & 3;
    const int nb = blockIdx.x, mb = blockIdx.y;

    FRAG_LOOP16(Af, Bf, mb * 8 + wm * 2, nb * 8 + wn * 4)

#pragma unroll
    for (int f = 0; f < 2; f++) {
#pragma unroll
        for (int half = 0; half < 2; half++) {
            int r = mb * 128 + wm * 32 + f * 16 + half * 8 + gid;
#pragma unroll
            for (int nf = 0; nf < 8; nf++) {
                int nl = wn * 64 + nf * 8 + tig * 2;
                *reinterpret_cast<float2*>(
                    &g_E2[(size_t)r * 512 + nb * 128 + nl]) =
                    make_float2(acc[f][nf][half * 2], acc[f][nf][half * 2 + 1]);
            }
        }
    }
}

// gates (per step): g_gates[64,2048] = gfrag(bf16 [ctx|h]) @ wcfrag^T + xproj[:,t,:]
__global__ void __launch_bounds__(256)
gates_hmma_kernel(int t)
{
    const int tid = threadIdx.x, lane = tid & 31, wid = tid >> 5;
    const int wm = wid >> 1, wn = wid & 1;
    const int gid = lane >> 2, tig = lane & 3;
    const int nb = blockIdx.x;

    const uint4* ap  = g_gfrag + (size_t)(wm * 64) * 32 + lane;
    const uint4* bq0 = g_wcfrag + (size_t)((nb * 4 + wn * 2) * 64) * 32 + lane;
    const uint4* bq1 = bq0 + (size_t)64 * 32;
    float acc[4][4] = {};

#pragma unroll 4
    for (int kt = 0; kt < 64; kt++) {
        uint4 av  = ap[kt * 32];
        uint4 bv0 = bq0[kt * 32];
        uint4 bv1 = bq1[kt * 32];
        mma_bf16(acc[0], av.x, av.y, av.z, av.w, bv0.x, bv0.y);
        mma_bf16(acc[1], av.x, av.y, av.z, av.w, bv0.z, bv0.w);
        mma_bf16(acc[2], av.x, av.y, av.z, av.w, bv1.x, bv1.y);
        mma_bf16(acc[3], av.x, av.y, av.z, av.w, bv1.z, bv1.w);
    }

#pragma unroll
    for (int nf = 0; nf < 4; nf++) {
        int c = nb * 64 + wn * 32 + nf * 8 + tig * 2;
        int r0 = wm * 16 + gid, r1 = r0 + 8;
        const float2 x0 = *reinterpret_cast<const float2*>(
            &g_xproj[(size_t)(r0 * TT + t) * 2048 + c]);
        const float2 x1 = *reinterpret_cast<const float2*>(
            &g_xproj[(size_t)(r1 * TT + t) * 2048 + c]);
        *reinterpret_cast<float2*>(&g_gates[r0 * 2048 + c]) =
            make_float2(acc[nf][0] + x0.x, acc[nf][1] + x0.y);
        *reinterpret_cast<float2*>(&g_gates[r1 * 2048 + c]) =
            make_float2(acc[nf][2] + x1.x, acc[nf][3] + x1.y);
    }
}

// ---------------- gfrag scatter helper ----------------
__device__ __forceinline__ void gfrag_store(int r, int c, float v0, float v1)
{
    int mt = r >> 4, rr = r & 15, gid = rr & 7;
    int kt = c >> 4, cc = c & 15;
    int tig = (cc & 7) >> 1;
    int comp = ((cc >> 3) << 1) | (rr >> 3);
    unsigned* base = reinterpret_cast<unsigned*>(
        &g_gfrag[(size_t)(mt * 64 + kt) * 32 + gid * 4 + tig]);
    base[comp] = pkbf(v0, v1);
}

// ---------------- fused pointwise(t-1) + attention(t) ----------------
__global__ void pwattn_kernel(const float* __restrict__ enc,
                              const float* __restrict__ be2d, int t)
{
    __shared__ float hs[512];
    __shared__ float sc[64];
    __shared__ float s_inv;
    const int b = blockIdx.x, tid = threadIdx.x;
    const int j = 2 * tid;                 // pair base (0..510)

    if (t > 0) {
        const int gb = b * 2048;
        float2 gi = *reinterpret_cast<const float2*>(&g_gates[gb + j]);
        float2 gf = *reinterpret_cast<const float2*>(&g_gates[gb + 512 + j]);
        float2 gg = *reinterpret_cast<const float2*>(&g_gates[gb + 1024 + j]);
        float2 go = *reinterpret_cast<const float2*>(&g_gates[gb + 1536 + j]);
        float2 cc = *reinterpret_cast<const float2*>(&g_c[b * 512 + j]);
        float si0 = 1.f / (1.f + expf(-gi.x)), si1 = 1.f / (1.f + expf(-gi.y));
        float sf0 = 1.f / (1.f + expf(-gf.x)), sf1 = 1.f / (1.f + expf(-gf.y));
        float so0 = 1.f / (1.f + expf(-go.x)), so1 = 1.f / (1.f + expf(-go.y));
        cc.x = sf0 * cc.x + si0 * tanhf(gg.x);
        cc.y = sf1 * cc.y + si1 * tanhf(gg.y);
        *reinterpret_cast<float2*>(&g_c[b * 512 + j]) = cc;
        float h0 = so0 * tanhf(cc.x);
        float h1 = so1 * tanhf(cc.y);
        *reinterpret_cast<float2*>(
            &g_outs[(size_t)(b * TT + (t - 1)) * 512 + j]) = make_float2(h0, h1);
        *reinterpret_cast<float2*>(&g_inp2[b * 1024 + 512 + j]) = make_float2(h0, h1);
        hs[j] = h0; hs[j + 1] = h1;
        gfrag_store(b, 512 + j, h0, h1);
    } else {
        float2 hv = *reinterpret_cast<const float2*>(&g_inp2[b * 1024 + 512 + j]);
        hv.x += be2d[j]; hv.y += be2d[j + 1];
        *reinterpret_cast<float2*>(&g_inp2[b * 1024 + 512 + j]) = hv;
        hs[j] = hv.x; hs[j + 1] = hv.y;
        gfrag_store(b, 512 + j, hv.x, hv.y);
    }
    __syncthreads();

    const int w = tid >> 5, lane = tid & 31;
    const float* E2b = g_E2 + (size_t)b * SS * 512;
    for (int s = w; s < SS; s += 8) {
        const float* er = E2b + (size_t)s * 512;
        float a = 0.f;
        for (int k = lane; k < 512; k += 32) a += hs[k] * er[k];
#pragma unroll
        for (int o = 16; o; o >>= 1) a += __shfl_xor_sync(0xffffffffu, a, o);
        if (lane == 0) sc[s] = a;
    }
    __syncthreads();

    if (w == 0) {
        float v0 = sc[lane], v1 = sc[lane + 32];
        float m = fmaxf(v0, v1);
#pragma unroll
        for (int o = 16; o; o >>= 1) m = fmaxf(m, __shfl_xor_sync(0xffffffffu, m, o));
        float e0 = expf(v0 - m), e1 = expf(v1 - m);
        float ssm = e0 + e1;
#pragma unroll
        for (int o = 16; o; o >>= 1) ssm += __shfl_xor_sync(0xffffffffu, ssm, o);
        sc[lane] = e0; sc[lane + 32] = e1;
        if (lane == 0) s_inv = 1.f / ssm;
    }
    __syncthreads();

    float inv = s_inv;
    const float* eb = enc + (size_t)b * SS * DD;
    {
        float a0 = 0.f, a1 = 0.f;
#pragma unroll 8
        for (int s = 0; s < SS; s++) {
            float2 e = *reinterpret_cast<const float2*>(&eb[(size_t)s * DD + j]);
            a0 += sc[s] * e.x;
            a1 += sc[s] * e.y;
        }
        a0 *= inv; a1 *= inv;
        *reinterpret_cast<float2*>(&g_inp2[b * 1024 + j]) = make_float2(a0, a1);
        gfrag_store(b, j, a0, a1);
    }
}

// final pointwise (produces outs[T-1])
__global__ void pw_final_kernel()
{
    const int b = blockIdx.x, j = threadIdx.x;
    const int gb = b * 2048;
    float gi = g_gates[gb + j];
    float gf = g_gates[gb + 512 + j];
    float gg = g_gates[gb + 1024 + j];
    float go = g_gates[gb + 1536 + j];
    float c = g_c[b * 512 + j];
    float si = 1.f / (1.f + expf(-gi));
    float sf = 1.f / (1.f + expf(-gf));
    float so = 1.f / (1.f + expf(-go));
    c = sf * c + si * tanhf(gg);
    float h = so * tanhf(c);
    g_outs[(size_t)(b * TT + TT - 1) * 512 + j] = h;
}

// ---------------- one-time prep ----------------
__global__ void prep_small_kernel(const float* __restrict__ eh, const float* __restrict__ st,
                                  const float* __restrict__ bih, const float* __restrict__ bhh)
{
    int i = blockIdx.x * blockDim.x + threadIdx.x;
    if (i < BB * 640) {
        int b = i / 640, j = i - b * 640;
        g_cat[i] = (j < 512) ? eh[b * 512 + j] : st[b * 512 + 384 + (j - 512)];
    } else if (i < BB * 640 + 2048) {
        int j = i - BB * 640;
        g_biassum[j] = bih[j] + bhh[j];
    } else if (i < BB * 640 + 2048 + BB * 512) {
        g_c[i - (BB * 640 + 2048)] = 0.f;
    } else if (i < BB * 640 + 2048 + 2 * BB * 512) {
        int i2 = i - (BB * 640 + 2048 + BB * 512);
        int b = i2 >> 9, j = i2 & 511;
        g_inp2[b * 1024 + 512 + j] = 0.f;   // h0 accumulator
    }
}

// ---------------- loss ----------------
__global__ void lablogit_kernel(const int* __restrict__ lab, const float* __restrict__ pw,
                                const float* __restrict__ pb)
{
    int gt = blockIdx.x * blockDim.x + threadIdx.x;
    int w = gt >> 5, lane = gt & 31;
    if (w >= BT) return;
    int l = lab[w];
    const float* o  = g_outs + (size_t)w * 512;
    const float* wr = pw + (size_t)l * 512;
    float a = 0.f;
    for (int k = lane; k < 512; k += 32) a += o[k] * wr[k];
#pragma unroll
    for (int off = 16; off; off >>= 1) a += __shfl_xor_sync(0xffffffffu, a, off);
    if (lane == 0) g_lab[w] = a + pb[l];
}

__global__ void loss_row_kernel(const int* __restrict__ lab)
{
    __shared__ float red[128];
    const int r = blockIdx.x, tid = threadIdx.x;
    const float* pm = g_pmax + (size_t)r * NT2;
    const float* ps = g_psum + (size_t)r * NT2;
    float m = -1e30f;
    for (int j = tid; j < NT2; j += 128) m = fmaxf(m, pm[j]);
    red[tid] = m; __syncthreads();
    for (int s = 64; s; s >>= 1) { if (tid < s) red[tid] = fmaxf(red[tid], red[tid + s]); __syncthreads(); }
    float M = red[0]; __syncthreads();
    float se = 0.f;
    for (int j = tid; j < NT2; j += 128) se += ps[j] * expf(pm[j] - M);
    red[tid] = se; __syncthreads();
    for (int s = 64; s; s >>= 1) { if (tid < s) red[tid] += red[tid + s]; __syncthreads(); }
    if (tid == 0) {
        float lse = M + logf(red[0]);
        int l = lab[r];
        g_nll[r] = (l > 0) ? (lse - g_lab[r]) : 0.f;
    }
}

__global__ void loss_final_kernel(const int* __restrict__ lab, float* __restrict__ out)
{
    __shared__ float red[64];
    const int b = threadIdx.x;
    float s = 0.f, cnt = 0.f;
    for (int t = 0; t < TT; t++) {
        int r = b * TT + t;
        s += g_nll[r];
        cnt += (lab[r] > 0) ? 1.f : 0.f;
    }
    red[b] = s / (cnt + 1e-6f);
    __syncthreads();
    if (b == 0) {
        float a = 0.f;
        for (int i = 0; i < 64; i++) a += red[i];
        out[0] = a / 64.f;
    }
}

// ---------------- host launcher ----------------
extern "C" void kernel_launch(void* const* d_in, const int* in_sizes, int n_in,
                              void* d_out, int out_size)
{
    const float* encode_hidden = (const float*)d_in[0];
    const float* encode_output = (const float*)d_in[1];
    const int*   seq_label     = (const int*)  d_in[3];
    const int*   decoder_input = (const int*)  d_in[4];
    const float* style_emb     = (const float*)d_in[5];
    const float* w_e2d         = (const float*)d_in[6];
    const float* b_e2d         = (const float*)d_in[7];
    const float* attn_W        = (const float*)d_in[8];
    const float* emb_table     = (const float*)d_in[9];
    const float* w_ih          = (const float*)d_in[10];
    const float* w_hh          = (const float*)d_in[11];
    const float* b_ih          = (const float*)d_in[12];
    const float* b_hh          = (const float*)d_in[13];
    const float* proj_w        = (const float*)d_in[14];
    const float* proj_b        = (const float*)d_in[15];
    float* out = (float*)d_out;

    float *p_cat, *p_inp2;
    uint4 *p_afrag, *p_eafrag, *p_bfrag, *p_wfrag, *p_encfrag, *p_awfrag;
    cudaGetSymbolAddress((void**)&p_cat,     g_cat);
    cudaGetSymbolAddress((void**)&p_inp2,    g_inp2);
    cudaGetSymbolAddress((void**)&p_afrag,   g_afrag);
    cudaGetSymbolAddress((void**)&p_eafrag,  g_eafrag);
    cudaGetSymbolAddress((void**)&p_bfrag,   g_bfrag);
    cudaGetSymbolAddress((void**)&p_wfrag,   g_wfrag);
    cudaGetSymbolAddress((void**)&p_encfrag, g_encfrag);
    cudaGetSymbolAddress((void**)&p_awfrag,  g_awfrag);

    // one-time prep + fragment conversions
    prep_small_kernel<<<552, 256>>>(encode_hidden, style_emb, b_ih, b_hh);
    conv_eafrag_kernel<<<352, 256>>>(decoder_input, emb_table);
    conv_wfrag_kernel<<<512, 256>>>(w_ih);
    conv_wcfrag_kernel<<<1024, 256>>>(w_ih, w_hh);
    conv_encfrag_kernel<<<1024, 256>>>(encode_output);
    conv_awfrag_kernel<<<128, 256>>>(attn_W);
    conv_bfrag_kernel<<<8000, 256>>>(proj_w);

    // h0 = cat @ W_e2d^T (bias added in pwattn t=0), split-K atomic fp32
    gemm_atomic_kernel<<<dim3(8, 1, 5), 256>>>(128,
        p_cat, 640, w_e2d, 640, p_inp2 + 512, 1024);

    // xproj = emb @ W_ih_emb^T + biassum  (HMMA)
    xproj_hmma_kernel<<<dim3(16, MT128), 256>>>(p_eafrag, p_wfrag);

    // E2 = enc @ attn_W^T  (HMMA)
    e2_hmma_kernel<<<dim3(4, 32), 256>>>(p_encfrag, p_awfrag);

    for (int t = 0; t < TT; t++) {
        pwattn_kernel<<<64, 256>>>(encode_output, b_e2d, t);
        gates_hmma_kernel<<<32, 256>>>(t);
    }
    pw_final_kernel<<<64, 512>>>();

    // loss
    conv_afrag_kernel<<<352, 256>>>();
    lablogit_kernel<<<168, 256>>>(seq_label, proj_w, proj_b);
    proj_hmma_kernel<<<dim3(NT2, MT128), 256>>>(p_afrag, p_bfrag, proj_b);
    loss_row_kernel<<<BT, 128>>>(seq_label);
    loss_final_kernel<<<1, 64>>>(seq_label, out);
}

// round 14
// speedup vs baseline: 2.0340x; 1.4090x over previous
#include <cuda_runtime.h>
#include <cuda_bf16.h>
#include <cstdint>
#include <math.h>

// Problem constants
#define BB 64
#define SS 64
#define TT 21
#define DD 512
#define VV 32000
#define BT (BB*TT)        // 1344
#define NT2 250           // proj N tiles of 128
#define MT128 11          // ceil(1344/128)
#define MT16 88           // m-frag tiles (1408/16)
#define KT16 32           // 512/16 k-steps
#define EMT 256           // enc m-frag tiles (4096/16)

// ---------------- static device scratch ----------------
__device__ float g_cat[BB*640];
__device__ float g_inp2[BB*1024];      // h0 accumulator ([512..1024) per batch)
__device__ float g_gates[BB*2048];
__device__ float g_c[BB*512];
__device__ float g_xproj[BT*2048];
__device__ float g_biassum[2048];
__device__ float g_E2[BB*SS*512];      // enc @ attn_W^T
__device__ float g_outs[BT*512];
__device__ uint4 g_afrag[MT16*KT16*32];        // outs A-frags (written by loop kernel)
__device__ uint4 g_eafrag[MT16*KT16*32];       // emb  A-frags
__device__ uint4 g_bfrag[(VV/16)*KT16*32];     // proj_w B-frags
__device__ uint4 g_wfrag[(2048/16)*KT16*32];   // W_ih_emb B-frags
__device__ uint4 g_wcfrag[128*64*32];          // [W_ih_ctx|W_hh] B-frags (N=2048,K=1024)
__device__ uint4 g_encfrag[EMT*KT16*32];       // enc A-frags
__device__ uint4 g_awfrag[32*KT16*32];         // attn_W B-frags
__device__ uint4 g_gfrag[4*64*32];             // per-step [ctx|h] A-frags (M=64,K=1024)
__device__ float g_pmax[BT*NT2];
__device__ float g_psum[BT*NT2];
__device__ float g_lab[BT];
__device__ float g_nll[BT];
__device__ unsigned g_bar_count = 0;
__device__ volatile unsigned g_bar_gen = 0;

// ---------------- grid barrier (64 co-resident CTAs) ----------------
__device__ __forceinline__ void grid_barrier()
{
    __syncthreads();
    if (threadIdx.x == 0) {
        __threadfence();
        unsigned gen = g_bar_gen;
        if (atomicAdd(&g_bar_count, 1u) == BB - 1) {
            g_bar_count = 0;
            __threadfence();
            g_bar_gen = gen + 1;
        } else {
            while (g_bar_gen == gen) { }
        }
    }
    __syncthreads();
}

// ---------------- packed f32x2 helpers (h0 FFMA GEMM) ----------------
__device__ __forceinline__ double pk2(float lo, float hi) {
    double d;
    asm("mov.b64 %0, {%1, %2};" : "=d"(d) : "f"(lo), "f"(hi));
    return d;
}
__device__ __forceinline__ void upk2(double v, float& lo, float& hi) {
    asm("mov.b64 {%0, %1}, %2;" : "=f"(lo), "=f"(hi) : "d"(v));
}
__device__ __forceinline__ void fma2(double& d, double a, double b) {
    asm("fma.rn.f32x2 %0, %1, %2, %0;" : "+d"(d) : "d"(a), "d"(b));
}

// ---------------- generic fp32 GEMM (only for h0), split-K atomic ----------------
__global__ void gemm_atomic_kernel(int klen,
                                   const float* __restrict__ A, int lda,
                                   const float* __restrict__ B, int ldb,
                                   float* __restrict__ C, int ldc)
{
    __shared__ float As[32][68];
    __shared__ float Bs[32][68];
    const int bm = blockIdx.y * 64;
    const int bn = blockIdx.x * 64;
    const int kbeg = blockIdx.z * klen;
    const int tid = threadIdx.x;
    const int tm = (tid >> 4) << 2;
    const int tn = (tid & 15) << 2;
    double acc2[4][2] = {};

    for (int k0 = kbeg; k0 < kbeg + klen; k0 += 32) {
#pragma unroll
        for (int i = 0; i < 8; i++) {
            int e = tid + i * 256;
            int m = e >> 5, k = e & 31;
            As[k][m] = A[(size_t)(bm + m) * lda + k0 + k];
        }
#pragma unroll
        for (int i = 0; i < 8; i++) {
            int e = tid + i * 256;
            int n = e >> 5, k = e & 31;
            Bs[k][n] = B[(size_t)(bn + n) * ldb + k0 + k];
        }
        __syncthreads();
#pragma unroll
        for (int k = 0; k < 32; k++) {
            float4 av = *reinterpret_cast<const float4*>(&As[k][tm]);
            float4 bv = *reinterpret_cast<const float4*>(&Bs[k][tn]);
            double b01 = pk2(bv.x, bv.y), b23 = pk2(bv.z, bv.w);
            double a0 = pk2(av.x, av.x), a1 = pk2(av.y, av.y);
            double a2 = pk2(av.z, av.z), a3 = pk2(av.w, av.w);
            fma2(acc2[0][0], a0, b01); fma2(acc2[0][1], a0, b23);
            fma2(acc2[1][0], a1, b01); fma2(acc2[1][1], a1, b23);
            fma2(acc2[2][0], a2, b01); fma2(acc2[2][1], a2, b23);
            fma2(acc2[3][0], a3, b01); fma2(acc2[3][1], a3, b23);
        }
        __syncthreads();
    }

    float acc[4][4];
#pragma unroll
    for (int i = 0; i < 4; i++) {
        upk2(acc2[i][0], acc[i][0], acc[i][1]);
        upk2(acc2[i][1], acc[i][2], acc[i][3]);
    }
#pragma unroll
    for (int i = 0; i < 4; i++) {
        size_t ro = (size_t)(bm + tm + i);
#pragma unroll
        for (int j = 0; j < 4; j++)
            atomicAdd(&C[ro * ldc + bn + tn + j], acc[i][j]);
    }
}

// ---------------- bf16 helpers ----------------
__device__ __forceinline__ unsigned pkbf(float lo, float hi) {
    __nv_bfloat162 h = __floats2bfloat162_rn(lo, hi);
    return *reinterpret_cast<unsigned*>(&h);
}

__device__ __forceinline__ void mma_bf16(float* d,
    unsigned a0, unsigned a1, unsigned a2, unsigned a3,
    unsigned b0, unsigned b1)
{
    asm volatile(
        "mma.sync.aligned.m16n8k16.row.col.f32.bf16.bf16.f32 "
        "{%0,%1,%2,%3},{%4,%5,%6,%7},{%8,%9},{%0,%1,%2,%3};\n"
        : "+f"(d[0]), "+f"(d[1]), "+f"(d[2]), "+f"(d[3])
        : "r"(a0), "r"(a1), "r"(a2), "r"(a3), "r"(b0), "r"(b1));
}

// ---------------- fragment conversion kernels ----------------
// emb A-frags: gathers emb_table[decoder_input[r]] directly
__global__ void conv_eafrag_kernel(const int* __restrict__ di,
                                   const float* __restrict__ et)
{
    int gt = blockIdx.x * 256 + threadIdx.x;
    if (gt >= MT16 * KT16 * 32) return;
    int lane = gt & 31;
    int kt = (gt >> 5) & 31;
    int mt = gt >> 10;
    int gid = lane >> 2, tig = lane & 3;
    int r0 = mt * 16 + gid, r1 = r0 + 8;
    int c0 = kt * 16 + tig * 2;
    uint4 v = make_uint4(0u, 0u, 0u, 0u);
    if (r0 < BT) {
        const float* e0 = et + (size_t)di[r0] * 512;
        v.x = pkbf(e0[c0], e0[c0 + 1]);
        v.z = pkbf(e0[c0 + 8], e0[c0 + 9]);
    }
    if (r1 < BT) {
        const float* e1 = et + (size_t)di[r1] * 512;
        v.y = pkbf(e1[c0], e1[c0 + 1]);
        v.w = pkbf(e1[c0 + 8], e1[c0 + 9]);
    }
    g_eafrag[(mt * KT16 + kt) * 32 + lane] = v;
}

// proj_w B-frags
__global__ void conv_bfrag_kernel(const float* __restrict__ W)
{
    int gt = blockIdx.x * 256 + threadIdx.x;
    int lane = gt & 31;
    int kt = (gt >> 5) & 31;
    int nt2 = gt >> 10;
    if (nt2 >= VV / 16) return;
    int gid = lane >> 2, tig = lane & 3;
    int k0 = kt * 16 + tig * 2;
    const float* w0 = W + (size_t)((nt2 * 2) * 8 + gid) * 512;
    const float* w1 = W + (size_t)((nt2 * 2 + 1) * 8 + gid) * 512;
    uint4 v;
    v.x = pkbf(w0[k0],     w0[k0 + 1]);
    v.y = pkbf(w0[k0 + 8], w0[k0 + 9]);
    v.z = pkbf(w1[k0],     w1[k0 + 1]);
    v.w = pkbf(w1[k0 + 8], w1[k0 + 9]);
    g_bfrag[(nt2 * KT16 + kt) * 32 + lane] = v;
}

// W_ih emb-slice B-frags: (n,k) = w_ih[n*1024 + 512 + k], N=2048, K=512
__global__ void conv_wfrag_kernel(const float* __restrict__ wih)
{
    int gt = blockIdx.x * 256 + threadIdx.x;
    int lane = gt & 31;
    int kt = (gt >> 5) & 31;
    int nt2 = gt >> 10;
    if (nt2 >= 2048 / 16) return;
    int gid = lane >> 2, tig = lane & 3;
    int k0 = kt * 16 + tig * 2;
    const float* w0 = wih + (size_t)((nt2 * 2) * 8 + gid) * 1024 + 512;
    const float* w1 = wih + (size_t)((nt2 * 2 + 1) * 8 + gid) * 1024 + 512;
    uint4 v;
    v.x = pkbf(w0[k0],     w0[k0 + 1]);
    v.y = pkbf(w0[k0 + 8], w0[k0 + 9]);
    v.z = pkbf(w1[k0],     w1[k0 + 1]);
    v.w = pkbf(w1[k0 + 8], w1[k0 + 9]);
    g_wfrag[(nt2 * KT16 + kt) * 32 + lane] = v;
}

// Wcomb B-frags directly from wih/whh
__global__ void conv_wcfrag_kernel(const float* __restrict__ wih,
                                   const float* __restrict__ whh)
{
    int gt = blockIdx.x * 256 + threadIdx.x;
    int lane = gt & 31;
    int kt = (gt >> 5) & 63;
    int nt2 = gt >> 11;
    if (nt2 >= 128) return;
    int gid = lane >> 2, tig = lane & 3;
    int n0 = (nt2 * 2) * 8 + gid;
    int n1 = (nt2 * 2 + 1) * 8 + gid;
    int k0 = kt * 16 + tig * 2;
    const float *p0, *p1;
    if (k0 < 512) {
        p0 = wih + (size_t)n0 * 1024 + k0;
        p1 = wih + (size_t)n1 * 1024 + k0;
    } else {
        p0 = whh + (size_t)n0 * 512 + (k0 - 512);
        p1 = whh + (size_t)n1 * 512 + (k0 - 512);
    }
    uint4 v;
    v.x = pkbf(p0[0], p0[1]);
    v.y = pkbf(p0[8], p0[9]);
    v.z = pkbf(p1[0], p1[1]);
    v.w = pkbf(p1[8], p1[9]);
    g_wcfrag[(nt2 * 64 + kt) * 32 + lane] = v;
}

// enc A-frags: M=4096, K=512
__global__ void conv_encfrag_kernel(const float* __restrict__ enc)
{
    int gt = blockIdx.x * 256 + threadIdx.x;
    if (gt >= EMT * KT16 * 32) return;
    int lane = gt & 31;
    int kt = (gt >> 5) & 31;
    int mt = gt >> 10;
    int gid = lane >> 2, tig = lane & 3;
    int r0 = mt * 16 + gid, r1 = r0 + 8;
    int c0 = kt * 16 + tig * 2;
    uint4 v;
    v.x = pkbf(enc[(size_t)r0*512 + c0],     enc[(size_t)r0*512 + c0 + 1]);
    v.y = pkbf(enc[(size_t)r1*512 + c0],     enc[(size_t)r1*512 + c0 + 1]);
    v.z = pkbf(enc[(size_t)r0*512 + c0 + 8], enc[(size_t)r0*512 + c0 + 9]);
    v.w = pkbf(enc[(size_t)r1*512 + c0 + 8], enc[(size_t)r1*512 + c0 + 9]);
    g_encfrag[(mt * KT16 + kt) * 32 + lane] = v;
}

// attn_W B-frags: N=512, K=512
__global__ void conv_awfrag_kernel(const float* __restrict__ W)
{
    int gt = blockIdx.x * 256 + threadIdx.x;
    int lane = gt & 31;
    int kt = (gt >> 5) & 31;
    int nt2 = gt >> 10;
    if (nt2 >= 32) return;
    int gid = lane >> 2, tig = lane & 3;
    int k0 = kt * 16 + tig * 2;
    const float* w0 = W + (size_t)((nt2 * 2) * 8 + gid) * 512;
    const float* w1 = W + (size_t)((nt2 * 2 + 1) * 8 + gid) * 512;
    uint4 v;
    v.x = pkbf(w0[k0],     w0[k0 + 1]);
    v.y = pkbf(w0[k0 + 8], w0[k0 + 9]);
    v.z = pkbf(w1[k0],     w1[k0 + 1]);
    v.w = pkbf(w1[k0 + 8], w1[k0 + 9]);
    g_awfrag[(nt2 * KT16 + kt) * 32 + lane] = v;
}

// ---------------- HMMA frag GEMM core (R9 config: 8 warps, warp 32x64) ----------------
#define FRAG_LOOP16(Af, Bf, mt0, nt2b)                                         \
    const uint4* a0p = (Af) + (size_t)((mt0) * KT16) * 32 + lane;              \
    const uint4* a1p = (Af) + (size_t)(((mt0) + 1) * KT16) * 32 + lane;        \
    const uint4* bp0 = (Bf) + (size_t)(((nt2b) + 0) * KT16) * 32 + lane;       \
    const uint4* bp1 = (Bf) + (size_t)(((nt2b) + 1) * KT16) * 32 + lane;       \
    const uint4* bp2 = (Bf) + (size_t)(((nt2b) + 2) * KT16) * 32 + lane;       \
    const uint4* bp3 = (Bf) + (size_t)(((nt2b) + 3) * KT16) * 32 + lane;       \
    float acc[2][8][4] = {};                                                   \
    _Pragma("unroll 4")                                                        \
    for (int kt = 0; kt < KT16; kt++) {                                        \
        uint4 av0 = a0p[kt * 32];                                              \
        uint4 av1 = a1p[kt * 32];                                              \
        uint4 bv0 = bp0[kt * 32];                                              \
        uint4 bv1 = bp1[kt * 32];                                              \
        uint4 bv2 = bp2[kt * 32];                                              \
        uint4 bv3 = bp3[kt * 32];                                              \
        mma_bf16(acc[0][0], av0.x, av0.y, av0.z, av0.w, bv0.x, bv0.y);         \
        mma_bf16(acc[0][1], av0.x, av0.y, av0.z, av0.w, bv0.z, bv0.w);         \
        mma_bf16(acc[0][2], av0.x, av0.y, av0.z, av0.w, bv1.x, bv1.y);         \
        mma_bf16(acc[0][3], av0.x, av0.y, av0.z, av0.w, bv1.z, bv1.w);         \
        mma_bf16(acc[0][4], av0.x, av0.y, av0.z, av0.w, bv2.x, bv2.y);         \
        mma_bf16(acc[0][5], av0.x, av0.y, av0.z, av0.w, bv2.z, bv2.w);         \
        mma_bf16(acc[0][6], av0.x, av0.y, av0.z, av0.w, bv3.x, bv3.y);         \
        mma_bf16(acc[0][7], av0.x, av0.y, av0.z, av0.w, bv3.z, bv3.w);         \
        mma_bf16(acc[1][0], av1.x, av1.y, av1.z, av1.w, bv0.x, bv0.y);         \
        mma_bf16(acc[1][1], av1.x, av1.y, av1.z, av1.w, bv0.z, bv0.w);         \
        mma_bf16(acc[1][2], av1.x, av1.y, av1.z, av1.w, bv1.x, bv1.y);         \
        mma_bf16(acc[1][3], av1.x, av1.y, av1.z, av1.w, bv1.z, bv1.w);         \
        mma_bf16(acc[1][4], av1.x, av1.y, av1.z, av1.w, bv2.x, bv2.y);         \
        mma_bf16(acc[1][5], av1.x, av1.y, av1.z, av1.w, bv2.z, bv2.w);         \
        mma_bf16(acc[1][6], av1.x, av1.y, av1.z, av1.w, bv3.x, bv3.y);         \
        mma_bf16(acc[1][7], av1.x, av1.y, av1.z, av1.w, bv3.z, bv3.w);         \
    }

// 16-mma issue block on current registers
#define MMA_BLOCK16()                                                          \
        mma_bf16(acc[0][0], av0.x, av0.y, av0.z, av0.w, bv0.x, bv0.y);         \
        mma_bf16(acc[0][1], av0.x, av0.y, av0.z, av0.w, bv0.z, bv0.w);         \
        mma_bf16(acc[0][2], av0.x, av0.y, av0.z, av0.w, bv1.x, bv1.y);         \
        mma_bf16(acc[0][3], av0.x, av0.y, av0.z, av0.w, bv1.z, bv1.w);         \
        mma_bf16(acc[0][4], av0.x, av0.y, av0.z, av0.w, bv2.x, bv2.y);         \
        mma_bf16(acc[0][5], av0.x, av0.y, av0.z, av0.w, bv2.z, bv2.w);         \
        mma_bf16(acc[0][6], av0.x, av0.y, av0.z, av0.w, bv3.x, bv3.y);         \
        mma_bf16(acc[0][7], av0.x, av0.y, av0.z, av0.w, bv3.z, bv3.w);         \
        mma_bf16(acc[1][0], av1.x, av1.y, av1.z, av1.w, bv0.x, bv0.y);         \
        mma_bf16(acc[1][1], av1.x, av1.y, av1.z, av1.w, bv0.z, bv0.w);         \
        mma_bf16(acc[1][2], av1.x, av1.y, av1.z, av1.w, bv1.x, bv1.y);         \
        mma_bf16(acc[1][3], av1.x, av1.y, av1.z, av1.w, bv1.z, bv1.w);         \
        mma_bf16(acc[1][4], av1.x, av1.y, av1.z, av1.w, bv2.x, bv2.y);         \
        mma_bf16(acc[1][5], av1.x, av1.y, av1.z, av1.w, bv2.z, bv2.w);         \
        mma_bf16(acc[1][6], av1.x, av1.y, av1.z, av1.w, bv3.x, bv3.y);         \
        mma_bf16(acc[1][7], av1.x, av1.y, av1.z, av1.w, bv3.z, bv3.w);

// proj: fused bias + per-row logsumexp partials, depth-1 register prefetch (R13)
__global__ void __launch_bounds__(256, 2)
proj_hmma_kernel(const uint4* __restrict__ Af, const uint4* __restrict__ Bf,
                 const float* __restrict__ pb)
{
    __shared__ float sb[128];
    __shared__ float smax[2][128], ssum[2][128];
    const int tid = threadIdx.x, lane = tid & 31, wid = tid >> 5;
    const int wm = wid >> 1, wn = wid & 1;
    const int gid = lane >> 2, tig = lane & 3;
    const int nb = blockIdx.x, mb = blockIdx.y;

    if (tid < 128) sb[tid] = pb[nb * 128 + tid];

    const int mt0 = mb * 8 + wm * 2;
    const int nt2b = nb * 8 + wn * 4;
    const uint4* a0p = Af + (size_t)(mt0 * KT16) * 32 + lane;
    const uint4* a1p = Af + (size_t)((mt0 + 1) * KT16) * 32 + lane;
    const uint4* bp0 = Bf + (size_t)((nt2b + 0) * KT16) * 32 + lane;
    const uint4* bp1 = Bf + (size_t)((nt2b + 1) * KT16) * 32 + lane;
    const uint4* bp2 = Bf + (size_t)((nt2b + 2) * KT16) * 32 + lane;
    const uint4* bp3 = Bf + (size_t)((nt2b + 3) * KT16) * 32 + lane;

    float acc[2][8][4] = {};
    uint4 av0 = a0p[0], av1 = a1p[0];
    uint4 bv0 = bp0[0], bv1 = bp1[0], bv2 = bp2[0], bv3 = bp3[0];

#pragma unroll 1
    for (int kt = 0; kt < KT16; kt++) {
        const int kn = (kt < KT16 - 1 ? kt + 1 : kt) * 32;
        uint4 nav0 = a0p[kn], nav1 = a1p[kn];
        uint4 nbv0 = bp0[kn], nbv1 = bp1[kn], nbv2 = bp2[kn], nbv3 = bp3[kn];
        MMA_BLOCK16()
        av0 = nav0; av1 = nav1;
        bv0 = nbv0; bv1 = nbv1; bv2 = nbv2; bv3 = nbv3;
    }
    __syncthreads();   // sb ready

#pragma unroll
    for (int f = 0; f < 2; f++) {
#pragma unroll
        for (int half = 0; half < 2; half++) {
            float v[16];
#pragma unroll
            for (int nf = 0; nf < 8; nf++) {
                float b0 = sb[wn * 64 + nf * 8 + tig * 2];
                float b1 = sb[wn * 64 + nf * 8 + tig * 2 + 1];
                v[nf * 2]     = acc[f][nf][half * 2]     + b0;
                v[nf * 2 + 1] = acc[f][nf][half * 2 + 1] + b1;
            }
            float mx = v[0];
#pragma unroll
            for (int i = 1; i < 16; i++) mx = fmaxf(mx, v[i]);
            mx = fmaxf(mx, __shfl_xor_sync(0xffffffffu, mx, 1));
            mx = fmaxf(mx, __shfl_xor_sync(0xffffffffu, mx, 2));
            float se = 0.f;
#pragma unroll
            for (int i = 0; i < 16; i++) se += expf(v[i] - mx);
            se += __shfl_xor_sync(0xffffffffu, se, 1);
            se += __shfl_xor_sync(0xffffffffu, se, 2);
            if (tig == 0) {
                int rowl = wm * 32 + f * 16 + half * 8 + gid;
                smax[wn][rowl] = mx;
                ssum[wn][rowl] = se;
            }
        }
    }
    __syncthreads();

    if (tid < 128) {
        int row = mb * 128 + tid;
        if (row < BT) {
            float m0 = smax[0][tid], m1 = smax[1][tid];
            float M = fmaxf(m0, m1);
            float S = ssum[0][tid] * expf(m0 - M) + ssum[1][tid] * expf(m1 - M);
            g_pmax[(size_t)row * NT2 + nb] = M;
            g_psum[(size_t)row * NT2 + nb] = S;
        }
    }
}

// xproj: C = embA @ WihB^T + biassum
__global__ void __launch_bounds__(256)
xproj_hmma_kernel(const uint4* __restrict__ Af, const uint4* __restrict__ Bf)
{
    __shared__ float sb[128];
    const int tid = threadIdx.x, lane = tid & 31, wid = tid >> 5;
    const int wm = wid >> 1, wn = wid & 1;
    const int gid = lane >> 2, tig = lane & 3;
    const int nb = blockIdx.x, mb = blockIdx.y;

    if (tid < 128) sb[tid] = g_biassum[nb * 128 + tid];

    FRAG_LOOP16(Af, Bf, mb * 8 + wm * 2, nb * 8 + wn * 4)
    __syncthreads();

#pragma unroll
    for (int f = 0; f < 2; f++) {
#pragma unroll
        for (int half = 0; half < 2; half++) {
            int r = mb * 128 + wm * 32 + f * 16 + half * 8 + gid;
            if (r >= BT) continue;
#pragma unroll
            for (int nf = 0; nf < 8; nf++) {
                int nl = wn * 64 + nf * 8 + tig * 2;
                float v0 = acc[f][nf][half * 2]     + sb[nl];
                float v1 = acc[f][nf][half * 2 + 1] + sb[nl + 1];
                *reinterpret_cast<float2*>(
                    &g_xproj[(size_t)r * 2048 + nb * 128 + nl]) = make_float2(v0, v1);
            }
        }
    }
}

// E2 = enc @ attn_W^T (store fp32, no bias; M=4096, N=512)
__global__ void __launch_bounds__(256)
e2_hmma_kernel(const uint4* __restrict__ Af, const uint4* __restrict__ Bf)
{
    const int tid = threadIdx.x, lane = tid & 31, wid = tid >> 5;
    const int wm = wid >> 1, wn = wid & 1;
    const int gid = lane >> 2, tig = lane & 3;
    const int nb = blockIdx.x, mb = blockIdx.y;

    FRAG_LOOP16(Af, Bf, mb * 8 + wm * 2, nb * 8 + wn * 4)

#pragma unroll
    for (int f = 0; f < 2; f++) {
#pragma unroll
        for (int half = 0; half < 2; half++) {
            int r = mb * 128 + wm * 32 + f * 16 + half * 8 + gid;
#pragma unroll
            for (int nf = 0; nf < 8; nf++) {
                int nl = wn * 64 + nf * 8 + tig * 2;
                *reinterpret_cast<float2*>(
                    &g_E2[(size_t)r * 512 + nb * 128 + nl]) =
                    make_float2(acc[f][nf][half * 2], acc[f][nf][half * 2 + 1]);
            }
        }
    }
}

// ---------------- frag scatter helpers ----------------
__device__ __forceinline__ void gfrag_store(int r, int c, float v0, float v1)
{
    int mt = r >> 4, rr = r & 15, gid = rr & 7;
    int kt = c >> 4, cc = c & 15;
    int tig = (cc & 7) >> 1;
    int comp = ((cc >> 3) << 1) | (rr >> 3);
    unsigned* base = reinterpret_cast<unsigned*>(
        &g_gfrag[(size_t)(mt * 64 + kt) * 32 + gid * 4 + tig]);
    base[comp] = pkbf(v0, v1);
}

__device__ __forceinline__ void afrag_store(int r, int c, float v0, float v1)
{
    int mt = r >> 4, rr = r & 15, gid = rr & 7;
    int kt = c >> 4, cc = c & 15;
    int tig = (cc & 7) >> 1;
    int comp = ((cc >> 3) << 1) | (rr >> 3);
    unsigned* base = reinterpret_cast<unsigned*>(
        &g_afrag[(size_t)(mt * KT16 + kt) * 32 + gid * 4 + tig]);
    base[comp] = pkbf(v0, v1);
}

// ---------------- persistent loop kernel: 21 steps, 64 CTAs ----------------
__global__ void __launch_bounds__(256)
loop_kernel(const float* __restrict__ enc, const float* __restrict__ be2d)
{
    __shared__ float hs[512];
    __shared__ float sc[64];
    __shared__ float s_inv;
    const int b = blockIdx.x, tid = threadIdx.x;
    const int j = 2 * tid;
    const int wid = tid >> 5, lane = tid & 31;
    const int gid = lane >> 2, tig = lane & 3;

    for (int t = 0; t < TT; t++) {
        // ---- Phase A: pointwise(t-1) + attention(t) for batch b ----
        if (t > 0) {
            const int gb = b * 2048;
            float2 gi = *reinterpret_cast<const float2*>(&g_gates[gb + j]);
            float2 gf = *reinterpret_cast<const float2*>(&g_gates[gb + 512 + j]);
            float2 gg = *reinterpret_cast<const float2*>(&g_gates[gb + 1024 + j]);
            float2 go = *reinterpret_cast<const float2*>(&g_gates[gb + 1536 + j]);
            float2 cc = *reinterpret_cast<const float2*>(&g_c[b * 512 + j]);
            float si0 = 1.f / (1.f + expf(-gi.x)), si1 = 1.f / (1.f + expf(-gi.y));
            float sf0 = 1.f / (1.f + expf(-gf.x)), sf1 = 1.f / (1.f + expf(-gf.y));
            float so0 = 1.f / (1.f + expf(-go.x)), so1 = 1.f / (1.f + expf(-go.y));
            cc.x = sf0 * cc.x + si0 * tanhf(gg.x);
            cc.y = sf1 * cc.y + si1 * tanhf(gg.y);
            *reinterpret_cast<float2*>(&g_c[b * 512 + j]) = cc;
            float h0 = so0 * tanhf(cc.x);
            float h1 = so1 * tanhf(cc.y);
            int r = b * TT + (t - 1);
            *reinterpret_cast<float2*>(&g_outs[(size_t)r * 512 + j]) = make_float2(h0, h1);
            afrag_store(r, j, h0, h1);
            hs[j] = h0; hs[j + 1] = h1;
            gfrag_store(b, 512 + j, h0, h1);
        } else {
            float2 hv = *reinterpret_cast<const float2*>(&g_inp2[b * 1024 + 512 + j]);
            hv.x += be2d[j]; hv.y += be2d[j + 1];
            hs[j] = hv.x; hs[j + 1] = hv.y;
            gfrag_store(b, 512 + j, hv.x, hv.y);
        }
        __syncthreads();

        const float* E2b = g_E2 + (size_t)b * SS * 512;
        for (int s = wid; s < SS; s += 8) {
            const float* er = E2b + (size_t)s * 512;
            float a = 0.f;
            for (int k = lane; k < 512; k += 32) a += hs[k] * er[k];
#pragma unroll
            for (int o = 16; o; o >>= 1) a += __shfl_xor_sync(0xffffffffu, a, o);
            if (lane == 0) sc[s] = a;
        }
        __syncthreads();

        if (wid == 0) {
            float v0 = sc[lane], v1 = sc[lane + 32];
            float m = fmaxf(v0, v1);
#pragma unroll
            for (int o = 16; o; o >>= 1) m = fmaxf(m, __shfl_xor_sync(0xffffffffu, m, o));
            float e0 = expf(v0 - m), e1 = expf(v1 - m);
            float ssm = e0 + e1;
#pragma unroll
            for (int o = 16; o; o >>= 1) ssm += __shfl_xor_sync(0xffffffffu, ssm, o);
            sc[lane] = e0; sc[lane + 32] = e1;
            if (lane == 0) s_inv = 1.f / ssm;
        }
        __syncthreads();

        {
            float inv = s_inv;
            const float* eb = enc + (size_t)b * SS * DD;
            float a0 = 0.f, a1 = 0.f;
#pragma unroll 8
            for (int s = 0; s < SS; s++) {
                float2 e = *reinterpret_cast<const float2*>(&eb[(size_t)s * DD + j]);
                a0 += sc[s] * e.x;
                a1 += sc[s] * e.y;
            }
            a0 *= inv; a1 *= inv;
            gfrag_store(b, j, a0, a1);
        }

        grid_barrier();

        // ---- Phase B: gates HMMA, CTA handles 32 cols (nb = b) ----
        {
            const int wm = wid >> 1, wn = wid & 1;
            const uint4* ap = g_gfrag + (size_t)(wm * 64) * 32 + lane;
            const uint4* bq = g_wcfrag + (size_t)((b * 2 + wn) * 64) * 32 + lane;
            float acc[2][4] = {};
#pragma unroll 4
            for (int kt = 0; kt < 64; kt++) {
                uint4 av = ap[kt * 32];
                uint4 bv = bq[kt * 32];
                mma_bf16(acc[0], av.x, av.y, av.z, av.w, bv.x, bv.y);
                mma_bf16(acc[1], av.x, av.y, av.z, av.w, bv.z, bv.w);
            }
#pragma unroll
            for (int nf = 0; nf < 2; nf++) {
                int c = b * 32 + wn * 16 + nf * 8 + tig * 2;
                int r0 = wm * 16 + gid, r1 = r0 + 8;
                const float2 x0 = *reinterpret_cast<const float2*>(
                    &g_xproj[(size_t)(r0 * TT + t) * 2048 + c]);
                const float2 x1 = *reinterpret_cast<const float2*>(
                    &g_xproj[(size_t)(r1 * TT + t) * 2048 + c]);
                *reinterpret_cast<float2*>(&g_gates[r0 * 2048 + c]) =
                    make_float2(acc[nf][0] + x0.x, acc[nf][1] + x0.y);
                *reinterpret_cast<float2*>(&g_gates[r1 * 2048 + c]) =
                    make_float2(acc[nf][2] + x1.x, acc[nf][3] + x1.y);
            }
        }

        grid_barrier();
    }

    // ---- final pointwise (outs[T-1]) ----
    {
        const int gb = b * 2048;
        float2 gi = *reinterpret_cast<const float2*>(&g_gates[gb + j]);
        float2 gf = *reinterpret_cast<const float2*>(&g_gates[gb + 512 + j]);
        float2 gg = *reinterpret_cast<const float2*>(&g_gates[gb + 1024 + j]);
        float2 go = *reinterpret_cast<const float2*>(&g_gates[gb + 1536 + j]);
        float2 cc = *reinterpret_cast<const float2*>(&g_c[b * 512 + j]);
        float si0 = 1.f / (1.f + expf(-gi.x)), si1 = 1.f / (1.f + expf(-gi.y));
        float sf0 = 1.f / (1.f + expf(-gf.x)), sf1 = 1.f / (1.f + expf(-gf.y));
        float so0 = 1.f / (1.f + expf(-go.x)), so1 = 1.f / (1.f + expf(-go.y));
        cc.x = sf0 * cc.x + si0 * tanhf(gg.x);
        cc.y = sf1 * cc.y + si1 * tanhf(gg.y);
        float h0 = so0 * tanhf(cc.x);
        float h1 = so1 * tanhf(cc.y);
        int r = b * TT + TT - 1;
        *reinterpret_cast<float2*>(&g_outs[(size_t)r * 512 + j]) = make_float2(h0, h1);
        afrag_store(r, j, h0, h1);
    }
}

// ---------------- one-time prep ----------------
__global__ void prep_small_kernel(const float* __restrict__ eh, const float* __restrict__ st,
                                  const float* __restrict__ bih, const float* __restrict__ bhh)
{
    int i = blockIdx.x * blockDim.x + threadIdx.x;
    if (i < BB * 640) {
        int b = i / 640, j = i - b * 640;
        g_cat[i] = (j < 512) ? eh[b * 512 + j] : st[b * 512 + 384 + (j - 512)];
    } else if (i < BB * 640 + 2048) {
        int j = i - BB * 640;
        g_biassum[j] = bih[j] + bhh[j];
    } else if (i < BB * 640 + 2048 + BB * 512) {
        g_c[i - (BB * 640 + 2048)] = 0.f;
    } else if (i < BB * 640 + 2048 + 2 * BB * 512) {
        int i2 = i - (BB * 640 + 2048 + BB * 512);
        int b = i2 >> 9, j = i2 & 511;
        g_inp2[b * 1024 + 512 + j] = 0.f;   // h0 accumulator
    } else if (i < BB * 640 + 2048 + 2 * BB * 512 + 4096) {
        // zero afrag pad tiles (rows 1344..1407 = mt 84..87)
        int i2 = i - (BB * 640 + 2048 + 2 * BB * 512);
        g_afrag[84 * KT16 * 32 + i2] = make_uint4(0u, 0u, 0u, 0u);
    }
}

// ---------------- loss ----------------
__global__ void lablogit_kernel(const int* __restrict__ lab, const float* __restrict__ pw,
                                const float* __restrict__ pb)
{
    int gt = blockIdx.x * blockDim.x + threadIdx.x;
    int w = gt >> 5, lane = gt & 31;
    if (w >= BT) return;
    int l = lab[w];
    const float* o  = g_outs + (size_t)w * 512;
    const float* wr = pw + (size_t)l * 512;
    float a = 0.f;
    for (int k = lane; k < 512; k += 32) a += o[k] * wr[k];
#pragma unroll
    for (int off = 16; off; off >>= 1) a += __shfl_xor_sync(0xffffffffu, a, off);
    if (lane == 0) g_lab[w] = a + pb[l];
}

__global__ void loss_row_kernel(const int* __restrict__ lab)
{
    __shared__ float red[128];
    const int r = blockIdx.x, tid = threadIdx.x;
    const float* pm = g_pmax + (size_t)r * NT2;
    const float* ps = g_psum + (size_t)r * NT2;
    float m = -1e30f;
    for (int j = tid; j < NT2; j += 128) m = fmaxf(m, pm[j]);
    red[tid] = m; __syncthreads();
    for (int s = 64; s; s >>= 1) { if (tid < s) red[tid] = fmaxf(red[tid], red[tid + s]); __syncthreads(); }
    float M = red[0]; __syncthreads();
    float se = 0.f;
    for (int j = tid; j < NT2; j += 128) se += ps[j] * expf(pm[j] - M);
    red[tid] = se; __syncthreads();
    for (int s = 64; s; s >>= 1) { if (tid < s) red[tid] += red[tid + s]; __syncthreads(); }
    if (tid == 0) {
        float lse = M + logf(red[0]);
        int l = lab[r];
        g_nll[r] = (l > 0) ? (lse - g_lab[r]) : 0.f;
    }
}

__global__ void loss_final_kernel(const int* __restrict__ lab, float* __restrict__ out)
{
    __shared__ float red[64];
    const int b = threadIdx.x;
    float s = 0.f, cnt = 0.f;
    for (int t = 0; t < TT; t++) {
        int r = b * TT + t;
        s += g_nll[r];
        cnt += (lab[r] > 0) ? 1.f : 0.f;
    }
    red[b] = s / (cnt + 1e-6f);
    __syncthreads();
    if (b == 0) {
        float a = 0.f;
        for (int i = 0; i < 64; i++) a += red[i];
        out[0] = a / 64.f;
    }
}

// ---------------- host launcher ----------------
extern "C" void kernel_launch(void* const* d_in, const int* in_sizes, int n_in,
                              void* d_out, int out_size)
{
    const float* encode_hidden = (const float*)d_in[0];
    const float* encode_output = (const float*)d_in[1];
    const int*   seq_label     = (const int*)  d_in[3];
    const int*   decoder_input = (const int*)  d_in[4];
    const float* style_emb     = (const float*)d_in[5];
    const float* w_e2d         = (const float*)d_in[6];
    const float* b_e2d         = (const float*)d_in[7];
    const float* attn_W        = (const float*)d_in[8];
    const float* emb_table     = (const float*)d_in[9];
    const float* w_ih          = (const float*)d_in[10];
    const float* w_hh          = (const float*)d_in[11];
    const float* b_ih          = (const float*)d_in[12];
    const float* b_hh          = (const float*)d_in[13];
    const float* proj_w        = (const float*)d_in[14];
    const float* proj_b        = (const float*)d_in[15];
    float* out = (float*)d_out;

    float *p_cat, *p_inp2;
    uint4 *p_afrag, *p_eafrag, *p_bfrag, *p_wfrag, *p_encfrag, *p_awfrag;
    cudaGetSymbolAddress((void**)&p_cat,     g_cat);
    cudaGetSymbolAddress((void**)&p_inp2,    g_inp2);
    cudaGetSymbolAddress((void**)&p_afrag,   g_afrag);
    cudaGetSymbolAddress((void**)&p_eafrag,  g_eafrag);
    cudaGetSymbolAddress((void**)&p_bfrag,   g_bfrag);
    cudaGetSymbolAddress((void**)&p_wfrag,   g_wfrag);
    cudaGetSymbolAddress((void**)&p_encfrag, g_encfrag);
    cudaGetSymbolAddress((void**)&p_awfrag,  g_awfrag);

    // one-time prep + fragment conversions
    prep_small_kernel<<<552, 256>>>(encode_hidden, style_emb, b_ih, b_hh);
    conv_eafrag_kernel<<<352, 256>>>(decoder_input, emb_table);
    conv_wfrag_kernel<<<512, 256>>>(w_ih);
    conv_wcfrag_kernel<<<1024, 256>>>(w_ih, w_hh);
    conv_encfrag_kernel<<<1024, 256>>>(encode_output);
    conv_awfrag_kernel<<<128, 256>>>(attn_W);
    conv_bfrag_kernel<<<8000, 256>>>(proj_w);

    // h0 = cat @ W_e2d^T (bias added in loop t=0), split-K atomic fp32
    gemm_atomic_kernel<<<dim3(8, 1, 5), 256>>>(128,
        p_cat, 640, w_e2d, 640, p_inp2 + 512, 1024);

    // xproj = emb @ W_ih_emb^T + biassum  (HMMA)
    xproj_hmma_kernel<<<dim3(16, MT128), 256>>>(p_eafrag, p_wfrag);

    // E2 = enc @ attn_W^T  (HMMA)
    e2_hmma_kernel<<<dim3(4, 32), 256>>>(p_encfrag, p_awfrag);

    // persistent 21-step recurrence (pointwise + attention + gates HMMA)
    loop_kernel<<<64, 256>>>(encode_output, b_e2d);

    // loss
    lablogit_kernel<<<168, 256>>>(seq_label, proj_w, proj_b);
    proj_hmma_kernel<<<dim3(NT2, MT128), 256>>>(p_afrag, p_bfrag, proj_b);
    loss_row_kernel<<<BT, 128>>>(seq_label);
    loss_final_kernel<<<1, 64>>>(seq_label, out);
}

// round 15
// speedup vs baseline: 2.6467x; 1.3012x over previous
#include <cuda_runtime.h>
#include <cuda_bf16.h>
#include <cstdint>
#include <math.h>

// Problem constants
#define BB 64
#define SS 64
#define TT 21
#define DD 512
#define VV 32000
#define BT (BB*TT)        // 1344
#define NT2 250           // proj N tiles of 128
#define MT128 11          // ceil(1344/128)
#define MT16 88           // m-frag tiles (1408/16)
#define KT16 32           // 512/16 k-steps
#define EMT 256           // enc m-frag tiles (4096/16)
#define NJOBS (MT128*NT2) // 2750
#define GRID_FUSED 296

// ---------------- static device scratch ----------------
__device__ float g_cat[BB*640];
__device__ float g_inp2[BB*1024];      // h0 accumulator ([512..1024) per batch)
__device__ float g_gates[BB*2048];
__device__ float g_c[BB*512];
__device__ float g_xproj[BT*2048];
__device__ float g_biassum[2048];
__device__ float g_E2[BB*SS*512];      // enc @ attn_W^T
__device__ float g_outs[BT*512];       // row r = t*64 + b
__device__ uint4 g_afrag[MT16*KT16*32];        // outs A-frags, rows t*64+b
__device__ uint4 g_eafrag[MT16*KT16*32];       // emb  A-frags (rows b*TT+t)
__device__ uint4 g_bfrag[(VV/16)*KT16*32];     // proj_w B-frags
__device__ uint4 g_wfrag[(2048/16)*KT16*32];   // W_ih_emb B-frags
__device__ uint4 g_wcfrag[128*64*32];          // [W_ih_ctx|W_hh] B-frags
__device__ uint4 g_encfrag[EMT*KT16*32];       // enc A-frags
__device__ uint4 g_awfrag[32*KT16*32];         // attn_W B-frags
__device__ uint4 g_gfrag[4*64*32];             // per-step [ctx|h] A-frags
__device__ float g_pmax[BT*NT2];               // row r = t*64+b
__device__ float g_psum[BT*NT2];
__device__ float g_nll[BT];                    // row r = t*64+b
__device__ unsigned g_bar_count = 0;
__device__ volatile unsigned g_bar_gen = 0;
__device__ volatile int g_done_t = 0;
__device__ unsigned g_job = 0;

// ---------------- grid barrier (64 loop CTAs only) ----------------
__device__ __forceinline__ void grid_barrier()
{
    __threadfence();
    __syncthreads();
    if (threadIdx.x == 0) {
        unsigned gen = g_bar_gen;
        if (atomicAdd(&g_bar_count, 1u) == BB - 1) {
            g_bar_count = 0;
            __threadfence();
            g_bar_gen = gen + 1;
        } else {
            while (g_bar_gen == gen) { }
        }
    }
    __syncthreads();
}

// ---------------- packed f32x2 helpers (h0 FFMA GEMM) ----------------
__device__ __forceinline__ double pk2(float lo, float hi) {
    double d;
    asm("mov.b64 %0, {%1, %2};" : "=d"(d) : "f"(lo), "f"(hi));
    return d;
}
__device__ __forceinline__ void upk2(double v, float& lo, float& hi) {
    asm("mov.b64 {%0, %1}, %2;" : "=f"(lo), "=f"(hi) : "d"(v));
}
__device__ __forceinline__ void fma2(double& d, double a, double b) {
    asm("fma.rn.f32x2 %0, %1, %2, %0;" : "+d"(d) : "d"(a), "d"(b));
}

// ---------------- h0 GEMM (split-K atomic fp32) ----------------
__global__ void gemm_atomic_kernel(int klen,
                                   const float* __restrict__ A, int lda,
                                   const float* __restrict__ B, int ldb,
                                   float* __restrict__ C, int ldc)
{
    __shared__ float As[32][68];
    __shared__ float Bs[32][68];
    const int bm = blockIdx.y * 64;
    const int bn = blockIdx.x * 64;
    const int kbeg = blockIdx.z * klen;
    const int tid = threadIdx.x;
    const int tm = (tid >> 4) << 2;
    const int tn = (tid & 15) << 2;
    double acc2[4][2] = {};

    for (int k0 = kbeg; k0 < kbeg + klen; k0 += 32) {
#pragma unroll
        for (int i = 0; i < 8; i++) {
            int e = tid + i * 256;
            int m = e >> 5, k = e & 31;
            As[k][m] = A[(size_t)(bm + m) * lda + k0 + k];
        }
#pragma unroll
        for (int i = 0; i < 8; i++) {
            int e = tid + i * 256;
            int n = e >> 5, k = e & 31;
            Bs[k][n] = B[(size_t)(bn + n) * ldb + k0 + k];
        }
        __syncthreads();
#pragma unroll
        for (int k = 0; k < 32; k++) {
            float4 av = *reinterpret_cast<const float4*>(&As[k][tm]);
            float4 bv = *reinterpret_cast<const float4*>(&Bs[k][tn]);
            double b01 = pk2(bv.x, bv.y), b23 = pk2(bv.z, bv.w);
            double a0 = pk2(av.x, av.x), a1 = pk2(av.y, av.y);
            double a2 = pk2(av.z, av.z), a3 = pk2(av.w, av.w);
            fma2(acc2[0][0], a0, b01); fma2(acc2[0][1], a0, b23);
            fma2(acc2[1][0], a1, b01); fma2(acc2[1][1], a1, b23);
            fma2(acc2[2][0], a2, b01); fma2(acc2[2][1], a2, b23);
            fma2(acc2[3][0], a3, b01); fma2(acc2[3][1], a3, b23);
        }
        __syncthreads();
    }

    float acc[4][4];
#pragma unroll
    for (int i = 0; i < 4; i++) {
        upk2(acc2[i][0], acc[i][0], acc[i][1]);
        upk2(acc2[i][1], acc[i][2], acc[i][3]);
    }
#pragma unroll
    for (int i = 0; i < 4; i++) {
        size_t ro = (size_t)(bm + tm + i);
#pragma unroll
        for (int j = 0; j < 4; j++)
            atomicAdd(&C[ro * ldc + bn + tn + j], acc[i][j]);
    }
}

// ---------------- bf16 helpers ----------------
__device__ __forceinline__ unsigned pkbf(float lo, float hi) {
    __nv_bfloat162 h = __floats2bfloat162_rn(lo, hi);
    return *reinterpret_cast<unsigned*>(&h);
}

__device__ __forceinline__ void mma_bf16(float* d,
    unsigned a0, unsigned a1, unsigned a2, unsigned a3,
    unsigned b0, unsigned b1)
{
    asm volatile(
        "mma.sync.aligned.m16n8k16.row.col.f32.bf16.bf16.f32 "
        "{%0,%1,%2,%3},{%4,%5,%6,%7},{%8,%9},{%0,%1,%2,%3};\n"
        : "+f"(d[0]), "+f"(d[1]), "+f"(d[2]), "+f"(d[3])
        : "r"(a0), "r"(a1), "r"(a2), "r"(a3), "r"(b0), "r"(b1));
}

// ---------------- fragment conversion kernels ----------------
__global__ void conv_eafrag_kernel(const int* __restrict__ di,
                                   const float* __restrict__ et)
{
    int gt = blockIdx.x * 256 + threadIdx.x;
    if (gt >= MT16 * KT16 * 32) return;
    int lane = gt & 31;
    int kt = (gt >> 5) & 31;
    int mt = gt >> 10;
    int gid = lane >> 2, tig = lane & 3;
    int r0 = mt * 16 + gid, r1 = r0 + 8;
    int c0 = kt * 16 + tig * 2;
    uint4 v = make_uint4(0u, 0u, 0u, 0u);
    if (r0 < BT) {
        const float* e0 = et + (size_t)di[r0] * 512;
        v.x = pkbf(e0[c0], e0[c0 + 1]);
        v.z = pkbf(e0[c0 + 8], e0[c0 + 9]);
    }
    if (r1 < BT) {
        const float* e1 = et + (size_t)di[r1] * 512;
        v.y = pkbf(e1[c0], e1[c0 + 1]);
        v.w = pkbf(e1[c0 + 8], e1[c0 + 9]);
    }
    g_eafrag[(mt * KT16 + kt) * 32 + lane] = v;
}

__global__ void conv_bfrag_kernel(const float* __restrict__ W)
{
    int gt = blockIdx.x * 256 + threadIdx.x;
    int lane = gt & 31;
    int kt = (gt >> 5) & 31;
    int nt2 = gt >> 10;
    if (nt2 >= VV / 16) return;
    int gid = lane >> 2, tig = lane & 3;
    int k0 = kt * 16 + tig * 2;
    const float* w0 = W + (size_t)((nt2 * 2) * 8 + gid) * 512;
    const float* w1 = W + (size_t)((nt2 * 2 + 1) * 8 + gid) * 512;
    uint4 v;
    v.x = pkbf(w0[k0],     w0[k0 + 1]);
    v.y = pkbf(w0[k0 + 8], w0[k0 + 9]);
    v.z = pkbf(w1[k0],     w1[k0 + 1]);
    v.w = pkbf(w1[k0 + 8], w1[k0 + 9]);
    g_bfrag[(nt2 * KT16 + kt) * 32 + lane] = v;
}

__global__ void conv_wfrag_kernel(const float* __restrict__ wih)
{
    int gt = blockIdx.x * 256 + threadIdx.x;
    int lane = gt & 31;
    int kt = (gt >> 5) & 31;
    int nt2 = gt >> 10;
    if (nt2 >= 2048 / 16) return;
    int gid = lane >> 2, tig = lane & 3;
    int k0 = kt * 16 + tig * 2;
    const float* w0 = wih + (size_t)((nt2 * 2) * 8 + gid) * 1024 + 512;
    const float* w1 = wih + (size_t)((nt2 * 2 + 1) * 8 + gid) * 1024 + 512;
    uint4 v;
    v.x = pkbf(w0[k0],     w0[k0 + 1]);
    v.y = pkbf(w0[k0 + 8], w0[k0 + 9]);
    v.z = pkbf(w1[k0],     w1[k0 + 1]);
    v.w = pkbf(w1[k0 + 8], w1[k0 + 9]);
    g_wfrag[(nt2 * KT16 + kt) * 32 + lane] = v;
}

__global__ void conv_wcfrag_kernel(const float* __restrict__ wih,
                                   const float* __restrict__ whh)
{
    int gt = blockIdx.x * 256 + threadIdx.x;
    int lane = gt & 31;
    int kt = (gt >> 5) & 63;
    int nt2 = gt >> 11;
    if (nt2 >= 128) return;
    int gid = lane >> 2, tig = lane & 3;
    int n0 = (nt2 * 2) * 8 + gid;
    int n1 = (nt2 * 2 + 1) * 8 + gid;
    int k0 = kt * 16 + tig * 2;
    const float *p0, *p1;
    if (k0 < 512) {
        p0 = wih + (size_t)n0 * 1024 + k0;
        p1 = wih + (size_t)n1 * 1024 + k0;
    } else {
        p0 = whh + (size_t)n0 * 512 + (k0 - 512);
        p1 = whh + (size_t)n1 * 512 + (k0 - 512);
    }
    uint4 v;
    v.x = pkbf(p0[0], p0[1]);
    v.y = pkbf(p0[8], p0[9]);
    v.z = pkbf(p1[0], p1[1]);
    v.w = pkbf(p1[8], p1[9]);
    g_wcfrag[(nt2 * 64 + kt) * 32 + lane] = v;
}

__global__ void conv_encfrag_kernel(const float* __restrict__ enc)
{
    int gt = blockIdx.x * 256 + threadIdx.x;
    if (gt >= EMT * KT16 * 32) return;
    int lane = gt & 31;
    int kt = (gt >> 5) & 31;
    int mt = gt >> 10;
    int gid = lane >> 2, tig = lane & 3;
    int r0 = mt * 16 + gid, r1 = r0 + 8;
    int c0 = kt * 16 + tig * 2;
    uint4 v;
    v.x = pkbf(enc[(size_t)r0*512 + c0],     enc[(size_t)r0*512 + c0 + 1]);
    v.y = pkbf(enc[(size_t)r1*512 + c0],     enc[(size_t)r1*512 + c0 + 1]);
    v.z = pkbf(enc[(size_t)r0*512 + c0 + 8], enc[(size_t)r0*512 + c0 + 9]);
    v.w = pkbf(enc[(size_t)r1*512 + c0 + 8], enc[(size_t)r1*512 + c0 + 9]);
    g_encfrag[(mt * KT16 + kt) * 32 + lane] = v;
}

__global__ void conv_awfrag_kernel(const float* __restrict__ W)
{
    int gt = blockIdx.x * 256 + threadIdx.x;
    int lane = gt & 31;
    int kt = (gt >> 5) & 31;
    int nt2 = gt >> 10;
    if (nt2 >= 32) return;
    int gid = lane >> 2, tig = lane & 3;
    int k0 = kt * 16 + tig * 2;
    const float* w0 = W + (size_t)((nt2 * 2) * 8 + gid) * 512;
    const float* w1 = W + (size_t)((nt2 * 2 + 1) * 8 + gid) * 512;
    uint4 v;
    v.x = pkbf(w0[k0],     w0[k0 + 1]);
    v.y = pkbf(w0[k0 + 8], w0[k0 + 9]);
    v.z = pkbf(w1[k0],     w1[k0 + 1]);
    v.w = pkbf(w1[k0 + 8], w1[k0 + 9]);
    g_awfrag[(nt2 * KT16 + kt) * 32 + lane] = v;
}

// ---------------- HMMA frag GEMM core (8 warps, warp 32x64) ----------------
#define FRAG_LOOP16(Af, Bf, mt0, nt2b)                                         \
    const uint4* a0p = (Af) + (size_t)((mt0) * KT16) * 32 + lane;              \
    const uint4* a1p = (Af) + (size_t)(((mt0) + 1) * KT16) * 32 + lane;        \
    const uint4* bp0 = (Bf) + (size_t)(((nt2b) + 0) * KT16) * 32 + lane;       \
    const uint4* bp1 = (Bf) + (size_t)(((nt2b) + 1) * KT16) * 32 + lane;       \
    const uint4* bp2 = (Bf) + (size_t)(((nt2b) + 2) * KT16) * 32 + lane;       \
    const uint4* bp3 = (Bf) + (size_t)(((nt2b) + 3) * KT16) * 32 + lane;       \
    float acc[2][8][4] = {};                                                   \
    _Pragma("unroll 4")                                                        \
    for (int kt = 0; kt < KT16; kt++) {                                        \
        uint4 av0 = a0p[kt * 32];                                              \
        uint4 av1 = a1p[kt * 32];                                              \
        uint4 bv0 = bp0[kt * 32];                                              \
        uint4 bv1 = bp1[kt * 32];                                              \
        uint4 bv2 = bp2[kt * 32];                                              \
        uint4 bv3 = bp3[kt * 32];                                              \
        mma_bf16(acc[0][0], av0.x, av0.y, av0.z, av0.w, bv0.x, bv0.y);         \
        mma_bf16(acc[0][1], av0.x, av0.y, av0.z, av0.w, bv0.z, bv0.w);         \
        mma_bf16(acc[0][2], av0.x, av0.y, av0.z, av0.w, bv1.x, bv1.y);         \
        mma_bf16(acc[0][3], av0.x, av0.y, av0.z, av0.w, bv1.z, bv1.w);         \
        mma_bf16(acc[0][4], av0.x, av0.y, av0.z, av0.w, bv2.x, bv2.y);         \
        mma_bf16(acc[0][5], av0.x, av0.y, av0.z, av0.w, bv2.z, bv2.w);         \
        mma_bf16(acc[0][6], av0.x, av0.y, av0.z, av0.w, bv3.x, bv3.y);         \
        mma_bf16(acc[0][7], av0.x, av0.y, av0.z, av0.w, bv3.z, bv3.w);         \
        mma_bf16(acc[1][0], av1.x, av1.y, av1.z, av1.w, bv0.x, bv0.y);         \
        mma_bf16(acc[1][1], av1.x, av1.y, av1.z, av1.w, bv0.z, bv0.w);         \
        mma_bf16(acc[1][2], av1.x, av1.y, av1.z, av1.w, bv1.x, bv1.y);         \
        mma_bf16(acc[1][3], av1.x, av1.y, av1.z, av1.w, bv1.z, bv1.w);         \
        mma_bf16(acc[1][4], av1.x, av1.y, av1.z, av1.w, bv2.x, bv2.y);         \
        mma_bf16(acc[1][5], av1.x, av1.y, av1.z, av1.w, bv2.z, bv2.w);         \
        mma_bf16(acc[1][6], av1.x, av1.y, av1.z, av1.w, bv3.x, bv3.y);         \
        mma_bf16(acc[1][7], av1.x, av1.y, av1.z, av1.w, bv3.z, bv3.w);         \
    }

#define MMA_BLOCK16()                                                          \
        mma_bf16(acc[0][0], av0.x, av0.y, av0.z, av0.w, bv0.x, bv0.y);         \
        mma_bf16(acc[0][1], av0.x, av0.y, av0.z, av0.w, bv0.z, bv0.w);         \
        mma_bf16(acc[0][2], av0.x, av0.y, av0.z, av0.w, bv1.x, bv1.y);         \
        mma_bf16(acc[0][3], av0.x, av0.y, av0.z, av0.w, bv1.z, bv1.w);         \
        mma_bf16(acc[0][4], av0.x, av0.y, av0.z, av0.w, bv2.x, bv2.y);         \
        mma_bf16(acc[0][5], av0.x, av0.y, av0.z, av0.w, bv2.z, bv2.w);         \
        mma_bf16(acc[0][6], av0.x, av0.y, av0.z, av0.w, bv3.x, bv3.y);         \
        mma_bf16(acc[0][7], av0.x, av0.y, av0.z, av0.w, bv3.z, bv3.w);         \
        mma_bf16(acc[1][0], av1.x, av1.y, av1.z, av1.w, bv0.x, bv0.y);         \
        mma_bf16(acc[1][1], av1.x, av1.y, av1.z, av1.w, bv0.z, bv0.w);         \
        mma_bf16(acc[1][2], av1.x, av1.y, av1.z, av1.w, bv1.x, bv1.y);         \
        mma_bf16(acc[1][3], av1.x, av1.y, av1.z, av1.w, bv1.z, bv1.w);         \
        mma_bf16(acc[1][4], av1.x, av1.y, av1.z, av1.w, bv2.x, bv2.y);         \
        mma_bf16(acc[1][5], av1.x, av1.y, av1.z, av1.w, bv2.z, bv2.w);         \
        mma_bf16(acc[1][6], av1.x, av1.y, av1.z, av1.w, bv3.x, bv3.y);         \
        mma_bf16(acc[1][7], av1.x, av1.y, av1.z, av1.w, bv3.z, bv3.w);

// xproj: C = embA @ WihB^T + biassum
__global__ void __launch_bounds__(256)
xproj_hmma_kernel(const uint4* __restrict__ Af, const uint4* __restrict__ Bf)
{
    __shared__ float sb[128];
    const int tid = threadIdx.x, lane = tid & 31, wid = tid >> 5;
    const int wm = wid >> 1, wn = wid & 1;
    const int gid = lane >> 2, tig = lane & 3;
    const int nb = blockIdx.x, mb = blockIdx.y;

    if (tid < 128) sb[tid] = g_biassum[nb * 128 + tid];

    FRAG_LOOP16(Af, Bf, mb * 8 + wm * 2, nb * 8 + wn * 4)
    __syncthreads();

#pragma unroll
    for (int f = 0; f < 2; f++) {
#pragma unroll
        for (int half = 0; half < 2; half++) {
            int r = mb * 128 + wm * 32 + f * 16 + half * 8 + gid;
            if (r >= BT) continue;
#pragma unroll
            for (int nf = 0; nf < 8; nf++) {
                int nl = wn * 64 + nf * 8 + tig * 2;
                float v0 = acc[f][nf][half * 2]     + sb[nl];
                float v1 = acc[f][nf][half * 2 + 1] + sb[nl + 1];
                *reinterpret_cast<float2*>(
                    &g_xproj[(size_t)r * 2048 + nb * 128 + nl]) = make_float2(v0, v1);
            }
        }
    }
}

// E2 = enc @ attn_W^T
__global__ void __launch_bounds__(256)
e2_hmma_kernel(const uint4* __restrict__ Af, const uint4* __restrict__ Bf)
{
    const int tid = threadIdx.x, lane = tid & 31, wid = tid >> 5;
    const int wm = wid >> 1, wn = wid & 1;
    const int gid = lane >> 2, tig = lane & 3;
    const int nb = blockIdx.x, mb = blockIdx.y;

    FRAG_LOOP16(Af, Bf, mb * 8 + wm * 2, nb * 8 + wn * 4)

#pragma unroll
    for (int f = 0; f < 2; f++) {
#pragma unroll
        for (int half = 0; half < 2; half++) {
            int r = mb * 128 + wm * 32 + f * 16 + half * 8 + gid;
#pragma unroll
            for (int nf = 0; nf < 8; nf++) {
                int nl = wn * 64 + nf * 8 + tig * 2;
                *reinterpret_cast<float2*>(
                    &g_E2[(size_t)r * 512 + nb * 128 + nl]) =
                    make_float2(acc[f][nf][half * 2], acc[f][nf][half * 2 + 1]);
            }
        }
    }
}

// ---------------- frag scatter helpers ----------------
__device__ __forceinline__ void gfrag_store(int r, int c, float v0, float v1)
{
    int mt = r >> 4, rr = r & 15, gid = rr & 7;
    int kt = c >> 4, cc = c & 15;
    int tig = (cc & 7) >> 1;
    int comp = ((cc >> 3) << 1) | (rr >> 3);
    unsigned* base = reinterpret_cast<unsigned*>(
        &g_gfrag[(size_t)(mt * 64 + kt) * 32 + gid * 4 + tig]);
    base[comp] = pkbf(v0, v1);
}

__device__ __forceinline__ void afrag_store(int r, int c, float v0, float v1)
{
    int mt = r >> 4, rr = r & 15, gid = rr & 7;
    int kt = c >> 4, cc = c & 15;
    int tig = (cc & 7) >> 1;
    int comp = ((cc >> 3) << 1) | (rr >> 3);
    unsigned* base = reinterpret_cast<unsigned*>(
        &g_afrag[(size_t)(mt * KT16 + kt) * 32 + gid * 4 + tig]);
    base[comp] = pkbf(v0, v1);
}

// ---------------- fused persistent kernel: recurrence (CTA<64) + proj workers ----------------
__global__ void __launch_bounds__(256, 2)
fused_kernel(const float* __restrict__ enc, const float* __restrict__ be2d,
             const uint4* __restrict__ Af, const uint4* __restrict__ Bf,
             const float* __restrict__ pb)
{
    __shared__ float hs[512];
    __shared__ float sc[64];
    __shared__ float s_inv;
    __shared__ float sb[128];
    __shared__ float smax[2][128], ssum[2][128];
    __shared__ unsigned s_job;
    const int tid = threadIdx.x;
    const int wid = tid >> 5, lane = tid & 31;
    const int gid = lane >> 2, tig = lane & 3;

    if (blockIdx.x < BB) {
        // ================= recurrence path =================
        const int b = blockIdx.x;
        const int j = 2 * tid;

        for (int t = 0; t < TT; t++) {
            // ---- Phase A: pointwise(t-1) + attention(t) ----
            if (t > 0) {
                const int gb = b * 2048;
                float2 gi = *reinterpret_cast<const float2*>(&g_gates[gb + j]);
                float2 gf = *reinterpret_cast<const float2*>(&g_gates[gb + 512 + j]);
                float2 gg = *reinterpret_cast<const float2*>(&g_gates[gb + 1024 + j]);
                float2 go = *reinterpret_cast<const float2*>(&g_gates[gb + 1536 + j]);
                float2 cc = *reinterpret_cast<const float2*>(&g_c[b * 512 + j]);
                float si0 = 1.f / (1.f + expf(-gi.x)), si1 = 1.f / (1.f + expf(-gi.y));
                float sf0 = 1.f / (1.f + expf(-gf.x)), sf1 = 1.f / (1.f + expf(-gf.y));
                float so0 = 1.f / (1.f + expf(-go.x)), so1 = 1.f / (1.f + expf(-go.y));
                cc.x = sf0 * cc.x + si0 * tanhf(gg.x);
                cc.y = sf1 * cc.y + si1 * tanhf(gg.y);
                *reinterpret_cast<float2*>(&g_c[b * 512 + j]) = cc;
                float h0 = so0 * tanhf(cc.x);
                float h1 = so1 * tanhf(cc.y);
                int r = (t - 1) * BB + b;
                *reinterpret_cast<float2*>(&g_outs[(size_t)r * 512 + j]) = make_float2(h0, h1);
                afrag_store(r, j, h0, h1);
                hs[j] = h0; hs[j + 1] = h1;
                gfrag_store(b, 512 + j, h0, h1);
            } else {
                float2 hv = *reinterpret_cast<const float2*>(&g_inp2[b * 1024 + 512 + j]);
                hv.x += be2d[j]; hv.y += be2d[j + 1];
                hs[j] = hv.x; hs[j + 1] = hv.y;
                gfrag_store(b, 512 + j, hv.x, hv.y);
            }
            __syncthreads();

            const float* E2b = g_E2 + (size_t)b * SS * 512;
            for (int s = wid; s < SS; s += 8) {
                const float* er = E2b + (size_t)s * 512;
                float a = 0.f;
                for (int k = lane; k < 512; k += 32) a += hs[k] * er[k];
#pragma unroll
                for (int o = 16; o; o >>= 1) a += __shfl_xor_sync(0xffffffffu, a, o);
                if (lane == 0) sc[s] = a;
            }
            __syncthreads();

            if (wid == 0) {
                float v0 = sc[lane], v1 = sc[lane + 32];
                float m = fmaxf(v0, v1);
#pragma unroll
                for (int o = 16; o; o >>= 1) m = fmaxf(m, __shfl_xor_sync(0xffffffffu, m, o));
                float e0 = expf(v0 - m), e1 = expf(v1 - m);
                float ssm = e0 + e1;
#pragma unroll
                for (int o = 16; o; o >>= 1) ssm += __shfl_xor_sync(0xffffffffu, ssm, o);
                sc[lane] = e0; sc[lane + 32] = e1;
                if (lane == 0) s_inv = 1.f / ssm;
            }
            __syncthreads();

            {
                float inv = s_inv;
                const float* eb = enc + (size_t)b * SS * DD;
                float a0 = 0.f, a1 = 0.f;
#pragma unroll 8
                for (int s = 0; s < SS; s++) {
                    float2 e = *reinterpret_cast<const float2*>(&eb[(size_t)s * DD + j]);
                    a0 += sc[s] * e.x;
                    a1 += sc[s] * e.y;
                }
                a0 *= inv; a1 *= inv;
                gfrag_store(b, j, a0, a1);
            }

            grid_barrier();
            if (b == 0 && tid == 0 && t > 0) g_done_t = t;   // outs rows [0, t) ready

            // ---- Phase B: gates HMMA, CTA handles 32 cols ----
            {
                const int wm = wid >> 1, wn = wid & 1;
                const uint4* ap = g_gfrag + (size_t)(wm * 64) * 32 + lane;
                const uint4* bq = g_wcfrag + (size_t)((b * 2 + wn) * 64) * 32 + lane;
                float acc[2][4] = {};
#pragma unroll 4
                for (int kt = 0; kt < 64; kt++) {
                    uint4 av = ap[kt * 32];
                    uint4 bv = bq[kt * 32];
                    mma_bf16(acc[0], av.x, av.y, av.z, av.w, bv.x, bv.y);
                    mma_bf16(acc[1], av.x, av.y, av.z, av.w, bv.z, bv.w);
                }
#pragma unroll
                for (int nf = 0; nf < 2; nf++) {
                    int c = b * 32 + wn * 16 + nf * 8 + tig * 2;
                    int r0 = wm * 16 + gid, r1 = r0 + 8;
                    const float2 x0 = *reinterpret_cast<const float2*>(
                        &g_xproj[(size_t)(r0 * TT + t) * 2048 + c]);
                    const float2 x1 = *reinterpret_cast<const float2*>(
                        &g_xproj[(size_t)(r1 * TT + t) * 2048 + c]);
                    *reinterpret_cast<float2*>(&g_gates[r0 * 2048 + c]) =
                        make_float2(acc[nf][0] + x0.x, acc[nf][1] + x0.y);
                    *reinterpret_cast<float2*>(&g_gates[r1 * 2048 + c]) =
                        make_float2(acc[nf][2] + x1.x, acc[nf][3] + x1.y);
                }
            }

            grid_barrier();
        }

        // ---- final pointwise (outs row 20*64+b) ----
        {
            const int gb = b * 2048;
            float2 gi = *reinterpret_cast<const float2*>(&g_gates[gb + j]);
            float2 gf = *reinterpret_cast<const float2*>(&g_gates[gb + 512 + j]);
            float2 gg = *reinterpret_cast<const float2*>(&g_gates[gb + 1024 + j]);
            float2 go = *reinterpret_cast<const float2*>(&g_gates[gb + 1536 + j]);
            float2 cc = *reinterpret_cast<const float2*>(&g_c[b * 512 + j]);
            float si0 = 1.f / (1.f + expf(-gi.x)), si1 = 1.f / (1.f + expf(-gi.y));
            float sf0 = 1.f / (1.f + expf(-gf.x)), sf1 = 1.f / (1.f + expf(-gf.y));
            float so0 = 1.f / (1.f + expf(-go.x)), so1 = 1.f / (1.f + expf(-go.y));
            cc.x = sf0 * cc.x + si0 * tanhf(gg.x);
            cc.y = sf1 * cc.y + si1 * tanhf(gg.y);
            float h0 = so0 * tanhf(cc.x);
            float h1 = so1 * tanhf(cc.y);
            int r = (TT - 1) * BB + b;
            *reinterpret_cast<float2*>(&g_outs[(size_t)r * 512 + j]) = make_float2(h0, h1);
            afrag_store(r, j, h0, h1);
        }

        grid_barrier();
        if (b == 0 && tid == 0) g_done_t = TT;
        // loop CTAs fall through and join the proj worker pool
    }

    // ================= proj worker path =================
    for (;;) {
        if (tid == 0) s_job = atomicAdd(&g_job, 1u);
        __syncthreads();
        unsigned job = s_job;
        if (job >= NJOBS) break;
        const int mb = job / NT2, nb = job % NT2;
        const int need = (2 * mb + 2 < TT + 1) ? 2 * mb + 2 : TT;

        if (tid == 0) {
            while (g_done_t < need) { __nanosleep(256); }
        }
        __syncthreads();

        if (tid < 128) sb[tid] = pb[nb * 128 + tid];

        const int wm = wid >> 1, wn = wid & 1;
        const int mt0 = mb * 8 + wm * 2;
        const int nt2b = nb * 8 + wn * 4;
        const uint4* a0p = Af + (size_t)(mt0 * KT16) * 32 + lane;
        const uint4* a1p = Af + (size_t)((mt0 + 1) * KT16) * 32 + lane;
        const uint4* bp0 = Bf + (size_t)((nt2b + 0) * KT16) * 32 + lane;
        const uint4* bp1 = Bf + (size_t)((nt2b + 1) * KT16) * 32 + lane;
        const uint4* bp2 = Bf + (size_t)((nt2b + 2) * KT16) * 32 + lane;
        const uint4* bp3 = Bf + (size_t)((nt2b + 3) * KT16) * 32 + lane;

        float acc[2][8][4] = {};
        uint4 av0 = a0p[0], av1 = a1p[0];
        uint4 bv0 = bp0[0], bv1 = bp1[0], bv2 = bp2[0], bv3 = bp3[0];

#pragma unroll 1
        for (int kt = 0; kt < KT16; kt++) {
            const int kn = (kt < KT16 - 1 ? kt + 1 : kt) * 32;
            uint4 nav0 = a0p[kn], nav1 = a1p[kn];
            uint4 nbv0 = bp0[kn], nbv1 = bp1[kn], nbv2 = bp2[kn], nbv3 = bp3[kn];
            MMA_BLOCK16()
            av0 = nav0; av1 = nav1;
            bv0 = nbv0; bv1 = nbv1; bv2 = nbv2; bv3 = nbv3;
        }
        __syncthreads();   // sb ready

#pragma unroll
        for (int f = 0; f < 2; f++) {
#pragma unroll
            for (int half = 0; half < 2; half++) {
                float v[16];
#pragma unroll
                for (int nf = 0; nf < 8; nf++) {
                    float b0 = sb[wn * 64 + nf * 8 + tig * 2];
                    float b1 = sb[wn * 64 + nf * 8 + tig * 2 + 1];
                    v[nf * 2]     = acc[f][nf][half * 2]     + b0;
                    v[nf * 2 + 1] = acc[f][nf][half * 2 + 1] + b1;
                }
                float mx = v[0];
#pragma unroll
                for (int i = 1; i < 16; i++) mx = fmaxf(mx, v[i]);
                mx = fmaxf(mx, __shfl_xor_sync(0xffffffffu, mx, 1));
                mx = fmaxf(mx, __shfl_xor_sync(0xffffffffu, mx, 2));
                float se = 0.f;
#pragma unroll
                for (int i = 0; i < 16; i++) se += expf(v[i] - mx);
                se += __shfl_xor_sync(0xffffffffu, se, 1);
                se += __shfl_xor_sync(0xffffffffu, se, 2);
                if (tig == 0) {
                    int rowl = wm * 32 + f * 16 + half * 8 + gid;
                    smax[wn][rowl] = mx;
                    ssum[wn][rowl] = se;
                }
            }
        }
        __syncthreads();

        if (tid < 128) {
            int row = mb * 128 + tid;
            if (row < BT) {
                float m0 = smax[0][tid], m1 = smax[1][tid];
                float M = fmaxf(m0, m1);
                float S = ssum[0][tid] * expf(m0 - M) + ssum[1][tid] * expf(m1 - M);
                g_pmax[(size_t)row * NT2 + nb] = M;
                g_psum[(size_t)row * NT2 + nb] = S;
            }
        }
        __syncthreads();
    }
}

// ---------------- one-time prep ----------------
__global__ void prep_small_kernel(const float* __restrict__ eh, const float* __restrict__ st,
                                  const float* __restrict__ bih, const float* __restrict__ bhh)
{
    int i = blockIdx.x * blockDim.x + threadIdx.x;
    if (i < BB * 640) {
        int b = i / 640, j = i - b * 640;
        g_cat[i] = (j < 512) ? eh[b * 512 + j] : st[b * 512 + 384 + (j - 512)];
    } else if (i < BB * 640 + 2048) {
        int j = i - BB * 640;
        g_biassum[j] = bih[j] + bhh[j];
    } else if (i < BB * 640 + 2048 + BB * 512) {
        g_c[i - (BB * 640 + 2048)] = 0.f;
    } else if (i < BB * 640 + 2048 + 2 * BB * 512) {
        int i2 = i - (BB * 640 + 2048 + BB * 512);
        int b = i2 >> 9, j = i2 & 511;
        g_inp2[b * 1024 + 512 + j] = 0.f;   // h0 accumulator
    } else if (i < BB * 640 + 2048 + 2 * BB * 512 + 4096) {
        int i2 = i - (BB * 640 + 2048 + 2 * BB * 512);
        g_afrag[84 * KT16 * 32 + i2] = make_uint4(0u, 0u, 0u, 0u);
    } else if (i == BB * 640 + 2048 + 2 * BB * 512 + 4096) {
        g_done_t = 0;
        g_job = 0;
    }
}

// ---------------- loss ----------------
// row r = t*64+b: fused label-logit + logsumexp reduction -> nll[r]
__global__ void loss_row_kernel(const int* __restrict__ lab,
                                const float* __restrict__ pw,
                                const float* __restrict__ pb)
{
    __shared__ float red[128];
    const int r = blockIdx.x, tid = threadIdx.x;
    const int b = r & 63, t = r >> 6;
    const int l = lab[b * TT + t];

    // label logit
    const float* o  = g_outs + (size_t)r * 512;
    const float* wr = pw + (size_t)l * 512;
    float a = 0.f;
    for (int k = tid; k < 512; k += 128) a += o[k] * wr[k];
    red[tid] = a; __syncthreads();
    for (int s = 64; s; s >>= 1) { if (tid < s) red[tid] += red[tid + s]; __syncthreads(); }
    float labl = red[0] + pb[l];
    __syncthreads();

    const float* pm = g_pmax + (size_t)r * NT2;
    const float* ps = g_psum + (size_t)r * NT2;
    float m = -1e30f;
    for (int j = tid; j < NT2; j += 128) m = fmaxf(m, pm[j]);
    red[tid] = m; __syncthreads();
    for (int s = 64; s; s >>= 1) { if (tid < s) red[tid] = fmaxf(red[tid], red[tid + s]); __syncthreads(); }
    float M = red[0]; __syncthreads();
    float se = 0.f;
    for (int j = tid; j < NT2; j += 128) se += ps[j] * expf(pm[j] - M);
    red[tid] = se; __syncthreads();
    for (int s = 64; s; s >>= 1) { if (tid < s) red[tid] += red[tid + s]; __syncthreads(); }
    if (tid == 0) {
        float lse = M + logf(red[0]);
        g_nll[r] = (l > 0) ? (lse - labl) : 0.f;
    }
}

__global__ void loss_final_kernel(const int* __restrict__ lab, float* __restrict__ out)
{
    __shared__ float red[64];
    const int b = threadIdx.x;
    float s = 0.f, cnt = 0.f;
    for (int t = 0; t < TT; t++) {
        s += g_nll[t * BB + b];
        cnt += (lab[b * TT + t] > 0) ? 1.f : 0.f;
    }
    red[b] = s / (cnt + 1e-6f);
    __syncthreads();
    if (b == 0) {
        float a = 0.f;
        for (int i = 0; i < 64; i++) a += red[i];
        out[0] = a / 64.f;
    }
}

// ---------------- host launcher ----------------
extern "C" void kernel_launch(void* const* d_in, const int* in_sizes, int n_in,
                              void* d_out, int out_size)
{
    const float* encode_hidden = (const float*)d_in[0];
    const float* encode_output = (const float*)d_in[1];
    const int*   seq_label     = (const int*)  d_in[3];
    const int*   decoder_input = (const int*)  d_in[4];
    const float* style_emb     = (const float*)d_in[5];
    const float* w_e2d         = (const float*)d_in[6];
    const float* b_e2d         = (const float*)d_in[7];
    const float* attn_W        = (const float*)d_in[8];
    const float* emb_table     = (const float*)d_in[9];
    const float* w_ih          = (const float*)d_in[10];
    const float* w_hh          = (const float*)d_in[11];
    const float* b_ih          = (const float*)d_in[12];
    const float* b_hh          = (const float*)d_in[13];
    const float* proj_w        = (const float*)d_in[14];
    const float* proj_b        = (const float*)d_in[15];
    float* out = (float*)d_out;

    float *p_cat, *p_inp2;
    uint4 *p_afrag, *p_eafrag, *p_bfrag, *p_wfrag, *p_encfrag, *p_awfrag;
    cudaGetSymbolAddress((void**)&p_cat,     g_cat);
    cudaGetSymbolAddress((void**)&p_inp2,    g_inp2);
    cudaGetSymbolAddress((void**)&p_afrag,   g_afrag);
    cudaGetSymbolAddress((void**)&p_eafrag,  g_eafrag);
    cudaGetSymbolAddress((void**)&p_bfrag,   g_bfrag);
    cudaGetSymbolAddress((void**)&p_wfrag,   g_wfrag);
    cudaGetSymbolAddress((void**)&p_encfrag, g_encfrag);
    cudaGetSymbolAddress((void**)&p_awfrag,  g_awfrag);

    // one-time prep + fragment conversions
    prep_small_kernel<<<552, 256>>>(encode_hidden, style_emb, b_ih, b_hh);
    conv_eafrag_kernel<<<352, 256>>>(decoder_input, emb_table);
    conv_wfrag_kernel<<<512, 256>>>(w_ih);
    conv_wcfrag_kernel<<<1024, 256>>>(w_ih, w_hh);
    conv_encfrag_kernel<<<1024, 256>>>(encode_output);
    conv_awfrag_kernel<<<128, 256>>>(attn_W);
    conv_bfrag_kernel<<<8000, 256>>>(proj_w);

    // h0 = cat @ W_e2d^T (bias added in fused t=0), split-K atomic fp32
    gemm_atomic_kernel<<<dim3(8, 1, 5), 256>>>(128,
        p_cat, 640, w_e2d, 640, p_inp2 + 512, 1024);

    // xproj = emb @ W_ih_emb^T + biassum  (HMMA)
    xproj_hmma_kernel<<<dim3(16, MT128), 256>>>(p_eafrag, p_wfrag);

    // E2 = enc @ attn_W^T  (HMMA)
    e2_hmma_kernel<<<dim3(4, 32), 256>>>(p_encfrag, p_awfrag);

    // fused persistent kernel: recurrence + overlapped projection+logsumexp
    fused_kernel<<<GRID_FUSED, 256>>>(encode_output, b_e2d, p_afrag, p_bfrag, proj_b);

    // loss
    loss_row_kernel<<<BT, 128>>>(seq_label, proj_w, proj_b);
    loss_final_kernel<<<1, 64>>>(seq_label, out);
}

// round 17
// speedup vs baseline: 2.7999x; 1.0579x over previous
#include <cuda_runtime.h>
#include <cuda_bf16.h>
#include <cstdint>
#include <math.h>

// Problem constants
#define BB 64
#define SS 64
#define TT 21
#define DD 512
#define VV 32000
#define BT (BB*TT)        // 1344
#define NT2 250           // proj N tiles of 128
#define MT128 11          // ceil(1344/128)
#define MT16 88           // m-frag tiles (1408/16)
#define KT16 32           // 512/16 k-steps
#define EMT 256           // enc m-frag tiles (4096/16)
#define NJOBS (MT128*NT2) // 2750
#define GRID_FUSED 296
#define NWORK (GRID_FUSED-BB)   // 232

// ---------------- static device scratch ----------------
__device__ float g_cat[BB*640];
__device__ float g_inp2[BB*1024];      // h0 accumulator ([512..1024) per batch)
__device__ float g_gates[BB*2048];
__device__ float g_c[BB*512];
__device__ float g_xproj[BT*2048];
__device__ float g_biassum[2048];
__device__ float g_E2[BB*SS*512];      // enc @ attn_W^T
__device__ float g_outs[BT*512];       // row r = t*64 + b
__device__ uint4 g_afrag[MT16*KT16*32];        // outs A-frags, rows t*64+b
__device__ uint4 g_eafrag[MT16*KT16*32];       // emb  A-frags (rows b*TT+t)
__device__ uint4 g_bfrag[(VV/16)*KT16*32];     // proj_w B-frags (built in fused)
__device__ uint4 g_wfrag[(2048/16)*KT16*32];   // W_ih_emb B-frags
__device__ uint4 g_wcfrag[128*64*32];          // [W_ih_ctx|W_hh] B-frags
__device__ uint4 g_encfrag[EMT*KT16*32];       // enc A-frags
__device__ uint4 g_awfrag[32*KT16*32];         // attn_W B-frags
__device__ uint4 g_gfrag[4*64*32];             // per-step [ctx|h] A-frags
__device__ float g_pmax[BT*NT2];               // row r = t*64+b
__device__ float g_psum[BT*NT2];
__device__ float g_nll[BT];                    // row r = t*64+b
__device__ unsigned g_bar_count = 0;
__device__ volatile unsigned g_bar_gen = 0;
__device__ volatile int g_done_t = 0;
__device__ unsigned g_job = 0;
__device__ volatile int g_conv_done = 0;

// ---------------- grid barrier (64 loop CTAs only) ----------------
__device__ __forceinline__ void grid_barrier()
{
    __threadfence();
    __syncthreads();
    if (threadIdx.x == 0) {
        unsigned gen = g_bar_gen;
        if (atomicAdd(&g_bar_count, 1u) == BB - 1) {
            g_bar_count = 0;
            __threadfence();
            g_bar_gen = gen + 1;
        } else {
            while (g_bar_gen == gen) { }
        }
    }
    __syncthreads();
}

// ---------------- packed f32x2 helpers (h0 FFMA GEMM) ----------------
__device__ __forceinline__ double pk2(float lo, float hi) {
    double d;
    asm("mov.b64 %0, {%1, %2};" : "=d"(d) : "f"(lo), "f"(hi));
    return d;
}
__device__ __forceinline__ void upk2(double v, float& lo, float& hi) {
    asm("mov.b64 {%0, %1}, %2;" : "=f"(lo), "=f"(hi) : "d"(v));
}
__device__ __forceinline__ void fma2(double& d, double a, double b) {
    asm("fma.rn.f32x2 %0, %1, %2, %0;" : "+d"(d) : "d"(a), "d"(b));
}

// ---------------- h0 GEMM (split-K atomic fp32) ----------------
__global__ void gemm_atomic_kernel(int klen,
                                   const float* __restrict__ A, int lda,
                                   const float* __restrict__ B, int ldb,
                                   float* __restrict__ C, int ldc)
{
    __shared__ float As[32][68];
    __shared__ float Bs[32][68];
    const int bm = blockIdx.y * 64;
    const int bn = blockIdx.x * 64;
    const int kbeg = blockIdx.z * klen;
    const int tid = threadIdx.x;
    const int tm = (tid >> 4) << 2;
    const int tn = (tid & 15) << 2;
    double acc2[4][2] = {};

    for (int k0 = kbeg; k0 < kbeg + klen; k0 += 32) {
#pragma unroll
        for (int i = 0; i < 8; i++) {
            int e = tid + i * 256;
            int m = e >> 5, k = e & 31;
            As[k][m] = A[(size_t)(bm + m) * lda + k0 + k];
        }
#pragma unroll
        for (int i = 0; i < 8; i++) {
            int e = tid + i * 256;
            int n = e >> 5, k = e & 31;
            Bs[k][n] = B[(size_t)(bn + n) * ldb + k0 + k];
        }
        __syncthreads();
#pragma unroll
        for (int k = 0; k < 32; k++) {
            float4 av = *reinterpret_cast<const float4*>(&As[k][tm]);
            float4 bv = *reinterpret_cast<const float4*>(&Bs[k][tn]);
            double b01 = pk2(bv.x, bv.y), b23 = pk2(bv.z, bv.w);
            double a0 = pk2(av.x, av.x), a1 = pk2(av.y, av.y);
            double a2 = pk2(av.z, av.z), a3 = pk2(av.w, av.w);
            fma2(acc2[0][0], a0, b01); fma2(acc2[0][1], a0, b23);
            fma2(acc2[1][0], a1, b01); fma2(acc2[1][1], a1, b23);
            fma2(acc2[2][0], a2, b01); fma2(acc2[2][1], a2, b23);
            fma2(acc2[3][0], a3, b01); fma2(acc2[3][1], a3, b23);
        }
        __syncthreads();
    }

    float acc[4][4];
#pragma unroll
    for (int i = 0; i < 4; i++) {
        upk2(acc2[i][0], acc[i][0], acc[i][1]);
        upk2(acc2[i][1], acc[i][2], acc[i][3]);
    }
#pragma unroll
    for (int i = 0; i < 4; i++) {
        size_t ro = (size_t)(bm + tm + i);
#pragma unroll
        for (int j = 0; j < 4; j++)
            atomicAdd(&C[ro * ldc + bn + tn + j], acc[i][j]);
    }
}

// ---------------- bf16 helpers ----------------
__device__ __forceinline__ unsigned pkbf(float lo, float hi) {
    __nv_bfloat162 h = __floats2bfloat162_rn(lo, hi);
    return *reinterpret_cast<unsigned*>(&h);
}

__device__ __forceinline__ void mma_bf16(float* d,
    unsigned a0, unsigned a1, unsigned a2, unsigned a3,
    unsigned b0, unsigned b1)
{
    asm volatile(
        "mma.sync.aligned.m16n8k16.row.col.f32.bf16.bf16.f32 "
        "{%0,%1,%2,%3},{%4,%5,%6,%7},{%8,%9},{%0,%1,%2,%3};\n"
        : "+f"(d[0]), "+f"(d[1]), "+f"(d[2]), "+f"(d[3])
        : "r"(a0), "r"(a1), "r"(a2), "r"(a3), "r"(b0), "r"(b1));
}

// ---------------- unified prep + fragment conversion kernel ----------------
// block ranges: [0,441) prep, [441,793) eafrag, [793,1305) wfrag,
// [1305,2329) wcfrag, [2329,3353) encfrag, [3353,3481) awfrag
#define CONV_GRID 3481

__global__ void conv_all_kernel(const float* __restrict__ eh, const float* __restrict__ st,
                                const float* __restrict__ bih, const float* __restrict__ bhh,
                                const int* __restrict__ di, const float* __restrict__ et,
                                const float* __restrict__ wih, const float* __restrict__ whh,
                                const float* __restrict__ enc, const float* __restrict__ aw)
{
    const int bid = blockIdx.x, tid = threadIdx.x;

    if (bid < 441) {
        int i = bid * 256 + tid;
        if (i < BB * 640) {
            int b = i / 640, j = i - b * 640;
            g_cat[i] = (j < 512) ? eh[b * 512 + j] : st[b * 512 + 384 + (j - 512)];
        } else if (i < BB * 640 + 2048) {
            int j = i - BB * 640;
            g_biassum[j] = bih[j] + bhh[j];
        } else if (i < BB * 640 + 2048 + BB * 512) {
            g_c[i - (BB * 640 + 2048)] = 0.f;
        } else if (i < BB * 640 + 2048 + 2 * BB * 512) {
            int i2 = i - (BB * 640 + 2048 + BB * 512);
            int b = i2 >> 9, j = i2 & 511;
            g_inp2[b * 1024 + 512 + j] = 0.f;   // h0 accumulator
        } else if (i < BB * 640 + 2048 + 2 * BB * 512 + 4096) {
            int i2 = i - (BB * 640 + 2048 + 2 * BB * 512);
            g_afrag[84 * KT16 * 32 + i2] = make_uint4(0u, 0u, 0u, 0u);
        } else if (i == BB * 640 + 2048 + 2 * BB * 512 + 4096) {
            g_done_t = 0;
            g_job = 0;
            g_conv_done = 0;
        }
        return;
    }

    const int lane = tid & 31;
    const int gid = lane >> 2, tig = lane & 3;

    if (bid < 793) {  // eafrag
        int gt = (bid - 441) * 256 + tid;
        if (gt >= MT16 * KT16 * 32) return;
        int kt = (gt >> 5) & 31;
        int mt = gt >> 10;
        int r0 = mt * 16 + gid, r1 = r0 + 8;
        int c0 = kt * 16 + tig * 2;
        uint4 v = make_uint4(0u, 0u, 0u, 0u);
        if (r0 < BT) {
            const float* e0 = et + (size_t)di[r0] * 512;
            v.x = pkbf(e0[c0], e0[c0 + 1]);
            v.z = pkbf(e0[c0 + 8], e0[c0 + 9]);
        }
        if (r1 < BT) {
            const float* e1 = et + (size_t)di[r1] * 512;
            v.y = pkbf(e1[c0], e1[c0 + 1]);
            v.w = pkbf(e1[c0 + 8], e1[c0 + 9]);
        }
        g_eafrag[(mt * KT16 + kt) * 32 + lane] = v;
    } else if (bid < 1305) {  // wfrag
        int gt = (bid - 793) * 256 + tid;
        int kt = (gt >> 5) & 31;
        int nt2 = gt >> 10;
        if (nt2 >= 2048 / 16) return;
        int k0 = kt * 16 + tig * 2;
        const float* w0 = wih + (size_t)((nt2 * 2) * 8 + gid) * 1024 + 512;
        const float* w1 = wih + (size_t)((nt2 * 2 + 1) * 8 + gid) * 1024 + 512;
        uint4 v;
        v.x = pkbf(w0[k0],     w0[k0 + 1]);
        v.y = pkbf(w0[k0 + 8], w0[k0 + 9]);
        v.z = pkbf(w1[k0],     w1[k0 + 1]);
        v.w = pkbf(w1[k0 + 8], w1[k0 + 9]);
        g_wfrag[(nt2 * KT16 + kt) * 32 + lane] = v;
    } else if (bid < 2329) {  // wcfrag
        int gt = (bid - 1305) * 256 + tid;
        int kt = (gt >> 5) & 63;
        int nt2 = gt >> 11;
        if (nt2 >= 128) return;
        int n0 = (nt2 * 2) * 8 + gid;
        int n1 = (nt2 * 2 + 1) * 8 + gid;
        int k0 = kt * 16 + tig * 2;
        const float *p0, *p1;
        if (k0 < 512) {
            p0 = wih + (size_t)n0 * 1024 + k0;
            p1 = wih + (size_t)n1 * 1024 + k0;
        } else {
            p0 = whh + (size_t)n0 * 512 + (k0 - 512);
            p1 = whh + (size_t)n1 * 512 + (k0 - 512);
        }
        uint4 v;
        v.x = pkbf(p0[0], p0[1]);
        v.y = pkbf(p0[8], p0[9]);
        v.z = pkbf(p1[0], p1[1]);
        v.w = pkbf(p1[8], p1[9]);
        g_wcfrag[(nt2 * 64 + kt) * 32 + lane] = v;
    } else if (bid < 3353) {  // encfrag
        int gt = (bid - 2329) * 256 + tid;
        if (gt >= EMT * KT16 * 32) return;
        int kt = (gt >> 5) & 31;
        int mt = gt >> 10;
        int r0 = mt * 16 + gid, r1 = r0 + 8;
        int c0 = kt * 16 + tig * 2;
        uint4 v;
        v.x = pkbf(enc[(size_t)r0*512 + c0],     enc[(size_t)r0*512 + c0 + 1]);
        v.y = pkbf(enc[(size_t)r1*512 + c0],     enc[(size_t)r1*512 + c0 + 1]);
        v.z = pkbf(enc[(size_t)r0*512 + c0 + 8], enc[(size_t)r0*512 + c0 + 9]);
        v.w = pkbf(enc[(size_t)r1*512 + c0 + 8], enc[(size_t)r1*512 + c0 + 9]);
        g_encfrag[(mt * KT16 + kt) * 32 + lane] = v;
    } else {  // awfrag
        int gt = (bid - 3353) * 256 + tid;
        int kt = (gt >> 5) & 31;
        int nt2 = gt >> 10;
        if (nt2 >= 32) return;
        int k0 = kt * 16 + tig * 2;
        const float* w0 = aw + (size_t)((nt2 * 2) * 8 + gid) * 512;
        const float* w1 = aw + (size_t)((nt2 * 2 + 1) * 8 + gid) * 512;
        uint4 v;
        v.x = pkbf(w0[k0],     w0[k0 + 1]);
        v.y = pkbf(w0[k0 + 8], w0[k0 + 9]);
        v.z = pkbf(w1[k0],     w1[k0 + 1]);
        v.w = pkbf(w1[k0 + 8], w1[k0 + 9]);
        g_awfrag[(nt2 * KT16 + kt) * 32 + lane] = v;
    }
}

// ---------------- HMMA frag GEMM core (8 warps, warp 32x64) ----------------
#define FRAG_LOOP16(Af, Bf, mt0, nt2b)                                         \
    const uint4* a0p = (Af) + (size_t)((mt0) * KT16) * 32 + lane;              \
    const uint4* a1p = (Af) + (size_t)(((mt0) + 1) * KT16) * 32 + lane;        \
    const uint4* bp0 = (Bf) + (size_t)(((nt2b) + 0) * KT16) * 32 + lane;       \
    const uint4* bp1 = (Bf) + (size_t)(((nt2b) + 1) * KT16) * 32 + lane;       \
    const uint4* bp2 = (Bf) + (size_t)(((nt2b) + 2) * KT16) * 32 + lane;       \
    const uint4* bp3 = (Bf) + (size_t)(((nt2b) + 3) * KT16) * 32 + lane;       \
    float acc[2][8][4] = {};                                                   \
    _Pragma("unroll 4")                                                        \
    for (int kt = 0; kt < KT16; kt++) {                                        \
        uint4 av0 = a0p[kt * 32];                                              \
        uint4 av1 = a1p[kt * 32];                                              \
        uint4 bv0 = bp0[kt * 32];                                              \
        uint4 bv1 = bp1[kt * 32];                                              \
        uint4 bv2 = bp2[kt * 32];                                              \
        uint4 bv3 = bp3[kt * 32];                                              \
        mma_bf16(acc[0][0], av0.x, av0.y, av0.z, av0.w, bv0.x, bv0.y);         \
        mma_bf16(acc[0][1], av0.x, av0.y, av0.z, av0.w, bv0.z, bv0.w);         \
        mma_bf16(acc[0][2], av0.x, av0.y, av0.z, av0.w, bv1.x, bv1.y);         \
        mma_bf16(acc[0][3], av0.x, av0.y, av0.z, av0.w, bv1.z, bv1.w);         \
        mma_bf16(acc[0][4], av0.x, av0.y, av0.z, av0.w, bv2.x, bv2.y);         \
        mma_bf16(acc[0][5], av0.x, av0.y, av0.z, av0.w, bv2.z, bv2.w);         \
        mma_bf16(acc[0][6], av0.x, av0.y, av0.z, av0.w, bv3.x, bv3.y);         \
        mma_bf16(acc[0][7], av0.x, av0.y, av0.z, av0.w, bv3.z, bv3.w);         \
        mma_bf16(acc[1][0], av1.x, av1.y, av1.z, av1.w, bv0.x, bv0.y);         \
        mma_bf16(acc[1][1], av1.x, av1.y, av1.z, av1.w, bv0.z, bv0.w);         \
        mma_bf16(acc[1][2], av1.x, av1.y, av1.z, av1.w, bv1.x, bv1.y);         \
        mma_bf16(acc[1][3], av1.x, av1.y, av1.z, av1.w, bv1.z, bv1.w);         \
        mma_bf16(acc[1][4], av1.x, av1.y, av1.z, av1.w, bv2.x, bv2.y);         \
        mma_bf16(acc[1][5], av1.x, av1.y, av1.z, av1.w, bv2.z, bv2.w);         \
        mma_bf16(acc[1][6], av1.x, av1.y, av1.z, av1.w, bv3.x, bv3.y);         \
        mma_bf16(acc[1][7], av1.x, av1.y, av1.z, av1.w, bv3.z, bv3.w);         \
    }

#define MMA_BLOCK16()                                                          \
        mma_bf16(acc[0][0], av0.x, av0.y, av0.z, av0.w, bv0.x, bv0.y);         \
        mma_bf16(acc[0][1], av0.x, av0.y, av0.z, av0.w, bv0.z, bv0.w);         \
        mma_bf16(acc[0][2], av0.x, av0.y, av0.z, av0.w, bv1.x, bv1.y);         \
        mma_bf16(acc[0][3], av0.x, av0.y, av0.z, av0.w, bv1.z, bv1.w);         \
        mma_bf16(acc[0][4], av0.x, av0.y, av0.z, av0.w, bv2.x, bv2.y);         \
        mma_bf16(acc[0][5], av0.x, av0.y, av0.z, av0.w, bv2.z, bv2.w);         \
        mma_bf16(acc[0][6], av0.x, av0.y, av0.z, av0.w, bv3.x, bv3.y);         \
        mma_bf16(acc[0][7], av0.x, av0.y, av0.z, av0.w, bv3.z, bv3.w);         \
        mma_bf16(acc[1][0], av1.x, av1.y, av1.z, av1.w, bv0.x, bv0.y);         \
        mma_bf16(acc[1][1], av1.x, av1.y, av1.z, av1.w, bv0.z, bv0.w);         \
        mma_bf16(acc[1][2], av1.x, av1.y, av1.z, av1.w, bv1.x, bv1.y);         \
        mma_bf16(acc[1][3], av1.x, av1.y, av1.z, av1.w, bv1.z, bv1.w);         \
        mma_bf16(acc[1][4], av1.x, av1.y, av1.z, av1.w, bv2.x, bv2.y);         \
        mma_bf16(acc[1][5], av1.x, av1.y, av1.z, av1.w, bv2.z, bv2.w);         \
        mma_bf16(acc[1][6], av1.x, av1.y, av1.z, av1.w, bv3.x, bv3.y);         \
        mma_bf16(acc[1][7], av1.x, av1.y, av1.z, av1.w, bv3.z, bv3.w);

// xproj: C = embA @ WihB^T + biassum
__global__ void __launch_bounds__(256)
xproj_hmma_kernel(const uint4* __restrict__ Af, const uint4* __restrict__ Bf)
{
    __shared__ float sb[128];
    const int tid = threadIdx.x, lane = tid & 31, wid = tid >> 5;
    const int wm = wid >> 1, wn = wid & 1;
    const int gid = lane >> 2, tig = lane & 3;
    const int nb = blockIdx.x, mb = blockIdx.y;

    if (tid < 128) sb[tid] = g_biassum[nb * 128 + tid];

    FRAG_LOOP16(Af, Bf, mb * 8 + wm * 2, nb * 8 + wn * 4)
    __syncthreads();

#pragma unroll
    for (int f = 0; f < 2; f++) {
#pragma unroll
        for (int half = 0; half < 2; half++) {
            int r = mb * 128 + wm * 32 + f * 16 + half * 8 + gid;
            if (r >= BT) continue;
#pragma unroll
            for (int nf = 0; nf < 8; nf++) {
                int nl = wn * 64 + nf * 8 + tig * 2;
                float v0 = acc[f][nf][half * 2]     + sb[nl];
                float v1 = acc[f][nf][half * 2 + 1] + sb[nl + 1];
                *reinterpret_cast<float2*>(
                    &g_xproj[(size_t)r * 2048 + nb * 128 + nl]) = make_float2(v0, v1);
            }
        }
    }
}

// E2 = enc @ attn_W^T
__global__ void __launch_bounds__(256)
e2_hmma_kernel(const uint4* __restrict__ Af, const uint4* __restrict__ Bf)
{
    const int tid = threadIdx.x, lane = tid & 31, wid = tid >> 5;
    const int wm = wid >> 1, wn = wid & 1;
    const int gid = lane >> 2, tig = lane & 3;
    const int nb = blockIdx.x, mb = blockIdx.y;

    FRAG_LOOP16(Af, Bf, mb * 8 + wm * 2, nb * 8 + wn * 4)

#pragma unroll
    for (int f = 0; f < 2; f++) {
#pragma unroll
        for (int half = 0; half < 2; half++) {
            int r = mb * 128 + wm * 32 + f * 16 + half * 8 + gid;
#pragma unroll
            for (int nf = 0; nf < 8; nf++) {
                int nl = wn * 64 + nf * 8 + tig * 2;
                *reinterpret_cast<float2*>(
                    &g_E2[(size_t)r * 512 + nb * 128 + nl]) =
                    make_float2(acc[f][nf][half * 2], acc[f][nf][half * 2 + 1]);
            }
        }
    }
}

// ---------------- frag scatter helpers ----------------
__device__ __forceinline__ void gfrag_store(int r, int c, float v0, float v1)
{
    int mt = r >> 4, rr = r & 15, gid = rr & 7;
    int kt = c >> 4, cc = c & 15;
    int tig = (cc & 7) >> 1;
    int comp = ((cc >> 3) << 1) | (rr >> 3);
    unsigned* base = reinterpret_cast<unsigned*>(
        &g_gfrag[(size_t)(mt * 64 + kt) * 32 + gid * 4 + tig]);
    base[comp] = pkbf(v0, v1);
}

__device__ __forceinline__ void afrag_store(int r, int c, float v0, float v1)
{
    int mt = r >> 4, rr = r & 15, gid = rr & 7;
    int kt = c >> 4, cc = c & 15;
    int tig = (cc & 7) >> 1;
    int comp = ((cc >> 3) << 1) | (rr >> 3);
    unsigned* base = reinterpret_cast<unsigned*>(
        &g_afrag[(size_t)(mt * KT16 + kt) * 32 + gid * 4 + tig]);
    base[comp] = pkbf(v0, v1);
}

// ---------------- fused persistent kernel ----------------
__global__ void __launch_bounds__(256, 2)
fused_kernel(const float* __restrict__ enc, const float* __restrict__ be2d,
             const uint4* __restrict__ Af, const uint4* __restrict__ Bf,
             const float* __restrict__ pw, const float* __restrict__ pb)
{
    __shared__ float hs[512];
    __shared__ float sc[64];
    __shared__ float s_inv;
    __shared__ float sb[128];
    __shared__ float smax[2][128], ssum[2][128];
    __shared__ unsigned s_job;
    const int tid = threadIdx.x;
    const int wid = tid >> 5, lane = tid & 31;
    const int gid = lane >> 2, tig = lane & 3;

    if (blockIdx.x < BB) {
        // ================= recurrence path =================
        const int b = blockIdx.x;
        const int j = 2 * tid;

        for (int t = 0; t < TT; t++) {
            // ---- Phase A: pointwise(t-1) + attention(t) ----
            if (t > 0) {
                const int gb = b * 2048;
                float2 gi = *reinterpret_cast<const float2*>(&g_gates[gb + j]);
                float2 gf = *reinterpret_cast<const float2*>(&g_gates[gb + 512 + j]);
                float2 gg = *reinterpret_cast<const float2*>(&g_gates[gb + 1024 + j]);
                float2 go = *reinterpret_cast<const float2*>(&g_gates[gb + 1536 + j]);
                float2 cc = *reinterpret_cast<const float2*>(&g_c[b * 512 + j]);
                float si0 = 1.f / (1.f + expf(-gi.x)), si1 = 1.f / (1.f + expf(-gi.y));
                float sf0 = 1.f / (1.f + expf(-gf.x)), sf1 = 1.f / (1.f + expf(-gf.y));
                float so0 = 1.f / (1.f + expf(-go.x)), so1 = 1.f / (1.f + expf(-go.y));
                cc.x = sf0 * cc.x + si0 * tanhf(gg.x);
                cc.y = sf1 * cc.y + si1 * tanhf(gg.y);
                *reinterpret_cast<float2*>(&g_c[b * 512 + j]) = cc;
                float h0 = so0 * tanhf(cc.x);
                float h1 = so1 * tanhf(cc.y);
                int r = (t - 1) * BB + b;
                *reinterpret_cast<float2*>(&g_outs[(size_t)r * 512 + j]) = make_float2(h0, h1);
                afrag_store(r, j, h0, h1);
                hs[j] = h0; hs[j + 1] = h1;
                gfrag_store(b, 512 + j, h0, h1);
            } else {
                float2 hv = *reinterpret_cast<const float2*>(&g_inp2[b * 1024 + 512 + j]);
                hv.x += be2d[j]; hv.y += be2d[j + 1];
                hs[j] = hv.x; hs[j + 1] = hv.y;
                gfrag_store(b, 512 + j, hv.x, hv.y);
            }
            __syncthreads();

            const float* E2b = g_E2 + (size_t)b * SS * 512;
            for (int s = wid; s < SS; s += 8) {
                const float* er = E2b + (size_t)s * 512;
                float a = 0.f;
                for (int k = lane; k < 512; k += 32) a += hs[k] * er[k];
#pragma unroll
                for (int o = 16; o; o >>= 1) a += __shfl_xor_sync(0xffffffffu, a, o);
                if (lane == 0) sc[s] = a;
            }
            __syncthreads();

            if (wid == 0) {
                float v0 = sc[lane], v1 = sc[lane + 32];
                float m = fmaxf(v0, v1);
#pragma unroll
                for (int o = 16; o; o >>= 1) m = fmaxf(m, __shfl_xor_sync(0xffffffffu, m, o));
                float e0 = expf(v0 - m), e1 = expf(v1 - m);
                float ssm = e0 + e1;
#pragma unroll
                for (int o = 16; o; o >>= 1) ssm += __shfl_xor_sync(0xffffffffu, ssm, o);
                sc[lane] = e0; sc[lane + 32] = e1;
                if (lane == 0) s_inv = 1.f / ssm;
            }
            __syncthreads();

            {
                float inv = s_inv;
                const float* eb = enc + (size_t)b * SS * DD;
                float a0 = 0.f, a1 = 0.f;
#pragma unroll 8
                for (int s = 0; s < SS; s++) {
                    float2 e = *reinterpret_cast<const float2*>(&eb[(size_t)s * DD + j]);
                    a0 += sc[s] * e.x;
                    a1 += sc[s] * e.y;
                }
                a0 *= inv; a1 *= inv;
                gfrag_store(b, j, a0, a1);
            }

            grid_barrier();
            if (b == 0 && tid == 0 && t > 0) g_done_t = t;

            // ---- Phase B: gates HMMA, CTA handles 32 cols ----
            {
                const int wm = wid >> 1, wn = wid & 1;
                const uint4* ap = g_gfrag + (size_t)(wm * 64) * 32 + lane;
                const uint4* bq = g_wcfrag + (size_t)((b * 2 + wn) * 64) * 32 + lane;
                float acc[2][4] = {};
#pragma unroll 4
                for (int kt = 0; kt < 64; kt++) {
                    uint4 av = ap[kt * 32];
                    uint4 bv = bq[kt * 32];
                    mma_bf16(acc[0], av.x, av.y, av.z, av.w, bv.x, bv.y);
                    mma_bf16(acc[1], av.x, av.y, av.z, av.w, bv.z, bv.w);
                }
#pragma unroll
                for (int nf = 0; nf < 2; nf++) {
                    int c = b * 32 + wn * 16 + nf * 8 + tig * 2;
                    int r0 = wm * 16 + gid, r1 = r0 + 8;
                    const float2 x0 = *reinterpret_cast<const float2*>(
                        &g_xproj[(size_t)(r0 * TT + t) * 2048 + c]);
                    const float2 x1 = *reinterpret_cast<const float2*>(
                        &g_xproj[(size_t)(r1 * TT + t) * 2048 + c]);
                    *reinterpret_cast<float2*>(&g_gates[r0 * 2048 + c]) =
                        make_float2(acc[nf][0] + x0.x, acc[nf][1] + x0.y);
                    *reinterpret_cast<float2*>(&g_gates[r1 * 2048 + c]) =
                        make_float2(acc[nf][2] + x1.x, acc[nf][3] + x1.y);
                }
            }

            grid_barrier();
        }

        // ---- final pointwise (outs row 20*64+b) ----
        {
            const int gb = b * 2048;
            float2 gi = *reinterpret_cast<const float2*>(&g_gates[gb + j]);
            float2 gf = *reinterpret_cast<const float2*>(&g_gates[gb + 512 + j]);
            float2 gg = *reinterpret_cast<const float2*>(&g_gates[gb + 1024 + j]);
            float2 go = *reinterpret_cast<const float2*>(&g_gates[gb + 1536 + j]);
            float2 cc = *reinterpret_cast<const float2*>(&g_c[b * 512 + j]);
            float si0 = 1.f / (1.f + expf(-gi.x)), si1 = 1.f / (1.f + expf(-gi.y));
            float sf0 = 1.f / (1.f + expf(-gf.x)), sf1 = 1.f / (1.f + expf(-gf.y));
            float so0 = 1.f / (1.f + expf(-go.x)), so1 = 1.f / (1.f + expf(-go.y));
            cc.x = sf0 * cc.x + si0 * tanhf(gg.x);
            cc.y = sf1 * cc.y + si1 * tanhf(gg.y);
            float h0 = so0 * tanhf(cc.x);
            float h1 = so1 * tanhf(cc.y);
            int r = (TT - 1) * BB + b;
            *reinterpret_cast<float2*>(&g_outs[(size_t)r * 512 + j]) = make_float2(h0, h1);
            afrag_store(r, j, h0, h1);
        }

        grid_barrier();
        if (b == 0 && tid == 0) g_done_t = TT;
        // loop CTAs fall through and join the proj worker pool
    } else {
        // ================= worker prologue: build proj_w B-frags =================
        const int w = blockIdx.x - BB;   // 0..NWORK-1
        for (int nt2 = w; nt2 < VV / 16; nt2 += NWORK) {
            for (int i = tid; i < 1024; i += 256) {
                int ln = i & 31, kt = i >> 5;
                int gd = ln >> 2, tg = ln & 3;
                int k0 = kt * 16 + tg * 2;
                const float* w0 = pw + (size_t)((nt2 * 2) * 8 + gd) * 512;
                const float* w1 = pw + (size_t)((nt2 * 2 + 1) * 8 + gd) * 512;
                uint4 v;
                v.x = pkbf(w0[k0],     w0[k0 + 1]);
                v.y = pkbf(w0[k0 + 8], w0[k0 + 9]);
                v.z = pkbf(w1[k0],     w1[k0 + 1]);
                v.w = pkbf(w1[k0 + 8], w1[k0 + 9]);
                g_bfrag[(nt2 * KT16 + kt) * 32 + ln] = v;
            }
        }
        __threadfence();
        __syncthreads();
        if (tid == 0) {
            atomicAdd((unsigned*)&g_conv_done, 1);
            while (g_conv_done < NWORK) { __nanosleep(128); }
        }
        __syncthreads();
    }

    // ================= proj worker path =================
    for (;;) {
        if (tid == 0) s_job = atomicAdd(&g_job, 1u);
        __syncthreads();
        unsigned job = s_job;
        if (job >= NJOBS) break;
        const int mb = job / NT2, nb = job % NT2;
        const int need = (2 * mb + 2 < TT + 1) ? 2 * mb + 2 : TT;

        if (tid == 0) {
            while (g_done_t < need) { __nanosleep(256); }
        }
        __syncthreads();

        if (tid < 128) sb[tid] = pb[nb * 128 + tid];

        const int wm = wid >> 1, wn = wid & 1;
        const int mt0 = mb * 8 + wm * 2;
        const int nt2b = nb * 8 + wn * 4;
        const uint4* a0p = Af + (size_t)(mt0 * KT16) * 32 + lane;
        const uint4* a1p = Af + (size_t)((mt0 + 1) * KT16) * 32 + lane;
        const uint4* bp0 = Bf + (size_t)((nt2b + 0) * KT16) * 32 + lane;
        const uint4* bp1 = Bf + (size_t)((nt2b + 1) * KT16) * 32 + lane;
        const uint4* bp2 = Bf + (size_t)((nt2b + 2) * KT16) * 32 + lane;
        const uint4* bp3 = Bf + (size_t)((nt2b + 3) * KT16) * 32 + lane;

        float acc[2][8][4] = {};
        uint4 av0 = a0p[0], av1 = a1p[0];
        uint4 bv0 = bp0[0], bv1 = bp1[0], bv2 = bp2[0], bv3 = bp3[0];

#pragma unroll 1
        for (int kt = 0; kt < KT16; kt++) {
            const int kn = (kt < KT16 - 1 ? kt + 1 : kt) * 32;
            uint4 nav0 = a0p[kn], nav1 = a1p[kn];
            uint4 nbv0 = bp0[kn], nbv1 = bp1[kn], nbv2 = bp2[kn], nbv3 = bp3[kn];
            MMA_BLOCK16()
            av0 = nav0; av1 = nav1;
            bv0 = nbv0; bv1 = nbv1; bv2 = nbv2; bv3 = nbv3;
        }
        __syncthreads();   // sb ready

#pragma unroll
        for (int f = 0; f < 2; f++) {
#pragma unroll
            for (int half = 0; half < 2; half++) {
                float v[16];
#pragma unroll
                for (int nf = 0; nf < 8; nf++) {
                    float b0 = sb[wn * 64 + nf * 8 + tig * 2];
                    float b1 = sb[wn * 64 + nf * 8 + tig * 2 + 1];
                    v[nf * 2]     = acc[f][nf][half * 2]     + b0;
                    v[nf * 2 + 1] = acc[f][nf][half * 2 + 1] + b1;
                }
                float mx = v[0];
#pragma unroll
                for (int i = 1; i < 16; i++) mx = fmaxf(mx, v[i]);
                mx = fmaxf(mx, __shfl_xor_sync(0xffffffffu, mx, 1));
                mx = fmaxf(mx, __shfl_xor_sync(0xffffffffu, mx, 2));
                float se = 0.f;
#pragma unroll
                for (int i = 0; i < 16; i++) se += expf(v[i] - mx);
                se += __shfl_xor_sync(0xffffffffu, se, 1);
                se += __shfl_xor_sync(0xffffffffu, se, 2);
                if (tig == 0) {
                    int rowl = wm * 32 + f * 16 + half * 8 + gid;
                    smax[wn][rowl] = mx;
                    ssum[wn][rowl] = se;
                }
            }
        }
        __syncthreads();

        if (tid < 128) {
            int row = mb * 128 + tid;
            if (row < BT) {
                float m0 = smax[0][tid], m1 = smax[1][tid];
                float M = fmaxf(m0, m1);
                float S = ssum[0][tid] * expf(m0 - M) + ssum[1][tid] * expf(m1 - M);
                g_pmax[(size_t)row * NT2 + nb] = M;
                g_psum[(size_t)row * NT2 + nb] = S;
            }
        }
        __syncthreads();
    }
}

// ---------------- loss ----------------
__global__ void loss_row_kernel(const int* __restrict__ lab,
                                const float* __restrict__ pw,
                                const float* __restrict__ pb)
{
    __shared__ float red[128];
    const int r = blockIdx.x, tid = threadIdx.x;
    const int b = r & 63, t = r >> 6;
    const int l = lab[b * TT + t];

    const float* o  = g_outs + (size_t)r * 512;
    const float* wr = pw + (size_t)l * 512;
    float a = 0.f;
    for (int k = tid; k < 512; k += 128) a += o[k] * wr[k];
    red[tid] = a; __syncthreads();
    for (int s = 64; s; s >>= 1) { if (tid < s) red[tid] += red[tid + s]; __syncthreads(); }
    float labl = red[0] + pb[l];
    __syncthreads();

    const float* pm = g_pmax + (size_t)r * NT2;
    const float* ps = g_psum + (size_t)r * NT2;
    float m = -1e30f;
    for (int j = tid; j < NT2; j += 128) m = fmaxf(m, pm[j]);
    red[tid] = m; __syncthreads();
    for (int s = 64; s; s >>= 1) { if (tid < s) red[tid] = fmaxf(red[tid], red[tid + s]); __syncthreads(); }
    float M = red[0]; __syncthreads();
    float se = 0.f;
    for (int j = tid; j < NT2; j += 128) se += ps[j] * expf(pm[j] - M);
    red[tid] = se; __syncthreads();
    for (int s = 64; s; s >>= 1) { if (tid < s) red[tid] += red[tid + s]; __syncthreads(); }
    if (tid == 0) {
        float lse = M + logf(red[0]);
        g_nll[r] = (l > 0) ? (lse - labl) : 0.f;
    }
}

__global__ void loss_final_kernel(const int* __restrict__ lab, float* __restrict__ out)
{
    __shared__ float red[64];
    const int b = threadIdx.x;
    float s = 0.f, cnt = 0.f;
    for (int t = 0; t < TT; t++) {
        s += g_nll[t * BB + b];
        cnt += (lab[b * TT + t] > 0) ? 1.f : 0.f;
    }
    red[b] = s / (cnt + 1e-6f);
    __syncthreads();
    if (b == 0) {
        float a = 0.f;
        for (int i = 0; i < 64; i++) a += red[i];
        out[0] = a / 64.f;
    }
}

// ---------------- host launcher ----------------
extern "C" void kernel_launch(void* const* d_in, const int* in_sizes, int n_in,
                              void* d_out, int out_size)
{
    const float* encode_hidden = (const float*)d_in[0];
    const float* encode_output = (const float*)d_in[1];
    const int*   seq_label     = (const int*)  d_in[3];
    const int*   decoder_input = (const int*)  d_in[4];
    const float* style_emb     = (const float*)d_in[5];
    const float* w_e2d         = (const float*)d_in[6];
    const float* b_e2d         = (const float*)d_in[7];
    const float* attn_W        = (const float*)d_in[8];
    const float* emb_table     = (const float*)d_in[9];
    const float* w_ih          = (const float*)d_in[10];
    const float* w_hh          = (const float*)d_in[11];
    const float* b_ih          = (const float*)d_in[12];
    const float* b_hh          = (const float*)d_in[13];
    const float* proj_w        = (const float*)d_in[14];
    const float* proj_b        = (const float*)d_in[15];
    float* out = (float*)d_out;

    float *p_cat, *p_inp2;
    uint4 *p_afrag, *p_eafrag, *p_bfrag, *p_wfrag, *p_encfrag, *p_awfrag;
    cudaGetSymbolAddress((void**)&p_cat,     g_cat);
    cudaGetSymbolAddress((void**)&p_inp2,    g_inp2);
    cudaGetSymbolAddress((void**)&p_afrag,   g_afrag);
    cudaGetSymbolAddress((void**)&p_eafrag,  g_eafrag);
    cudaGetSymbolAddress((void**)&p_bfrag,   g_bfrag);
    cudaGetSymbolAddress((void**)&p_wfrag,   g_wfrag);
    cudaGetSymbolAddress((void**)&p_encfrag, g_encfrag);
    cudaGetSymbolAddress((void**)&p_awfrag,  g_awfrag);

    // unified prep + fragment conversions (all independent, one launch)
    conv_all_kernel<<<CONV_GRID, 256>>>(encode_hidden, style_emb, b_ih, b_hh,
                                        decoder_input, emb_table, w_ih, w_hh,
                                        encode_output, attn_W);

    // h0 = cat @ W_e2d^T (bias added in fused t=0), split-K atomic fp32
    gemm_atomic_kernel<<<dim3(8, 1, 5), 256>>>(128,
        p_cat, 640, w_e2d, 640, p_inp2 + 512, 1024);

    // xproj = emb @ W_ih_emb^T + biassum  (HMMA)
    xproj_hmma_kernel<<<dim3(16, MT128), 256>>>(p_eafrag, p_wfrag);

    // E2 = enc @ attn_W^T  (HMMA)
    e2_hmma_kernel<<<dim3(4, 32), 256>>>(p_encfrag, p_awfrag);

    // fused persistent kernel: recurrence + bfrag conversion + overlapped projection
    fused_kernel<<<GRID_FUSED, 256>>>(encode_output, b_e2d, p_afrag, p_bfrag,
                                      proj_w, proj_b);

    // loss
    loss_row_kernel<<<BT, 128>>>(seq_label, proj_w, proj_b);
    loss_final_kernel<<<1, 64>>>(seq_label, out);
}